// round 11
// baseline (speedup 1.0000x reference)
#include <cuda_runtime.h>
#include <cuda_bf16.h>
#include <math.h>
#include <stdint.h>

typedef unsigned long long ull;

#define DM 512
#define TS 4096
#define NB 2
#define NH 8
#define DHD 64
#define BT_ (NB*TS)    // 8192
#define BH_ (NB*NH)    // 16

// ---------------- device scratch (static, allocation-free) ----------------
// RULE (root cause of R4-R7 failures): these symbols are referenced ONLY
// inside device code. Never pass a __device__ symbol as a kernel argument.
__device__ __nv_bfloat16 g_Wb[4][DM*DM];
__device__ float g_ws[4][DM];
__device__ __nv_bfloat16 g_xhi[BT_*DM];
__device__ __nv_bfloat16 g_xlo[BT_*DM];
__device__ __nv_bfloat16 g_chi[BT_*DM];
__device__ __nv_bfloat16 g_clo[BT_*DM];
__device__ float g_q [BH_*TS*DHD];
__device__ float g_k [BH_*TS*DHD];
__device__ float g_v [BH_*TS*DHD];
__device__ __nv_bfloat16 g_kchi[BH_*TS*DHD];  // compacted K, [bh][j][d]
__device__ __nv_bfloat16 g_kclo[BH_*TS*DHD];
__device__ __nv_bfloat16 g_vchi[BH_*DHD*TS];  // compacted V transposed, [bh][d][j]
__device__ __nv_bfloat16 g_vclo[BH_*DHD*TS];
__device__ int   g_kept[NB*TS];
__device__ int   g_cnt[NB];
__device__ int   g_absmax;

// ---------------- mma / cp.async helpers ----------------
static __device__ __forceinline__ void mma16816(float* d, const uint32_t* a, const uint32_t* b){
    asm volatile("mma.sync.aligned.m16n8k16.row.col.f32.bf16.bf16.f32 "
        "{%0,%1,%2,%3}, {%4,%5,%6,%7}, {%8,%9}, {%0,%1,%2,%3};"
        : "+f"(d[0]),"+f"(d[1]),"+f"(d[2]),"+f"(d[3])
        : "r"(a[0]),"r"(a[1]),"r"(a[2]),"r"(a[3]), "r"(b[0]),"r"(b[1]));
}
static __device__ __forceinline__ uint32_t lds32(const void* p){
    return *(const uint32_t*)p;
}
static __device__ __forceinline__ uint32_t pkbf(float x, float y){
    uint32_t r; asm("cvt.rn.bf16x2.f32 %0, %1, %2;" : "=r"(r) : "f"(y), "f"(x)); return r;
}
static __device__ __forceinline__ uint32_t smem_u32(const void* p){
    uint32_t a;
    asm("{ .reg .u64 t; cvta.to.shared.u64 t, %1; cvt.u32.u64 %0, t; }" : "=r"(a) : "l"(p));
    return a;
}
static __device__ __forceinline__ void cp16(uint32_t dst, const void* src){
    asm volatile("cp.async.ca.shared.global [%0], [%1], 16;" :: "r"(dst), "l"(src) : "memory");
}
static __device__ __forceinline__ void cp16z(uint32_t dst, const void* src, int ssz){
    asm volatile("cp.async.ca.shared.global [%0], [%1], 16, %2;" :: "r"(dst), "l"(src), "r"(ssz) : "memory");
}
#define CP_COMMIT() asm volatile("cp.async.commit_group;" ::: "memory")
#define CP_WAIT1()  asm volatile("cp.async.wait_group 1;" ::: "memory")
#define CP_WAIT0()  asm volatile("cp.async.wait_group 0;" ::: "memory")

// ---------------- 1. per-row symmetric int8 weight quant ----------------
__global__ void quant_weights_kernel(const float* __restrict__ Wq, const float* __restrict__ Wk,
                                     const float* __restrict__ Wv, const float* __restrict__ Wo)
{
    int w = blockIdx.y;
    int row = blockIdx.x;
    const float* srcs[4] = {Wq, Wk, Wv, Wo};
    const float* wr = srcs[w] + row*DM;
    __nv_bfloat16* dst = &g_Wb[w][row*DM];
    int tid = threadIdx.x; // 128
    if (w==0 && row==0 && tid==0) g_absmax = 0;
    float mx = 0.f;
    for (int i=tid;i<DM;i+=128) mx = fmaxf(mx, fabsf(wr[i]));
    for (int off=16;off;off>>=1) mx = fmaxf(mx, __shfl_xor_sync(0xffffffffu, mx, off));
    __shared__ float sm4[4];
    if ((tid&31)==0) sm4[tid>>5] = mx;
    __syncthreads();
    mx = fmaxf(fmaxf(sm4[0],sm4[1]), fmaxf(sm4[2],sm4[3]));
    float s = fmaxf(__fdiv_rn(mx, 127.0f), 1e-8f);
    if (tid==0) g_ws[w][row] = s;
    for (int i=tid;i<DM;i+=128){
        float qv = rintf(__fdiv_rn(wr[i], s));
        qv = fminf(fmaxf(qv, -127.f), 127.f);
        dst[i] = __float2bfloat16(qv);
    }
}

// ---------------- 1b. bf16 hi/lo split of x ----------------
__global__ void split_x_kernel(const float* __restrict__ src)
{
    int i = (blockIdx.x*256 + threadIdx.x)*4;
    float4 v = *(const float4*)&src[i];
    __nv_bfloat16 h0=__float2bfloat16(v.x), h1=__float2bfloat16(v.y);
    __nv_bfloat16 h2=__float2bfloat16(v.z), h3=__float2bfloat16(v.w);
    __nv_bfloat162 hA; hA.x=h0; hA.y=h1;
    __nv_bfloat162 hB; hB.x=h2; hB.y=h3;
    __nv_bfloat162 lA; lA.x=__float2bfloat16(v.x-__bfloat162float(h0)); lA.y=__float2bfloat16(v.y-__bfloat162float(h1));
    __nv_bfloat162 lB; lB.x=__float2bfloat16(v.z-__bfloat162float(h2)); lB.y=__float2bfloat16(v.w-__bfloat162float(h3));
    *(__nv_bfloat162*)&g_xhi[i]   = hA;
    *(__nv_bfloat162*)&g_xhi[i+2] = hB;
    *(__nv_bfloat162*)&g_xlo[i]   = lA;
    *(__nv_bfloat162*)&g_xlo[i+2] = lB;
}

// ---------------- 2. mask compaction ----------------
__global__ void compact_kernel(const int* __restrict__ mask)
{
    int b = blockIdx.x;
    const int* m = mask + b*TS;
    __shared__ int part[1024];
    int tid = threadIdx.x; // 1024
    int base = tid*4;
    int f0 = m[base]!=0, f1 = m[base+1]!=0, f2 = m[base+2]!=0, f3 = m[base+3]!=0;
    int s = f0+f1+f2+f3;
    part[tid] = s;
    __syncthreads();
    for (int off=1; off<1024; off<<=1){
        int v = (tid>=off) ? part[tid-off] : 0;
        __syncthreads();
        part[tid] += v;
        __syncthreads();
    }
    int o = part[tid] - s + b*TS;
    if (f0) g_kept[o++] = base;
    if (f1) g_kept[o++] = base+1;
    if (f2) g_kept[o++] = base+2;
    if (f3) g_kept[o++] = base+3;
    if (tid==1023) g_cnt[b] = part[1023];
}

// ---------------- 3. mma GEMM, cp.async 3-stage pipeline, 1 barrier/iter ----------------
// Block 128x128, BK=32, 256 threads = 8 warps. Dynamic smem: 3 stages x
// (Ahi|Alo|B) tiles of 128 rows x 80B.
#define GTILE 10240
#define GST3  (3*GTILE)          // 30720 per stage
#define GEMM_SMEM (3*GST3)       // 92160
__global__ void __launch_bounds__(256) gemm_mma_kernel(
    const float* __restrict__ bq, const float* __restrict__ bk,
    const float* __restrict__ bv, const float* __restrict__ bo,
    float* __restrict__ outp, int modebase)
{
    extern __shared__ __align__(16) char dsm[];
    __shared__ float s_sc[128], s_bi[128];
    __shared__ float red8[8];
    int mode = modebase + blockIdx.z;
    int tid = threadIdx.x, lane = tid&31, wid = tid>>5;
    int wm = wid>>1, wn = wid&1;
    int g = lane>>2, t = lane&3;
    int rowbase = blockIdx.x*128, nbase = blockIdx.y*128;
    uint32_t sbase = smem_u32(dsm);

    const __nv_bfloat16* __restrict__ Ahi = (mode<3) ? g_xhi : g_chi;
    const __nv_bfloat16* __restrict__ Alo = (mode<3) ? g_xlo : g_clo;
    const __nv_bfloat16* __restrict__ Bw  = g_Wb[mode];
    const float* biasp = (mode==0)?bq:((mode==1)?bk:((mode==2)?bv:bo));

    auto issue_tile = [&](int st, int kt){
        uint32_t stg = sbase + st*GST3;
        int kb = kt*32;
        #pragma unroll
        for (int i=0;i<2;i++){
            int id = tid + i*256;   // 0..511
            int r = id>>2, c = id&3;
            cp16(stg +           r*80 + c*16, &Ahi[(rowbase+r)*DM + kb + c*8]);
            cp16(stg + GTILE   + r*80 + c*16, &Alo[(rowbase+r)*DM + kb + c*8]);
            cp16(stg + 2*GTILE + r*80 + c*16, &Bw [(nbase  +r)*DM + kb + c*8]);
        }
    };

    issue_tile(0, 0); CP_COMMIT();
    issue_tile(1, 1); CP_COMMIT();
    if (tid<128) s_sc[tid] = g_ws[mode][nbase+tid];
    else         s_bi[tid-128] = biasp[nbase+tid-128];

    float acc[2][8][4];
    #pragma unroll
    for (int mt=0;mt<2;mt++)
      #pragma unroll
      for (int nt=0;nt<8;nt++)
        #pragma unroll
        for (int c=0;c<4;c++) acc[mt][nt][c] = 0.f;

    for (int kt=0; kt<16; kt++){
        CP_WAIT1();
        __syncthreads();          // tile kt visible to all; prior reads of slot (kt+2)%3 done
        if (kt+2 < 16) issue_tile((kt+2)%3, kt+2);
        CP_COMMIT();
        const char* stg = dsm + (kt%3)*GST3;
        #pragma unroll
        for (int ks=0; ks<32; ks+=16){
            uint32_t af[2][2][4];
            #pragma unroll
            for (int h=0; h<2; h++)
              #pragma unroll
              for (int mt=0; mt<2; mt++){
                int r0 = wm*32 + mt*16;
                const char* base = stg + h*GTILE;
                af[h][mt][0] = lds32(base + (r0+g  )*80 + (ks+2*t  )*2);
                af[h][mt][1] = lds32(base + (r0+g+8)*80 + (ks+2*t  )*2);
                af[h][mt][2] = lds32(base + (r0+g  )*80 + (ks+2*t+8)*2);
                af[h][mt][3] = lds32(base + (r0+g+8)*80 + (ks+2*t+8)*2);
              }
            #pragma unroll
            for (int np=0; np<8; np++){
                int n0 = wn*64 + np*8;
                uint32_t bf2[2];
                bf2[0] = lds32(stg + 2*GTILE + (n0+g)*80 + (ks+2*t  )*2);
                bf2[1] = lds32(stg + 2*GTILE + (n0+g)*80 + (ks+2*t+8)*2);
                #pragma unroll
                for (int mt=0; mt<2; mt++){
                    mma16816(acc[mt][np], af[0][mt], bf2);
                    mma16816(acc[mt][np], af[1][mt], bf2);
                }
            }
        }
    }
    float amax = 0.f;
    float* qkv = (mode==0)?g_q:((mode==1)?g_k:g_v);
    #pragma unroll
    for (int mt=0;mt<2;mt++){
      #pragma unroll
      for (int nt=0;nt<8;nt++){
        int ncol = wn*64 + nt*8 + 2*t;
        float s0 = s_sc[ncol], s1 = s_sc[ncol+1];
        float b0 = s_bi[ncol], b1 = s_bi[ncol+1];
        #pragma unroll
        for (int rh=0; rh<2; rh++){
            int row = rowbase + wm*32 + mt*16 + g + rh*8;
            float v0 = acc[mt][nt][rh*2  ]*s0 + b0;
            float v1 = acc[mt][nt][rh*2+1]*s1 + b1;
            float2 w; w.x = v0; w.y = v1;
            if (mode<3){
                int o = nbase + ncol;
                int head = o>>6, dh = o&63;
                int bb = row>>12, tt = row&4095;
                *(float2*)&qkv[((bb*NH+head)*TS + tt)*DHD + dh] = w;
            } else {
                *(float2*)&outp[row*DM + nbase + ncol] = w;
                amax = fmaxf(amax, fmaxf(fabsf(v0), fabsf(v1)));
            }
        }
      }
    }
    if (mode==3){
        for (int off=16;off;off>>=1) amax = fmaxf(amax, __shfl_xor_sync(0xffffffffu, amax, off));
        if (lane==0) red8[wid] = amax;
        __syncthreads();
        if (tid==0){
            float m = red8[0];
            #pragma unroll
            for (int i=1;i<8;i++) m = fmaxf(m, red8[i]);
            atomicMax(&g_absmax, __float_as_int(m));
        }
    }
}

// ---------------- 4. fused coalesced gather: K -> [bh][j][d], V -> [bh][d][j] ----------------
// grid (TS/64, BH_), block 256. Row reads are contiguous 256B; V transposed via smem.
__global__ void __launch_bounds__(256) gather_kv_kernel()
{
    __shared__ float vs[64][65];
    __shared__ int srcs[64];
    int bh = blockIdx.y;
    int b = bh>>3;
    int jbase = blockIdx.x*64;
    int cnt = g_cnt[b];
    int tid = threadIdx.x;
    if (tid < 64){
        int j = jbase + tid;
        srcs[tid] = (j < cnt) ? g_kept[b*TS + j] : -1;
    }
    __syncthreads();
    #pragma unroll
    for (int i=0;i<16;i++){
        int id = tid + i*256;
        int j = id>>6, d = id&63;
        int src = srcs[j];
        if (src >= 0){
            float kv = g_k[(bh*TS + src)*DHD + d];
            __nv_bfloat16 h = __float2bfloat16(kv);
            int o = (bh*TS + jbase + j)*DHD + d;
            g_kchi[o] = h;
            g_kclo[o] = __float2bfloat16(kv - __bfloat162float(h));
            vs[j][d] = g_v[(bh*TS + src)*DHD + d];
        } else {
            vs[j][d] = 0.f;
        }
    }
    __syncthreads();
    #pragma unroll
    for (int i=0;i<16;i++){
        int id = tid + i*256;
        int d = id>>6, j = id&63;
        float vv = vs[j][d];
        __nv_bfloat16 h = __float2bfloat16(vv);
        int o = (bh*DHD + d)*TS + jbase + j;
        g_vchi[o] = h;
        g_vclo[o] = __float2bfloat16(vv - __bfloat162float(h));
    }
}

// ---------------- 5. flash attention: BQ=128, BK=64, 8 warps, 2-stage cp.async ----------
#define ASK 144                  // row stride bytes (72 bf16; 16B aligned)
#define AQ_REG 18432             // Q hi or lo: 128 rows x 144B
#define AST   36864              // per KV stage: KH|KL|VH|VL, 64x144 each
#define ATT_SMEM (2*AQ_REG + 2*AST)   // 110592
__global__ void __launch_bounds__(256, 2) attn_mma_kernel()
{
    extern __shared__ __align__(16) char smem[];
    const int OQH=0, OQL=AQ_REG;
    int bh = blockIdx.y;
    int b = bh>>3, h = bh&7;
    int qbase = blockIdx.x*128;
    int tid = threadIdx.x, lane = tid&31, wid = tid>>5;
    int g = lane>>2, t = lane&3;
    int cnt = g_cnt[b];
    uint32_t sbase = smem_u32(smem);

    // issue K/V tile (64 keys at kb) into stage st; hw zero-fill past cnt.
    // Addresses clamped in-bounds (ssz handles the masking).
    auto issue_kv = [&](int st, int kb){
        uint32_t stg = sbase + 2*AQ_REG + st*AST;
        #pragma unroll
        for (int i=0;i<2;i++){
            int id = tid + i*256;   // 0..511
            int j = id>>3, c = id&7;
            int jj = kb + j;
            int kssz = (jj < cnt) ? 16 : 0;
            int jc = jj < TS ? jj : TS-1;
            cp16z(stg +         j*ASK + c*16, &g_kchi[(bh*TS+jc)*DHD + c*8], kssz);
            cp16z(stg +  9216 + j*ASK + c*16, &g_kclo[(bh*TS+jc)*DHD + c*8], kssz);
            int vb = (cnt - (kb + c*8))*2;
            vb = vb < 0 ? 0 : (vb > 16 ? 16 : vb);
            int cb2 = kb + c*8; if (cb2 > TS-8) cb2 = TS-8;
            cp16z(stg + 18432 + j*ASK + c*16, &g_vchi[(bh*DHD+j)*TS + cb2], vb);
            cp16z(stg + 27648 + j*ASK + c*16, &g_vclo[(bh*DHD+j)*TS + cb2], vb);
        }
    };

    issue_kv(0, 0);
    CP_COMMIT();

    // Q: load fp32, scale, hi/lo split into smem (128 rows)
    #pragma unroll
    for (int i=0;i<8;i++){
        int id = tid + i*256;       // 0..2047
        int q = id>>4, c = id&15;
        float4 v = *(const float4*)&g_q[(bh*TS + qbase + q)*DHD + c*4];
        v.x *= 0.125f; v.y *= 0.125f; v.z *= 0.125f; v.w *= 0.125f;
        __nv_bfloat16 h0=__float2bfloat16(v.x), h1=__float2bfloat16(v.y);
        __nv_bfloat16 h2=__float2bfloat16(v.z), h3=__float2bfloat16(v.w);
        int o = q*ASK + c*8;
        *(uint32_t*)(smem + OQH + o)     = pkbf(__bfloat162float(h0), __bfloat162float(h1));
        *(uint32_t*)(smem + OQH + o + 4) = pkbf(__bfloat162float(h2), __bfloat162float(h3));
        *(uint32_t*)(smem + OQL + o)     = pkbf(v.x-__bfloat162float(h0), v.y-__bfloat162float(h1));
        *(uint32_t*)(smem + OQL + o + 4) = pkbf(v.z-__bfloat162float(h2), v.w-__bfloat162float(h3));
    }
    __syncthreads();

    // hoist Q fragments
    uint32_t qh[4][4], ql[4][4];
    int m0 = wid*16;
    #pragma unroll
    for (int kt=0;kt<4;kt++){
        int k0 = kt*16;
        qh[kt][0] = lds32(smem + OQH + (m0+g  )*ASK + (k0+2*t  )*2);
        qh[kt][1] = lds32(smem + OQH + (m0+g+8)*ASK + (k0+2*t  )*2);
        qh[kt][2] = lds32(smem + OQH + (m0+g  )*ASK + (k0+2*t+8)*2);
        qh[kt][3] = lds32(smem + OQH + (m0+g+8)*ASK + (k0+2*t+8)*2);
        ql[kt][0] = lds32(smem + OQL + (m0+g  )*ASK + (k0+2*t  )*2);
        ql[kt][1] = lds32(smem + OQL + (m0+g+8)*ASK + (k0+2*t  )*2);
        ql[kt][2] = lds32(smem + OQL + (m0+g  )*ASK + (k0+2*t+8)*2);
        ql[kt][3] = lds32(smem + OQL + (m0+g+8)*ASK + (k0+2*t+8)*2);
    }

    float oacc[8][4];
    #pragma unroll
    for (int np=0;np<8;np++){ oacc[np][0]=0.f; oacc[np][1]=0.f; oacc[np][2]=0.f; oacc[np][3]=0.f; }
    float sprev[2] = {-1e30f, -1e30f};
    float lrun[2]  = {0.f, 0.f};
    int NT = (cnt + 63) >> 6;

    for (int it=0; it<NT; it++){
        int kb = it*64;
        CP_WAIT0();
        __syncthreads();          // tile it visible; prior reads of slot (it+1)&1 done
        if (it+1 < NT) issue_kv((it+1)&1, kb+64);
        CP_COMMIT();
        const char* stg = smem + 2*AQ_REG + (it&1)*AST;
        const char* pKH = stg;
        const char* pKL = stg + 9216;
        const char* pVH = stg + 18432;
        const char* pVL = stg + 27648;

        // S = Q K^T (3 hi/lo combos)
        float sacc[8][4];
        #pragma unroll
        for (int np=0;np<8;np++){ sacc[np][0]=0.f; sacc[np][1]=0.f; sacc[np][2]=0.f; sacc[np][3]=0.f; }
        #pragma unroll
        for (int kt=0;kt<4;kt++){
            int k0 = kt*16;
            #pragma unroll
            for (int np=0;np<8;np++){
                int nn = np*8 + g;
                uint32_t bh2[2], bl2[2];
                bh2[0] = lds32(pKH + nn*ASK + (k0+2*t  )*2);
                bh2[1] = lds32(pKH + nn*ASK + (k0+2*t+8)*2);
                bl2[0] = lds32(pKL + nn*ASK + (k0+2*t  )*2);
                bl2[1] = lds32(pKL + nn*ASK + (k0+2*t+8)*2);
                mma16816(sacc[np], qh[kt], bh2);
                mma16816(sacc[np], qh[kt], bl2);
                mma16816(sacc[np], ql[kt], bh2);
            }
        }
        if (kb + 64 > cnt){
            #pragma unroll
            for (int np=0;np<8;np++)
              #pragma unroll
              for (int c=0;c<4;c++){
                  int j = kb + np*8 + 2*t + (c&1);
                  if (j >= cnt) sacc[np][c] = -1e30f;
              }
        }
        // online softmax
        float mt0 = sprev[0], mt1 = sprev[1];
        #pragma unroll
        for (int np=0;np<8;np++){
            mt0 = fmaxf(mt0, fmaxf(sacc[np][0], sacc[np][1]));
            mt1 = fmaxf(mt1, fmaxf(sacc[np][2], sacc[np][3]));
        }
        mt0 = fmaxf(mt0, __shfl_xor_sync(0xffffffffu, mt0, 1));
        mt0 = fmaxf(mt0, __shfl_xor_sync(0xffffffffu, mt0, 2));
        mt1 = fmaxf(mt1, __shfl_xor_sync(0xffffffffu, mt1, 1));
        mt1 = fmaxf(mt1, __shfl_xor_sync(0xffffffffu, mt1, 2));
        float c0 = __expf(sprev[0]-mt0), c1 = __expf(sprev[1]-mt1);
        float rs0 = 0.f, rs1 = 0.f;
        #pragma unroll
        for (int np=0;np<8;np++){
            sacc[np][0] = __expf(sacc[np][0]-mt0); rs0 += sacc[np][0];
            sacc[np][1] = __expf(sacc[np][1]-mt0); rs0 += sacc[np][1];
            sacc[np][2] = __expf(sacc[np][2]-mt1); rs1 += sacc[np][2];
            sacc[np][3] = __expf(sacc[np][3]-mt1); rs1 += sacc[np][3];
        }
        rs0 += __shfl_xor_sync(0xffffffffu, rs0, 1);
        rs0 += __shfl_xor_sync(0xffffffffu, rs0, 2);
        rs1 += __shfl_xor_sync(0xffffffffu, rs1, 1);
        rs1 += __shfl_xor_sync(0xffffffffu, rs1, 2);
        lrun[0] = lrun[0]*c0 + rs0;
        lrun[1] = lrun[1]*c1 + rs1;
        sprev[0] = mt0; sprev[1] = mt1;
        #pragma unroll
        for (int np=0;np<8;np++){
            oacc[np][0]*=c0; oacc[np][1]*=c0; oacc[np][2]*=c1; oacc[np][3]*=c1;
        }
        // O += P V (3 combos); P A-frags in-register (C-layout == A-layout)
        #pragma unroll
        for (int kt=0;kt<4;kt++){
            int k0 = kt*16;
            uint32_t ah[4], al[4];
            {
                float p0 = sacc[2*kt][0],   p1 = sacc[2*kt][1];
                float p2 = sacc[2*kt][2],   p3 = sacc[2*kt][3];
                float p4 = sacc[2*kt+1][0], p5 = sacc[2*kt+1][1];
                float p6 = sacc[2*kt+1][2], p7 = sacc[2*kt+1][3];
                ah[0] = pkbf(p0,p1); ah[1] = pkbf(p2,p3);
                ah[2] = pkbf(p4,p5); ah[3] = pkbf(p6,p7);
                al[0] = pkbf(p0-__bfloat162float(__float2bfloat16(p0)), p1-__bfloat162float(__float2bfloat16(p1)));
                al[1] = pkbf(p2-__bfloat162float(__float2bfloat16(p2)), p3-__bfloat162float(__float2bfloat16(p3)));
                al[2] = pkbf(p4-__bfloat162float(__float2bfloat16(p4)), p5-__bfloat162float(__float2bfloat16(p5)));
                al[3] = pkbf(p6-__bfloat162float(__float2bfloat16(p6)), p7-__bfloat162float(__float2bfloat16(p7)));
            }
            #pragma unroll
            for (int np=0;np<8;np++){
                int nn = np*8 + g;
                uint32_t vh2[2], vl2[2];
                vh2[0] = lds32(pVH + nn*ASK + (k0+2*t  )*2);
                vh2[1] = lds32(pVH + nn*ASK + (k0+2*t+8)*2);
                vl2[0] = lds32(pVL + nn*ASK + (k0+2*t  )*2);
                vl2[1] = lds32(pVL + nn*ASK + (k0+2*t+8)*2);
                mma16816(oacc[np], ah, vh2);
                mma16816(oacc[np], ah, vl2);
                mma16816(oacc[np], al, vh2);
            }
        }
    }
    // epilogue: normalize, hi/lo split, write ctx as bf16
    float inv0 = __fdiv_rn(1.0f, lrun[0]);
    float inv1 = __fdiv_rn(1.0f, lrun[1]);
    int t0 = qbase + m0 + g;
    int t1 = t0 + 8;
    #pragma unroll
    for (int np=0;np<8;np++){
        int col = h*DHD + np*8 + 2*t;
        float v0 = oacc[np][0]*inv0, v1 = oacc[np][1]*inv0;
        float v2 = oacc[np][2]*inv1, v3 = oacc[np][3]*inv1;
        __nv_bfloat16 h0=__float2bfloat16(v0), h1=__float2bfloat16(v1);
        __nv_bfloat16 h2=__float2bfloat16(v2), h3=__float2bfloat16(v3);
        *(uint32_t*)&g_chi[(b*TS + t0)*DM + col] = pkbf(__bfloat162float(h0), __bfloat162float(h1));
        *(uint32_t*)&g_clo[(b*TS + t0)*DM + col] = pkbf(v0-__bfloat162float(h0), v1-__bfloat162float(h1));
        *(uint32_t*)&g_chi[(b*TS + t1)*DM + col] = pkbf(__bfloat162float(h2), __bfloat162float(h3));
        *(uint32_t*)&g_clo[(b*TS + t1)*DM + col] = pkbf(v2-__bfloat162float(h2), v3-__bfloat162float(h3));
    }
}

// ---------------- 7. final per-tensor int8 quant-dequant ----------------
__global__ void quant_out_kernel(float* __restrict__ outp)
{
    float s = fmaxf(__fdiv_rn(__int_as_float(g_absmax), 127.0f), 1e-8f);
    int i = blockIdx.x*256 + threadIdx.x;
    float v = outp[i];
    float qv = rintf(__fdiv_rn(v, s));
    qv = fminf(fmaxf(qv, -127.f), 127.f);
    outp[i] = qv * s;
}

// ---------------- launch ----------------
extern "C" void kernel_launch(void* const* d_in, const int* in_sizes, int n_in,
                              void* d_out, int out_size)
{
    (void)in_sizes; (void)n_in; (void)out_size;
    const float* x  = (const float*)d_in[0];
    const int*   mk = (const int*)  d_in[1];
    const float* Wq = (const float*)d_in[2];
    const float* bq = (const float*)d_in[3];
    const float* Wk = (const float*)d_in[4];
    const float* bk = (const float*)d_in[5];
    const float* Wv = (const float*)d_in[6];
    const float* bv = (const float*)d_in[7];
    const float* Wo = (const float*)d_in[8];
    const float* bo = (const float*)d_in[9];
    float* outp = (float*)d_out;

    cudaFuncSetAttribute(gemm_mma_kernel, cudaFuncAttributeMaxDynamicSharedMemorySize, GEMM_SMEM);
    cudaFuncSetAttribute(attn_mma_kernel, cudaFuncAttributeMaxDynamicSharedMemorySize, ATT_SMEM);

    quant_weights_kernel<<<dim3(DM,4), 128>>>(Wq,Wk,Wv,Wo);
    split_x_kernel<<<(BT_*DM)/1024, 256>>>(x);
    compact_kernel<<<NB, 1024>>>(mk);
    gemm_mma_kernel<<<dim3(BT_/128, DM/128, 3), 256, GEMM_SMEM>>>(bq,bk,bv,bo, outp, 0);
    gather_kv_kernel<<<dim3(TS/64, BH_), 256>>>();
    attn_mma_kernel<<<dim3(TS/128, BH_), 256, ATT_SMEM>>>();
    gemm_mma_kernel<<<dim3(BT_/128, DM/128, 1), 256, GEMM_SMEM>>>(bq,bk,bv,bo, outp, 3);
    quant_out_kernel<<<(BT_*DM)/256, 256>>>(outp);
}

// round 12
// speedup vs baseline: 1.0328x; 1.0328x over previous
#include <cuda_runtime.h>
#include <cuda_bf16.h>
#include <math.h>
#include <stdint.h>

typedef unsigned long long ull;

#define DM 512
#define TS 4096
#define NB 2
#define NH 8
#define DHD 64
#define BT_ (NB*TS)    // 8192
#define BH_ (NB*NH)    // 16

// ---------------- device scratch (static, allocation-free) ----------------
// RULE (root cause of R4-R7 failures): these symbols are referenced ONLY
// inside device code. Never pass a __device__ symbol as a kernel argument.
__device__ __nv_bfloat16 g_Wb[4][DM*DM];
__device__ float g_ws[4][DM];
__device__ __nv_bfloat16 g_xhi[BT_*DM];
__device__ __nv_bfloat16 g_xlo[BT_*DM];
__device__ __nv_bfloat16 g_chi[BT_*DM];
__device__ __nv_bfloat16 g_clo[BT_*DM];
__device__ float g_q [BH_*TS*DHD];
__device__ float g_k [BH_*TS*DHD];
__device__ float g_v [BH_*TS*DHD];
__device__ __nv_bfloat16 g_kchi[BH_*TS*DHD];  // compacted K, [bh][j][d]
__device__ __nv_bfloat16 g_kclo[BH_*TS*DHD];
__device__ __nv_bfloat16 g_vchi[BH_*DHD*TS];  // compacted V transposed, [bh][d][j]
__device__ __nv_bfloat16 g_vclo[BH_*DHD*TS];
__device__ int   g_kept[NB*TS];
__device__ int   g_cnt[NB];
__device__ int   g_absmax;

// ---------------- mma / cp.async helpers ----------------
static __device__ __forceinline__ void mma16816(float* d, const uint32_t* a, const uint32_t* b){
    asm volatile("mma.sync.aligned.m16n8k16.row.col.f32.bf16.bf16.f32 "
        "{%0,%1,%2,%3}, {%4,%5,%6,%7}, {%8,%9}, {%0,%1,%2,%3};"
        : "+f"(d[0]),"+f"(d[1]),"+f"(d[2]),"+f"(d[3])
        : "r"(a[0]),"r"(a[1]),"r"(a[2]),"r"(a[3]), "r"(b[0]),"r"(b[1]));
}
static __device__ __forceinline__ uint32_t lds32(const void* p){
    return *(const uint32_t*)p;
}
static __device__ __forceinline__ uint32_t pkbf(float x, float y){
    uint32_t r; asm("cvt.rn.bf16x2.f32 %0, %1, %2;" : "=r"(r) : "f"(y), "f"(x)); return r;
}
static __device__ __forceinline__ uint32_t smem_u32(const void* p){
    uint32_t a;
    asm("{ .reg .u64 t; cvta.to.shared.u64 t, %1; cvt.u32.u64 %0, t; }" : "=r"(a) : "l"(p));
    return a;
}
static __device__ __forceinline__ void cp16(uint32_t dst, const void* src){
    asm volatile("cp.async.ca.shared.global [%0], [%1], 16;" :: "r"(dst), "l"(src) : "memory");
}
static __device__ __forceinline__ void cp16z(uint32_t dst, const void* src, int ssz){
    asm volatile("cp.async.ca.shared.global [%0], [%1], 16, %2;" :: "r"(dst), "l"(src), "r"(ssz) : "memory");
}
#define CP_COMMIT() asm volatile("cp.async.commit_group;" ::: "memory")
#define CP_WAIT1()  asm volatile("cp.async.wait_group 1;" ::: "memory")
#define CP_WAIT0()  asm volatile("cp.async.wait_group 0;" ::: "memory")

// ---------------- 1. per-row symmetric int8 weight quant ----------------
__global__ void quant_weights_kernel(const float* __restrict__ Wq, const float* __restrict__ Wk,
                                     const float* __restrict__ Wv, const float* __restrict__ Wo)
{
    int w = blockIdx.y;
    int row = blockIdx.x;
    const float* srcs[4] = {Wq, Wk, Wv, Wo};
    const float* wr = srcs[w] + row*DM;
    __nv_bfloat16* dst = &g_Wb[w][row*DM];
    int tid = threadIdx.x; // 128
    if (w==0 && row==0 && tid==0) g_absmax = 0;
    float mx = 0.f;
    for (int i=tid;i<DM;i+=128) mx = fmaxf(mx, fabsf(wr[i]));
    for (int off=16;off;off>>=1) mx = fmaxf(mx, __shfl_xor_sync(0xffffffffu, mx, off));
    __shared__ float sm4[4];
    if ((tid&31)==0) sm4[tid>>5] = mx;
    __syncthreads();
    mx = fmaxf(fmaxf(sm4[0],sm4[1]), fmaxf(sm4[2],sm4[3]));
    float s = fmaxf(__fdiv_rn(mx, 127.0f), 1e-8f);
    if (tid==0) g_ws[w][row] = s;
    for (int i=tid;i<DM;i+=128){
        float qv = rintf(__fdiv_rn(wr[i], s));
        qv = fminf(fmaxf(qv, -127.f), 127.f);
        dst[i] = __float2bfloat16(qv);
    }
}

// ---------------- 1b. bf16 hi/lo split of x ----------------
__global__ void split_x_kernel(const float* __restrict__ src)
{
    int i = (blockIdx.x*256 + threadIdx.x)*4;
    float4 v = *(const float4*)&src[i];
    __nv_bfloat16 h0=__float2bfloat16(v.x), h1=__float2bfloat16(v.y);
    __nv_bfloat16 h2=__float2bfloat16(v.z), h3=__float2bfloat16(v.w);
    __nv_bfloat162 hA; hA.x=h0; hA.y=h1;
    __nv_bfloat162 hB; hB.x=h2; hB.y=h3;
    __nv_bfloat162 lA; lA.x=__float2bfloat16(v.x-__bfloat162float(h0)); lA.y=__float2bfloat16(v.y-__bfloat162float(h1));
    __nv_bfloat162 lB; lB.x=__float2bfloat16(v.z-__bfloat162float(h2)); lB.y=__float2bfloat16(v.w-__bfloat162float(h3));
    *(__nv_bfloat162*)&g_xhi[i]   = hA;
    *(__nv_bfloat162*)&g_xhi[i+2] = hB;
    *(__nv_bfloat162*)&g_xlo[i]   = lA;
    *(__nv_bfloat162*)&g_xlo[i+2] = lB;
}

// ---------------- 2. mask compaction ----------------
__global__ void compact_kernel(const int* __restrict__ mask)
{
    int b = blockIdx.x;
    const int* m = mask + b*TS;
    __shared__ int part[1024];
    int tid = threadIdx.x; // 1024
    int base = tid*4;
    int f0 = m[base]!=0, f1 = m[base+1]!=0, f2 = m[base+2]!=0, f3 = m[base+3]!=0;
    int s = f0+f1+f2+f3;
    part[tid] = s;
    __syncthreads();
    for (int off=1; off<1024; off<<=1){
        int v = (tid>=off) ? part[tid-off] : 0;
        __syncthreads();
        part[tid] += v;
        __syncthreads();
    }
    int o = part[tid] - s + b*TS;
    if (f0) g_kept[o++] = base;
    if (f1) g_kept[o++] = base+1;
    if (f2) g_kept[o++] = base+2;
    if (f3) g_kept[o++] = base+3;
    if (tid==1023) g_cnt[b] = part[1023];
}

// ---------------- 3. mma GEMM, cp.async 2-stage pipeline (R10 structure, proven 95.9us) ------
#define GTILE 10240
#define GST3  (3*GTILE)          // 30720 per stage
#define GEMM_SMEM (2*GST3)       // 61440
__global__ void __launch_bounds__(256) gemm_mma_kernel(
    const float* __restrict__ bq, const float* __restrict__ bk,
    const float* __restrict__ bv, const float* __restrict__ bo,
    float* __restrict__ outp, int modebase)
{
    extern __shared__ __align__(16) char dsm[];
    __shared__ float s_sc[128], s_bi[128];
    __shared__ float red8[8];
    int mode = modebase + blockIdx.z;
    int tid = threadIdx.x, lane = tid&31, wid = tid>>5;
    int wm = wid>>1, wn = wid&1;
    int g = lane>>2, t = lane&3;
    int rowbase = blockIdx.x*128, nbase = blockIdx.y*128;
    uint32_t sbase = smem_u32(dsm);

    const __nv_bfloat16* __restrict__ Ahi = (mode<3) ? g_xhi : g_chi;
    const __nv_bfloat16* __restrict__ Alo = (mode<3) ? g_xlo : g_clo;
    const __nv_bfloat16* __restrict__ Bw  = g_Wb[mode];
    const float* biasp = (mode==0)?bq:((mode==1)?bk:((mode==2)?bv:bo));

    auto issue_tile = [&](int st, int kt){
        uint32_t stg = sbase + st*GST3;
        int kb = kt*32;
        #pragma unroll
        for (int i=0;i<2;i++){
            int id = tid + i*256;   // 0..511
            int r = id>>2, c = id&3;
            cp16(stg +           r*80 + c*16, &Ahi[(rowbase+r)*DM + kb + c*8]);
            cp16(stg + GTILE   + r*80 + c*16, &Alo[(rowbase+r)*DM + kb + c*8]);
            cp16(stg + 2*GTILE + r*80 + c*16, &Bw [(nbase  +r)*DM + kb + c*8]);
        }
    };

    issue_tile(0, 0);
    CP_COMMIT();
    if (tid<128) s_sc[tid] = g_ws[mode][nbase+tid];
    else         s_bi[tid-128] = biasp[nbase+tid-128];

    float acc[2][8][4];
    #pragma unroll
    for (int mt=0;mt<2;mt++)
      #pragma unroll
      for (int nt=0;nt<8;nt++)
        #pragma unroll
        for (int c=0;c<4;c++) acc[mt][nt][c] = 0.f;

    for (int kt=0; kt<16; kt++){
        if (kt+1 < 16) issue_tile((kt+1)&1, kt+1);
        CP_COMMIT();
        CP_WAIT1();
        __syncthreads();
        const char* stg = dsm + (kt&1)*GST3;
        #pragma unroll
        for (int ks=0; ks<32; ks+=16){
            uint32_t af[2][2][4];
            #pragma unroll
            for (int h=0; h<2; h++)
              #pragma unroll
              for (int mt=0; mt<2; mt++){
                int r0 = wm*32 + mt*16;
                const char* base = stg + h*GTILE;
                af[h][mt][0] = lds32(base + (r0+g  )*80 + (ks+2*t  )*2);
                af[h][mt][1] = lds32(base + (r0+g+8)*80 + (ks+2*t  )*2);
                af[h][mt][2] = lds32(base + (r0+g  )*80 + (ks+2*t+8)*2);
                af[h][mt][3] = lds32(base + (r0+g+8)*80 + (ks+2*t+8)*2);
              }
            #pragma unroll
            for (int np=0; np<8; np++){
                int n0 = wn*64 + np*8;
                uint32_t bf2[2];
                bf2[0] = lds32(stg + 2*GTILE + (n0+g)*80 + (ks+2*t  )*2);
                bf2[1] = lds32(stg + 2*GTILE + (n0+g)*80 + (ks+2*t+8)*2);
                #pragma unroll
                for (int mt=0; mt<2; mt++){
                    mma16816(acc[mt][np], af[0][mt], bf2);
                    mma16816(acc[mt][np], af[1][mt], bf2);
                }
            }
        }
        __syncthreads();
    }
    float amax = 0.f;
    float* qkv = (mode==0)?g_q:((mode==1)?g_k:g_v);
    #pragma unroll
    for (int mt=0;mt<2;mt++){
      #pragma unroll
      for (int nt=0;nt<8;nt++){
        int ncol = wn*64 + nt*8 + 2*t;
        float s0 = s_sc[ncol], s1 = s_sc[ncol+1];
        float b0 = s_bi[ncol], b1 = s_bi[ncol+1];
        #pragma unroll
        for (int rh=0; rh<2; rh++){
            int row = rowbase + wm*32 + mt*16 + g + rh*8;
            float v0 = acc[mt][nt][rh*2  ]*s0 + b0;
            float v1 = acc[mt][nt][rh*2+1]*s1 + b1;
            float2 w; w.x = v0; w.y = v1;
            if (mode<3){
                int o = nbase + ncol;
                int head = o>>6, dh = o&63;
                int bb = row>>12, tt = row&4095;
                *(float2*)&qkv[((bb*NH+head)*TS + tt)*DHD + dh] = w;
            } else {
                *(float2*)&outp[row*DM + nbase + ncol] = w;
                amax = fmaxf(amax, fmaxf(fabsf(v0), fabsf(v1)));
            }
        }
      }
    }
    if (mode==3){
        for (int off=16;off;off>>=1) amax = fmaxf(amax, __shfl_xor_sync(0xffffffffu, amax, off));
        if (lane==0) red8[wid] = amax;
        __syncthreads();
        if (tid==0){
            float m = red8[0];
            #pragma unroll
            for (int i=1;i<8;i++) m = fmaxf(m, red8[i]);
            atomicMax(&g_absmax, __float_as_int(m));
        }
    }
}

// ---------------- 4. fused coalesced gather (R11, proven): K -> [bh][j][d], V -> [bh][d][j] ---
__global__ void __launch_bounds__(256) gather_kv_kernel()
{
    __shared__ float vs[64][65];
    __shared__ int srcs[64];
    int bh = blockIdx.y;
    int b = bh>>3;
    int jbase = blockIdx.x*64;
    int cnt = g_cnt[b];
    int tid = threadIdx.x;
    if (tid < 64){
        int j = jbase + tid;
        srcs[tid] = (j < cnt) ? g_kept[b*TS + j] : -1;
    }
    __syncthreads();
    #pragma unroll
    for (int i=0;i<16;i++){
        int id = tid + i*256;
        int j = id>>6, d = id&63;
        int src = srcs[j];
        if (src >= 0){
            float kv = g_k[(bh*TS + src)*DHD + d];
            __nv_bfloat16 h = __float2bfloat16(kv);
            int o = (bh*TS + jbase + j)*DHD + d;
            g_kchi[o] = h;
            g_kclo[o] = __float2bfloat16(kv - __bfloat162float(h));
            vs[j][d] = g_v[(bh*TS + src)*DHD + d];
        } else {
            vs[j][d] = 0.f;
        }
    }
    __syncthreads();
    #pragma unroll
    for (int i=0;i<16;i++){
        int id = tid + i*256;
        int d = id>>6, j = id&63;
        float vv = vs[j][d];
        __nv_bfloat16 h = __float2bfloat16(vv);
        int o = (bh*DHD + d)*TS + jbase + j;
        g_vchi[o] = h;
        g_vclo[o] = __float2bfloat16(vv - __bfloat162float(h));
    }
}

// ---------------- 5. flash attention (R11, proven): BQ=128, BK=64, single-sync pipeline -------
#define ASK 144                  // row stride bytes (72 bf16; 16B aligned)
#define AQ_REG 18432             // Q hi or lo: 128 rows x 144B
#define AST   36864              // per KV stage: KH|KL|VH|VL, 64x144 each
#define ATT_SMEM (2*AQ_REG + 2*AST)   // 110592
__global__ void __launch_bounds__(256, 2) attn_mma_kernel()
{
    extern __shared__ __align__(16) char smem[];
    const int OQH=0, OQL=AQ_REG;
    int bh = blockIdx.y;
    int b = bh>>3, h = bh&7;
    int qbase = blockIdx.x*128;
    int tid = threadIdx.x, lane = tid&31, wid = tid>>5;
    int g = lane>>2, t = lane&3;
    int cnt = g_cnt[b];
    uint32_t sbase = smem_u32(smem);

    auto issue_kv = [&](int st, int kb){
        uint32_t stg = sbase + 2*AQ_REG + st*AST;
        #pragma unroll
        for (int i=0;i<2;i++){
            int id = tid + i*256;   // 0..511
            int j = id>>3, c = id&7;
            int jj = kb + j;
            int kssz = (jj < cnt) ? 16 : 0;
            int jc = jj < TS ? jj : TS-1;
            cp16z(stg +         j*ASK + c*16, &g_kchi[(bh*TS+jc)*DHD + c*8], kssz);
            cp16z(stg +  9216 + j*ASK + c*16, &g_kclo[(bh*TS+jc)*DHD + c*8], kssz);
            int vb = (cnt - (kb + c*8))*2;
            vb = vb < 0 ? 0 : (vb > 16 ? 16 : vb);
            int cb2 = kb + c*8; if (cb2 > TS-8) cb2 = TS-8;
            cp16z(stg + 18432 + j*ASK + c*16, &g_vchi[(bh*DHD+j)*TS + cb2], vb);
            cp16z(stg + 27648 + j*ASK + c*16, &g_vclo[(bh*DHD+j)*TS + cb2], vb);
        }
    };

    issue_kv(0, 0);
    CP_COMMIT();

    // Q: load fp32, scale, hi/lo split into smem (128 rows)
    #pragma unroll
    for (int i=0;i<8;i++){
        int id = tid + i*256;       // 0..2047
        int q = id>>4, c = id&15;
        float4 v = *(const float4*)&g_q[(bh*TS + qbase + q)*DHD + c*4];
        v.x *= 0.125f; v.y *= 0.125f; v.z *= 0.125f; v.w *= 0.125f;
        __nv_bfloat16 h0=__float2bfloat16(v.x), h1=__float2bfloat16(v.y);
        __nv_bfloat16 h2=__float2bfloat16(v.z), h3=__float2bfloat16(v.w);
        int o = q*ASK + c*8;
        *(uint32_t*)(smem + OQH + o)     = pkbf(__bfloat162float(h0), __bfloat162float(h1));
        *(uint32_t*)(smem + OQH + o + 4) = pkbf(__bfloat162float(h2), __bfloat162float(h3));
        *(uint32_t*)(smem + OQL + o)     = pkbf(v.x-__bfloat162float(h0), v.y-__bfloat162float(h1));
        *(uint32_t*)(smem + OQL + o + 4) = pkbf(v.z-__bfloat162float(h2), v.w-__bfloat162float(h3));
    }
    __syncthreads();

    // hoist Q fragments
    uint32_t qh[4][4], ql[4][4];
    int m0 = wid*16;
    #pragma unroll
    for (int kt=0;kt<4;kt++){
        int k0 = kt*16;
        qh[kt][0] = lds32(smem + OQH + (m0+g  )*ASK + (k0+2*t  )*2);
        qh[kt][1] = lds32(smem + OQH + (m0+g+8)*ASK + (k0+2*t  )*2);
        qh[kt][2] = lds32(smem + OQH + (m0+g  )*ASK + (k0+2*t+8)*2);
        qh[kt][3] = lds32(smem + OQH + (m0+g+8)*ASK + (k0+2*t+8)*2);
        ql[kt][0] = lds32(smem + OQL + (m0+g  )*ASK + (k0+2*t  )*2);
        ql[kt][1] = lds32(smem + OQL + (m0+g+8)*ASK + (k0+2*t  )*2);
        ql[kt][2] = lds32(smem + OQL + (m0+g  )*ASK + (k0+2*t+8)*2);
        ql[kt][3] = lds32(smem + OQL + (m0+g+8)*ASK + (k0+2*t+8)*2);
    }

    float oacc[8][4];
    #pragma unroll
    for (int np=0;np<8;np++){ oacc[np][0]=0.f; oacc[np][1]=0.f; oacc[np][2]=0.f; oacc[np][3]=0.f; }
    float sprev[2] = {-1e30f, -1e30f};
    float lrun[2]  = {0.f, 0.f};
    int NT = (cnt + 63) >> 6;

    for (int it=0; it<NT; it++){
        int kb = it*64;
        CP_WAIT0();
        __syncthreads();          // tile it visible; prior reads of slot (it+1)&1 done
        if (it+1 < NT) issue_kv((it+1)&1, kb+64);
        CP_COMMIT();
        const char* stg = smem + 2*AQ_REG + (it&1)*AST;
        const char* pKH = stg;
        const char* pKL = stg + 9216;
        const char* pVH = stg + 18432;
        const char* pVL = stg + 27648;

        // S = Q K^T (3 hi/lo combos)
        float sacc[8][4];
        #pragma unroll
        for (int np=0;np<8;np++){ sacc[np][0]=0.f; sacc[np][1]=0.f; sacc[np][2]=0.f; sacc[np][3]=0.f; }
        #pragma unroll
        for (int kt=0;kt<4;kt++){
            int k0 = kt*16;
            #pragma unroll
            for (int np=0;np<8;np++){
                int nn = np*8 + g;
                uint32_t bh2[2], bl2[2];
                bh2[0] = lds32(pKH + nn*ASK + (k0+2*t  )*2);
                bh2[1] = lds32(pKH + nn*ASK + (k0+2*t+8)*2);
                bl2[0] = lds32(pKL + nn*ASK + (k0+2*t  )*2);
                bl2[1] = lds32(pKL + nn*ASK + (k0+2*t+8)*2);
                mma16816(sacc[np], qh[kt], bh2);
                mma16816(sacc[np], qh[kt], bl2);
                mma16816(sacc[np], ql[kt], bh2);
            }
        }
        if (kb + 64 > cnt){
            #pragma unroll
            for (int np=0;np<8;np++)
              #pragma unroll
              for (int c=0;c<4;c++){
                  int j = kb + np*8 + 2*t + (c&1);
                  if (j >= cnt) sacc[np][c] = -1e30f;
              }
        }
        // online softmax
        float mt0 = sprev[0], mt1 = sprev[1];
        #pragma unroll
        for (int np=0;np<8;np++){
            mt0 = fmaxf(mt0, fmaxf(sacc[np][0], sacc[np][1]));
            mt1 = fmaxf(mt1, fmaxf(sacc[np][2], sacc[np][3]));
        }
        mt0 = fmaxf(mt0, __shfl_xor_sync(0xffffffffu, mt0, 1));
        mt0 = fmaxf(mt0, __shfl_xor_sync(0xffffffffu, mt0, 2));
        mt1 = fmaxf(mt1, __shfl_xor_sync(0xffffffffu, mt1, 1));
        mt1 = fmaxf(mt1, __shfl_xor_sync(0xffffffffu, mt1, 2));
        float c0 = __expf(sprev[0]-mt0), c1 = __expf(sprev[1]-mt1);
        float rs0 = 0.f, rs1 = 0.f;
        #pragma unroll
        for (int np=0;np<8;np++){
            sacc[np][0] = __expf(sacc[np][0]-mt0); rs0 += sacc[np][0];
            sacc[np][1] = __expf(sacc[np][1]-mt0); rs0 += sacc[np][1];
            sacc[np][2] = __expf(sacc[np][2]-mt1); rs1 += sacc[np][2];
            sacc[np][3] = __expf(sacc[np][3]-mt1); rs1 += sacc[np][3];
        }
        rs0 += __shfl_xor_sync(0xffffffffu, rs0, 1);
        rs0 += __shfl_xor_sync(0xffffffffu, rs0, 2);
        rs1 += __shfl_xor_sync(0xffffffffu, rs1, 1);
        rs1 += __shfl_xor_sync(0xffffffffu, rs1, 2);
        lrun[0] = lrun[0]*c0 + rs0;
        lrun[1] = lrun[1]*c1 + rs1;
        sprev[0] = mt0; sprev[1] = mt1;
        #pragma unroll
        for (int np=0;np<8;np++){
            oacc[np][0]*=c0; oacc[np][1]*=c0; oacc[np][2]*=c1; oacc[np][3]*=c1;
        }
        // O += P V (3 combos); P A-frags in-register (C-layout == A-layout)
        #pragma unroll
        for (int kt=0;kt<4;kt++){
            int k0 = kt*16;
            uint32_t ah[4], al[4];
            {
                float p0 = sacc[2*kt][0],   p1 = sacc[2*kt][1];
                float p2 = sacc[2*kt][2],   p3 = sacc[2*kt][3];
                float p4 = sacc[2*kt+1][0], p5 = sacc[2*kt+1][1];
                float p6 = sacc[2*kt+1][2], p7 = sacc[2*kt+1][3];
                ah[0] = pkbf(p0,p1); ah[1] = pkbf(p2,p3);
                ah[2] = pkbf(p4,p5); ah[3] = pkbf(p6,p7);
                al[0] = pkbf(p0-__bfloat162float(__float2bfloat16(p0)), p1-__bfloat162float(__float2bfloat16(p1)));
                al[1] = pkbf(p2-__bfloat162float(__float2bfloat16(p2)), p3-__bfloat162float(__float2bfloat16(p3)));
                al[2] = pkbf(p4-__bfloat162float(__float2bfloat16(p4)), p5-__bfloat162float(__float2bfloat16(p5)));
                al[3] = pkbf(p6-__bfloat162float(__float2bfloat16(p6)), p7-__bfloat162float(__float2bfloat16(p7)));
            }
            #pragma unroll
            for (int np=0;np<8;np++){
                int nn = np*8 + g;
                uint32_t vh2[2], vl2[2];
                vh2[0] = lds32(pVH + nn*ASK + (k0+2*t  )*2);
                vh2[1] = lds32(pVH + nn*ASK + (k0+2*t+8)*2);
                vl2[0] = lds32(pVL + nn*ASK + (k0+2*t  )*2);
                vl2[1] = lds32(pVL + nn*ASK + (k0+2*t+8)*2);
                mma16816(oacc[np], ah, vh2);
                mma16816(oacc[np], ah, vl2);
                mma16816(oacc[np], al, vh2);
            }
        }
    }
    // epilogue: normalize, hi/lo split, write ctx as bf16
    float inv0 = __fdiv_rn(1.0f, lrun[0]);
    float inv1 = __fdiv_rn(1.0f, lrun[1]);
    int t0 = qbase + m0 + g;
    int t1 = t0 + 8;
    #pragma unroll
    for (int np=0;np<8;np++){
        int col = h*DHD + np*8 + 2*t;
        float v0 = oacc[np][0]*inv0, v1 = oacc[np][1]*inv0;
        float v2 = oacc[np][2]*inv1, v3 = oacc[np][3]*inv1;
        __nv_bfloat16 h0=__float2bfloat16(v0), h1=__float2bfloat16(v1);
        __nv_bfloat16 h2=__float2bfloat16(v2), h3=__float2bfloat16(v3);
        *(uint32_t*)&g_chi[(b*TS + t0)*DM + col] = pkbf(__bfloat162float(h0), __bfloat162float(h1));
        *(uint32_t*)&g_clo[(b*TS + t0)*DM + col] = pkbf(v0-__bfloat162float(h0), v1-__bfloat162float(h1));
        *(uint32_t*)&g_chi[(b*TS + t1)*DM + col] = pkbf(__bfloat162float(h2), __bfloat162float(h3));
        *(uint32_t*)&g_clo[(b*TS + t1)*DM + col] = pkbf(v2-__bfloat162float(h2), v3-__bfloat162float(h3));
    }
}

// ---------------- 7. final per-tensor int8 quant-dequant ----------------
__global__ void quant_out_kernel(float* __restrict__ outp)
{
    float s = fmaxf(__fdiv_rn(__int_as_float(g_absmax), 127.0f), 1e-8f);
    int i = blockIdx.x*256 + threadIdx.x;
    float v = outp[i];
    float qv = rintf(__fdiv_rn(v, s));
    qv = fminf(fmaxf(qv, -127.f), 127.f);
    outp[i] = qv * s;
}

// ---------------- launch ----------------
extern "C" void kernel_launch(void* const* d_in, const int* in_sizes, int n_in,
                              void* d_out, int out_size)
{
    (void)in_sizes; (void)n_in; (void)out_size;
    const float* x  = (const float*)d_in[0];
    const int*   mk = (const int*)  d_in[1];
    const float* Wq = (const float*)d_in[2];
    const float* bq = (const float*)d_in[3];
    const float* Wk = (const float*)d_in[4];
    const float* bk = (const float*)d_in[5];
    const float* Wv = (const float*)d_in[6];
    const float* bv = (const float*)d_in[7];
    const float* Wo = (const float*)d_in[8];
    const float* bo = (const float*)d_in[9];
    float* outp = (float*)d_out;

    cudaFuncSetAttribute(gemm_mma_kernel, cudaFuncAttributeMaxDynamicSharedMemorySize, GEMM_SMEM);
    cudaFuncSetAttribute(attn_mma_kernel, cudaFuncAttributeMaxDynamicSharedMemorySize, ATT_SMEM);

    quant_weights_kernel<<<dim3(DM,4), 128>>>(Wq,Wk,Wv,Wo);
    split_x_kernel<<<(BT_*DM)/1024, 256>>>(x);
    compact_kernel<<<NB, 1024>>>(mk);
    gemm_mma_kernel<<<dim3(BT_/128, DM/128, 3), 256, GEMM_SMEM>>>(bq,bk,bv,bo, outp, 0);
    gather_kv_kernel<<<dim3(TS/64, BH_), 256>>>();
    attn_mma_kernel<<<dim3(TS/128, BH_), 256, ATT_SMEM>>>();
    gemm_mma_kernel<<<dim3(BT_/128, DM/128, 1), 256, GEMM_SMEM>>>(bq,bk,bv,bo, outp, 3);
    quant_out_kernel<<<(BT_*DM)/256, 256>>>(outp);
}

// round 13
// speedup vs baseline: 1.1084x; 1.0732x over previous
#include <cuda_runtime.h>
#include <cuda_bf16.h>
#include <math.h>
#include <stdint.h>

typedef unsigned long long ull;

#define DM 512
#define TS 4096
#define NB 2
#define NH 8
#define DHD 64
#define BT_ (NB*TS)    // 8192
#define BH_ (NB*NH)    // 16

// ---------------- device scratch (static, allocation-free) ----------------
// RULE (root cause of R4-R7 failures): these symbols are referenced ONLY
// inside device code. Never pass a __device__ symbol as a kernel argument.
__device__ __nv_bfloat16 g_Wb[4][DM*DM];
__device__ float g_ws[4][DM];
__device__ __nv_bfloat16 g_xhi[BT_*DM];
__device__ __nv_bfloat16 g_xlo[BT_*DM];
__device__ __nv_bfloat16 g_chi[BT_*DM];
__device__ __nv_bfloat16 g_clo[BT_*DM];
__device__ float g_q [BH_*TS*DHD];
__device__ float g_k [BH_*TS*DHD];
__device__ float g_v [BH_*TS*DHD];
__device__ __nv_bfloat16 g_kchi[BH_*TS*DHD];  // compacted K, [bh][j][d]
__device__ __nv_bfloat16 g_kclo[BH_*TS*DHD];
__device__ __nv_bfloat16 g_vchi[BH_*DHD*TS];  // compacted V transposed, [bh][d][j]
__device__ __nv_bfloat16 g_vclo[BH_*DHD*TS];
__device__ int   g_kept[NB*TS];
__device__ int   g_cnt[NB];
__device__ int   g_absmax;

// ---------------- mma / ldmatrix / cp.async helpers ----------------
static __device__ __forceinline__ void mma16816(float* d, const uint32_t* a, const uint32_t* b){
    asm volatile("mma.sync.aligned.m16n8k16.row.col.f32.bf16.bf16.f32 "
        "{%0,%1,%2,%3}, {%4,%5,%6,%7}, {%8,%9}, {%0,%1,%2,%3};"
        : "+f"(d[0]),"+f"(d[1]),"+f"(d[2]),"+f"(d[3])
        : "r"(a[0]),"r"(a[1]),"r"(a[2]),"r"(a[3]), "r"(b[0]),"r"(b[1]));
}
// ldmatrix x4: loader proven bit-equivalent to direct-LDS fragments (R5==R6 evidence)
static __device__ __forceinline__ void ldsm4(uint32_t* r, uint32_t a){
    asm volatile("ldmatrix.sync.aligned.m8n8.x4.shared.b16 {%0,%1,%2,%3}, [%4];"
        : "=r"(r[0]),"=r"(r[1]),"=r"(r[2]),"=r"(r[3]) : "r"(a));
}
static __device__ __forceinline__ uint32_t pkbf(float x, float y){
    uint32_t r; asm("cvt.rn.bf16x2.f32 %0, %1, %2;" : "=r"(r) : "f"(y), "f"(x)); return r;
}
static __device__ __forceinline__ uint32_t smem_u32(const void* p){
    uint32_t a;
    asm("{ .reg .u64 t; cvta.to.shared.u64 t, %1; cvt.u32.u64 %0, t; }" : "=r"(a) : "l"(p));
    return a;
}
static __device__ __forceinline__ void cp16(uint32_t dst, const void* src){
    asm volatile("cp.async.ca.shared.global [%0], [%1], 16;" :: "r"(dst), "l"(src) : "memory");
}
static __device__ __forceinline__ void cp16z(uint32_t dst, const void* src, int ssz){
    asm volatile("cp.async.ca.shared.global [%0], [%1], 16, %2;" :: "r"(dst), "l"(src), "r"(ssz) : "memory");
}
#define CP_COMMIT() asm volatile("cp.async.commit_group;" ::: "memory")
#define CP_WAIT1()  asm volatile("cp.async.wait_group 1;" ::: "memory")
#define CP_WAIT0()  asm volatile("cp.async.wait_group 0;" ::: "memory")

// ---------------- 1. per-row symmetric int8 weight quant ----------------
__global__ void quant_weights_kernel(const float* __restrict__ Wq, const float* __restrict__ Wk,
                                     const float* __restrict__ Wv, const float* __restrict__ Wo)
{
    int w = blockIdx.y;
    int row = blockIdx.x;
    const float* srcs[4] = {Wq, Wk, Wv, Wo};
    const float* wr = srcs[w] + row*DM;
    __nv_bfloat16* dst = &g_Wb[w][row*DM];
    int tid = threadIdx.x; // 128
    if (w==0 && row==0 && tid==0) g_absmax = 0;
    float mx = 0.f;
    for (int i=tid;i<DM;i+=128) mx = fmaxf(mx, fabsf(wr[i]));
    for (int off=16;off;off>>=1) mx = fmaxf(mx, __shfl_xor_sync(0xffffffffu, mx, off));
    __shared__ float sm4[4];
    if ((tid&31)==0) sm4[tid>>5] = mx;
    __syncthreads();
    mx = fmaxf(fmaxf(sm4[0],sm4[1]), fmaxf(sm4[2],sm4[3]));
    float s = fmaxf(__fdiv_rn(mx, 127.0f), 1e-8f);
    if (tid==0) g_ws[w][row] = s;
    for (int i=tid;i<DM;i+=128){
        float qv = rintf(__fdiv_rn(wr[i], s));
        qv = fminf(fmaxf(qv, -127.f), 127.f);
        dst[i] = __float2bfloat16(qv);
    }
}

// ---------------- 1b. bf16 hi/lo split of x ----------------
__global__ void split_x_kernel(const float* __restrict__ src)
{
    int i = (blockIdx.x*256 + threadIdx.x)*4;
    float4 v = *(const float4*)&src[i];
    __nv_bfloat16 h0=__float2bfloat16(v.x), h1=__float2bfloat16(v.y);
    __nv_bfloat16 h2=__float2bfloat16(v.z), h3=__float2bfloat16(v.w);
    __nv_bfloat162 hA; hA.x=h0; hA.y=h1;
    __nv_bfloat162 hB; hB.x=h2; hB.y=h3;
    __nv_bfloat162 lA; lA.x=__float2bfloat16(v.x-__bfloat162float(h0)); lA.y=__float2bfloat16(v.y-__bfloat162float(h1));
    __nv_bfloat162 lB; lB.x=__float2bfloat16(v.z-__bfloat162float(h2)); lB.y=__float2bfloat16(v.w-__bfloat162float(h3));
    *(__nv_bfloat162*)&g_xhi[i]   = hA;
    *(__nv_bfloat162*)&g_xhi[i+2] = hB;
    *(__nv_bfloat162*)&g_xlo[i]   = lA;
    *(__nv_bfloat162*)&g_xlo[i+2] = lB;
}

// ---------------- 2. mask compaction ----------------
__global__ void compact_kernel(const int* __restrict__ mask)
{
    int b = blockIdx.x;
    const int* m = mask + b*TS;
    __shared__ int part[1024];
    int tid = threadIdx.x; // 1024
    int base = tid*4;
    int f0 = m[base]!=0, f1 = m[base+1]!=0, f2 = m[base+2]!=0, f3 = m[base+3]!=0;
    int s = f0+f1+f2+f3;
    part[tid] = s;
    __syncthreads();
    for (int off=1; off<1024; off<<=1){
        int v = (tid>=off) ? part[tid-off] : 0;
        __syncthreads();
        part[tid] += v;
        __syncthreads();
    }
    int o = part[tid] - s + b*TS;
    if (f0) g_kept[o++] = base;
    if (f1) g_kept[o++] = base+1;
    if (f2) g_kept[o++] = base+2;
    if (f3) g_kept[o++] = base+3;
    if (tid==1023) g_cnt[b] = part[1023];
}

// ---------------- 3. mma GEMM, cp.async 2-stage pipeline + ldmatrix fragments ----------------
#define GTILE 10240
#define GST3  (3*GTILE)          // 30720 per stage
#define GEMM_SMEM (2*GST3)       // 61440
__global__ void __launch_bounds__(256) gemm_mma_kernel(
    const float* __restrict__ bq, const float* __restrict__ bk,
    const float* __restrict__ bv, const float* __restrict__ bo,
    float* __restrict__ outp, int modebase)
{
    extern __shared__ __align__(16) char dsm[];
    __shared__ float s_sc[128], s_bi[128];
    __shared__ float red8[8];
    int mode = modebase + blockIdx.z;
    int tid = threadIdx.x, lane = tid&31, wid = tid>>5;
    int wm = wid>>1, wn = wid&1;
    int g = lane>>2, t = lane&3;
    int rowbase = blockIdx.x*128, nbase = blockIdx.y*128;
    uint32_t sbase = smem_u32(dsm);

    const __nv_bfloat16* __restrict__ Ahi = (mode<3) ? g_xhi : g_chi;
    const __nv_bfloat16* __restrict__ Alo = (mode<3) ? g_xlo : g_clo;
    const __nv_bfloat16* __restrict__ Bw  = g_Wb[mode];
    const float* biasp = (mode==0)?bq:((mode==1)?bk:((mode==2)?bv:bo));

    auto issue_tile = [&](int st, int kt){
        uint32_t stg = sbase + st*GST3;
        int kb = kt*32;
        #pragma unroll
        for (int i=0;i<2;i++){
            int id = tid + i*256;   // 0..511
            int r = id>>2, c = id&3;
            cp16(stg +           r*80 + c*16, &Ahi[(rowbase+r)*DM + kb + c*8]);
            cp16(stg + GTILE   + r*80 + c*16, &Alo[(rowbase+r)*DM + kb + c*8]);
            cp16(stg + 2*GTILE + r*80 + c*16, &Bw [(nbase  +r)*DM + kb + c*8]);
        }
    };

    issue_tile(0, 0);
    CP_COMMIT();
    if (tid<128) s_sc[tid] = g_ws[mode][nbase+tid];
    else         s_bi[tid-128] = biasp[tid-128+nbase];

    float acc[2][8][4];
    #pragma unroll
    for (int mt=0;mt<2;mt++)
      #pragma unroll
      for (int nt=0;nt<8;nt++)
        #pragma unroll
        for (int c=0;c<4;c++) acc[mt][nt][c] = 0.f;

    // ldmatrix lane mapping (validated R5==R6): A x4 at row r0+(lane&15), col ks+((lane>>4)<<3);
    // B x4 covers an n16 x k16 region: row nn, col kc with g2=lane>>3, lr=lane&7.
    int aRow = lane&15, aCol = (lane>>4)<<3;
    int g2 = lane>>3, lr = lane&7;

    for (int kt=0; kt<16; kt++){
        if (kt+1 < 16) issue_tile((kt+1)&1, kt+1);
        CP_COMMIT();
        CP_WAIT1();
        __syncthreads();
        uint32_t stg = sbase + (kt&1)*GST3;
        #pragma unroll
        for (int ks=0; ks<32; ks+=16){
            uint32_t af[2][2][4];
            #pragma unroll
            for (int h=0; h<2; h++)
              #pragma unroll
              for (int mt=0; mt<2; mt++){
                int r0 = wm*32 + mt*16;
                ldsm4(af[h][mt], stg + h*GTILE + (uint32_t)((r0+aRow)*80 + (ks+aCol)*2));
              }
            #pragma unroll
            for (int p=0; p<4; p++){
                int nn = wn*64 + p*16 + ((g2>>1)<<3) + lr;
                int kc = ks + ((g2&1)<<3);
                uint32_t bf4[4];
                ldsm4(bf4, stg + 2*GTILE + (uint32_t)(nn*80 + kc*2));
                #pragma unroll
                for (int mt=0; mt<2; mt++){
                    mma16816(acc[mt][p*2],   af[0][mt], bf4);
                    mma16816(acc[mt][p*2+1], af[0][mt], bf4+2);
                    mma16816(acc[mt][p*2],   af[1][mt], bf4);
                    mma16816(acc[mt][p*2+1], af[1][mt], bf4+2);
                }
            }
        }
        __syncthreads();
    }
    float amax = 0.f;
    float* qkv = (mode==0)?g_q:((mode==1)?g_k:g_v);
    #pragma unroll
    for (int mt=0;mt<2;mt++){
      #pragma unroll
      for (int nt=0;nt<8;nt++){
        int ncol = wn*64 + nt*8 + 2*t;
        float s0 = s_sc[ncol], s1 = s_sc[ncol+1];
        float b0 = s_bi[ncol], b1 = s_bi[ncol+1];
        #pragma unroll
        for (int rh=0; rh<2; rh++){
            int row = rowbase + wm*32 + mt*16 + g + rh*8;
            float v0 = acc[mt][nt][rh*2  ]*s0 + b0;
            float v1 = acc[mt][nt][rh*2+1]*s1 + b1;
            float2 w; w.x = v0; w.y = v1;
            if (mode<3){
                int o = nbase + ncol;
                int head = o>>6, dh = o&63;
                int bb = row>>12, tt = row&4095;
                *(float2*)&qkv[((bb*NH+head)*TS + tt)*DHD + dh] = w;
            } else {
                *(float2*)&outp[row*DM + nbase + ncol] = w;
                amax = fmaxf(amax, fmaxf(fabsf(v0), fabsf(v1)));
            }
        }
      }
    }
    if (mode==3){
        for (int off=16;off;off>>=1) amax = fmaxf(amax, __shfl_xor_sync(0xffffffffu, amax, off));
        if (lane==0) red8[wid] = amax;
        __syncthreads();
        if (tid==0){
            float m = red8[0];
            #pragma unroll
            for (int i=1;i<8;i++) m = fmaxf(m, red8[i]);
            atomicMax(&g_absmax, __float_as_int(m));
        }
    }
}

// ---------------- 4. fused coalesced gather: K -> [bh][j][d], V -> [bh][d][j] ----------------
__global__ void __launch_bounds__(256) gather_kv_kernel()
{
    __shared__ float vs[64][65];
    __shared__ int srcs[64];
    int bh = blockIdx.y;
    int b = bh>>3;
    int jbase = blockIdx.x*64;
    int cnt = g_cnt[b];
    int tid = threadIdx.x;
    if (tid < 64){
        int j = jbase + tid;
        srcs[tid] = (j < cnt) ? g_kept[b*TS + j] : -1;
    }
    __syncthreads();
    #pragma unroll
    for (int i=0;i<16;i++){
        int id = tid + i*256;
        int j = id>>6, d = id&63;
        int src = srcs[j];
        if (src >= 0){
            float kv = g_k[(bh*TS + src)*DHD + d];
            __nv_bfloat16 h = __float2bfloat16(kv);
            int o = (bh*TS + jbase + j)*DHD + d;
            g_kchi[o] = h;
            g_kclo[o] = __float2bfloat16(kv - __bfloat162float(h));
            vs[j][d] = g_v[(bh*TS + src)*DHD + d];
        } else {
            vs[j][d] = 0.f;
        }
    }
    __syncthreads();
    #pragma unroll
    for (int i=0;i<16;i++){
        int id = tid + i*256;
        int d = id>>6, j = id&63;
        float vv = vs[j][d];
        __nv_bfloat16 h = __float2bfloat16(vv);
        int o = (bh*DHD + d)*TS + jbase + j;
        g_vchi[o] = h;
        g_vclo[o] = __float2bfloat16(vv - __bfloat162float(h));
    }
}

// ---------------- 5. flash attention: BQ=128, BK=64, single-sync pipeline + ldmatrix ---------
#define ASK 144                  // row stride bytes (72 bf16; 16B aligned)
#define AQ_REG 18432             // Q hi or lo: 128 rows x 144B
#define AST   36864              // per KV stage: KH|KL|VH|VL, 64x144 each
#define ATT_SMEM (2*AQ_REG + 2*AST)   // 110592
__global__ void __launch_bounds__(256, 2) attn_mma_kernel()
{
    extern __shared__ __align__(16) char smem[];
    const int OQH=0, OQL=AQ_REG;
    int bh = blockIdx.y;
    int b = bh>>3, h = bh&7;
    int qbase = blockIdx.x*128;
    int tid = threadIdx.x, lane = tid&31, wid = tid>>5;
    int g = lane>>2, t = lane&3;
    int cnt = g_cnt[b];
    uint32_t sbase = smem_u32(smem);

    auto issue_kv = [&](int st, int kb){
        uint32_t stg = sbase + 2*AQ_REG + st*AST;
        #pragma unroll
        for (int i=0;i<2;i++){
            int id = tid + i*256;   // 0..511
            int j = id>>3, c = id&7;
            int jj = kb + j;
            int kssz = (jj < cnt) ? 16 : 0;
            int jc = jj < TS ? jj : TS-1;
            cp16z(stg +         j*ASK + c*16, &g_kchi[(bh*TS+jc)*DHD + c*8], kssz);
            cp16z(stg +  9216 + j*ASK + c*16, &g_kclo[(bh*TS+jc)*DHD + c*8], kssz);
            int vb = (cnt - (kb + c*8))*2;
            vb = vb < 0 ? 0 : (vb > 16 ? 16 : vb);
            int cb2 = kb + c*8; if (cb2 > TS-8) cb2 = TS-8;
            cp16z(stg + 18432 + j*ASK + c*16, &g_vchi[(bh*DHD+j)*TS + cb2], vb);
            cp16z(stg + 27648 + j*ASK + c*16, &g_vclo[(bh*DHD+j)*TS + cb2], vb);
        }
    };

    issue_kv(0, 0);
    CP_COMMIT();

    // Q: load fp32, scale, hi/lo split into smem (128 rows)
    #pragma unroll
    for (int i=0;i<8;i++){
        int id = tid + i*256;       // 0..2047
        int q = id>>4, c = id&15;
        float4 v = *(const float4*)&g_q[(bh*TS + qbase + q)*DHD + c*4];
        v.x *= 0.125f; v.y *= 0.125f; v.z *= 0.125f; v.w *= 0.125f;
        __nv_bfloat16 h0=__float2bfloat16(v.x), h1=__float2bfloat16(v.y);
        __nv_bfloat16 h2=__float2bfloat16(v.z), h3=__float2bfloat16(v.w);
        int o = q*ASK + c*8;
        *(uint32_t*)(smem + OQH + o)     = pkbf(__bfloat162float(h0), __bfloat162float(h1));
        *(uint32_t*)(smem + OQH + o + 4) = pkbf(__bfloat162float(h2), __bfloat162float(h3));
        *(uint32_t*)(smem + OQL + o)     = pkbf(v.x-__bfloat162float(h0), v.y-__bfloat162float(h1));
        *(uint32_t*)(smem + OQL + o + 4) = pkbf(v.z-__bfloat162float(h2), v.w-__bfloat162float(h3));
    }
    __syncthreads();

    // hoist Q fragments via ldmatrix
    uint32_t qh[4][4], ql[4][4];
    int m0 = wid*16;
    int aRow = lane&15, aCol = (lane>>4)<<3;
    int g2 = lane>>3, lr = lane&7;
    #pragma unroll
    for (int kt=0;kt<4;kt++){
        uint32_t off = (uint32_t)((m0+aRow)*ASK + (kt*16+aCol)*2);
        ldsm4(qh[kt], sbase + OQH + off);
        ldsm4(ql[kt], sbase + OQL + off);
    }

    float oacc[8][4];
    #pragma unroll
    for (int np=0;np<8;np++){ oacc[np][0]=0.f; oacc[np][1]=0.f; oacc[np][2]=0.f; oacc[np][3]=0.f; }
    float sprev[2] = {-1e30f, -1e30f};
    float lrun[2]  = {0.f, 0.f};
    int NT = (cnt + 63) >> 6;

    for (int it=0; it<NT; it++){
        int kb = it*64;
        CP_WAIT0();
        __syncthreads();          // tile it visible; prior reads of slot (it+1)&1 done
        if (it+1 < NT) issue_kv((it+1)&1, kb+64);
        CP_COMMIT();
        uint32_t stg = sbase + 2*AQ_REG + (it&1)*AST;
        uint32_t uKH = stg, uKL = stg + 9216, uVH = stg + 18432, uVL = stg + 27648;

        // S = Q K^T (3 hi/lo combos); K B-frags via one ldmatrix.x4 per (kt, np-pair)
        float sacc[8][4];
        #pragma unroll
        for (int np=0;np<8;np++){ sacc[np][0]=0.f; sacc[np][1]=0.f; sacc[np][2]=0.f; sacc[np][3]=0.f; }
        #pragma unroll
        for (int kt=0;kt<4;kt++){
            #pragma unroll
            for (int p=0;p<4;p++){
                int nn = p*16 + ((g2>>1)<<3) + lr;
                int kc = kt*16 + ((g2&1)<<3);
                uint32_t off = (uint32_t)(nn*ASK + kc*2);
                uint32_t bh4[4], bl4[4];
                ldsm4(bh4, uKH + off);
                ldsm4(bl4, uKL + off);
                mma16816(sacc[p*2],   qh[kt], bh4);
                mma16816(sacc[p*2+1], qh[kt], bh4+2);
                mma16816(sacc[p*2],   qh[kt], bl4);
                mma16816(sacc[p*2+1], qh[kt], bl4+2);
                mma16816(sacc[p*2],   ql[kt], bh4);
                mma16816(sacc[p*2+1], ql[kt], bh4+2);
            }
        }
        if (kb + 64 > cnt){
            #pragma unroll
            for (int np=0;np<8;np++)
              #pragma unroll
              for (int c=0;c<4;c++){
                  int j = kb + np*8 + 2*t + (c&1);
                  if (j >= cnt) sacc[np][c] = -1e30f;
              }
        }
        // online softmax
        float mt0 = sprev[0], mt1 = sprev[1];
        #pragma unroll
        for (int np=0;np<8;np++){
            mt0 = fmaxf(mt0, fmaxf(sacc[np][0], sacc[np][1]));
            mt1 = fmaxf(mt1, fmaxf(sacc[np][2], sacc[np][3]));
        }
        mt0 = fmaxf(mt0, __shfl_xor_sync(0xffffffffu, mt0, 1));
        mt0 = fmaxf(mt0, __shfl_xor_sync(0xffffffffu, mt0, 2));
        mt1 = fmaxf(mt1, __shfl_xor_sync(0xffffffffu, mt1, 1));
        mt1 = fmaxf(mt1, __shfl_xor_sync(0xffffffffu, mt1, 2));
        float c0 = __expf(sprev[0]-mt0), c1 = __expf(sprev[1]-mt1);
        float rs0 = 0.f, rs1 = 0.f;
        #pragma unroll
        for (int np=0;np<8;np++){
            sacc[np][0] = __expf(sacc[np][0]-mt0); rs0 += sacc[np][0];
            sacc[np][1] = __expf(sacc[np][1]-mt0); rs0 += sacc[np][1];
            sacc[np][2] = __expf(sacc[np][2]-mt1); rs1 += sacc[np][2];
            sacc[np][3] = __expf(sacc[np][3]-mt1); rs1 += sacc[np][3];
        }
        rs0 += __shfl_xor_sync(0xffffffffu, rs0, 1);
        rs0 += __shfl_xor_sync(0xffffffffu, rs0, 2);
        rs1 += __shfl_xor_sync(0xffffffffu, rs1, 1);
        rs1 += __shfl_xor_sync(0xffffffffu, rs1, 2);
        lrun[0] = lrun[0]*c0 + rs0;
        lrun[1] = lrun[1]*c1 + rs1;
        sprev[0] = mt0; sprev[1] = mt1;
        #pragma unroll
        for (int np=0;np<8;np++){
            oacc[np][0]*=c0; oacc[np][1]*=c0; oacc[np][2]*=c1; oacc[np][3]*=c1;
        }
        // O += P V (3 combos); P A-frags in-register; V B-frags via ldmatrix.x4
        #pragma unroll
        for (int kt=0;kt<4;kt++){
            uint32_t ah[4], al[4];
            {
                float p0 = sacc[2*kt][0],   p1 = sacc[2*kt][1];
                float p2 = sacc[2*kt][2],   p3 = sacc[2*kt][3];
                float p4 = sacc[2*kt+1][0], p5 = sacc[2*kt+1][1];
                float p6 = sacc[2*kt+1][2], p7 = sacc[2*kt+1][3];
                ah[0] = pkbf(p0,p1); ah[1] = pkbf(p2,p3);
                ah[2] = pkbf(p4,p5); ah[3] = pkbf(p6,p7);
                al[0] = pkbf(p0-__bfloat162float(__float2bfloat16(p0)), p1-__bfloat162float(__float2bfloat16(p1)));
                al[1] = pkbf(p2-__bfloat162float(__float2bfloat16(p2)), p3-__bfloat162float(__float2bfloat16(p3)));
                al[2] = pkbf(p4-__bfloat162float(__float2bfloat16(p4)), p5-__bfloat162float(__float2bfloat16(p5)));
                al[3] = pkbf(p6-__bfloat162float(__float2bfloat16(p6)), p7-__bfloat162float(__float2bfloat16(p7)));
            }
            #pragma unroll
            for (int p=0;p<4;p++){
                int nn = p*16 + ((g2>>1)<<3) + lr;
                int kc = kt*16 + ((g2&1)<<3);
                uint32_t off = (uint32_t)(nn*ASK + kc*2);
                uint32_t vh4[4], vl4[4];
                ldsm4(vh4, uVH + off);
                ldsm4(vl4, uVL + off);
                mma16816(oacc[p*2],   ah, vh4);
                mma16816(oacc[p*2+1], ah, vh4+2);
                mma16816(oacc[p*2],   ah, vl4);
                mma16816(oacc[p*2+1], ah, vl4+2);
                mma16816(oacc[p*2],   al, vh4);
                mma16816(oacc[p*2+1], al, vh4+2);
            }
        }
    }
    // epilogue: normalize, hi/lo split, write ctx as bf16
    float inv0 = __fdiv_rn(1.0f, lrun[0]);
    float inv1 = __fdiv_rn(1.0f, lrun[1]);
    int t0 = qbase + m0 + g;
    int t1 = t0 + 8;
    #pragma unroll
    for (int np=0;np<8;np++){
        int col = h*DHD + np*8 + 2*t;
        float v0 = oacc[np][0]*inv0, v1 = oacc[np][1]*inv0;
        float v2 = oacc[np][2]*inv1, v3 = oacc[np][3]*inv1;
        __nv_bfloat16 h0=__float2bfloat16(v0), h1=__float2bfloat16(v1);
        __nv_bfloat16 h2=__float2bfloat16(v2), h3=__float2bfloat16(v3);
        *(uint32_t*)&g_chi[(b*TS + t0)*DM + col] = pkbf(__bfloat162float(h0), __bfloat162float(h1));
        *(uint32_t*)&g_clo[(b*TS + t0)*DM + col] = pkbf(v0-__bfloat162float(h0), v1-__bfloat162float(h1));
        *(uint32_t*)&g_chi[(b*TS + t1)*DM + col] = pkbf(__bfloat162float(h2), __bfloat162float(h3));
        *(uint32_t*)&g_clo[(b*TS + t1)*DM + col] = pkbf(v2-__bfloat162float(h2), v3-__bfloat162float(h3));
    }
}

// ---------------- 7. final per-tensor int8 quant-dequant ----------------
__global__ void quant_out_kernel(float* __restrict__ outp)
{
    float s = fmaxf(__fdiv_rn(__int_as_float(g_absmax), 127.0f), 1e-8f);
    int i = blockIdx.x*256 + threadIdx.x;
    float v = outp[i];
    float qv = rintf(__fdiv_rn(v, s));
    qv = fminf(fmaxf(qv, -127.f), 127.f);
    outp[i] = qv * s;
}

// ---------------- launch ----------------
extern "C" void kernel_launch(void* const* d_in, const int* in_sizes, int n_in,
                              void* d_out, int out_size)
{
    (void)in_sizes; (void)n_in; (void)out_size;
    const float* x  = (const float*)d_in[0];
    const int*   mk = (const int*)  d_in[1];
    const float* Wq = (const float*)d_in[2];
    const float* bq = (const float*)d_in[3];
    const float* Wk = (const float*)d_in[4];
    const float* bk = (const float*)d_in[5];
    const float* Wv = (const float*)d_in[6];
    const float* bv = (const float*)d_in[7];
    const float* Wo = (const float*)d_in[8];
    const float* bo = (const float*)d_in[9];
    float* outp = (float*)d_out;

    cudaFuncSetAttribute(gemm_mma_kernel, cudaFuncAttributeMaxDynamicSharedMemorySize, GEMM_SMEM);
    cudaFuncSetAttribute(attn_mma_kernel, cudaFuncAttributeMaxDynamicSharedMemorySize, ATT_SMEM);

    quant_weights_kernel<<<dim3(DM,4), 128>>>(Wq,Wk,Wv,Wo);
    split_x_kernel<<<(BT_*DM)/1024, 256>>>(x);
    compact_kernel<<<NB, 1024>>>(mk);
    gemm_mma_kernel<<<dim3(BT_/128, DM/128, 3), 256, GEMM_SMEM>>>(bq,bk,bv,bo, outp, 0);
    gather_kv_kernel<<<dim3(TS/64, BH_), 256>>>();
    attn_mma_kernel<<<dim3(TS/128, BH_), 256, ATT_SMEM>>>();
    gemm_mma_kernel<<<dim3(BT_/128, DM/128, 1), 256, GEMM_SMEM>>>(bq,bk,bv,bo, outp, 3);
    quant_out_kernel<<<(BT_*DM)/256, 256>>>(outp);
}

// round 14
// speedup vs baseline: 1.1097x; 1.0012x over previous
#include <cuda_runtime.h>
#include <cuda_bf16.h>
#include <math.h>
#include <stdint.h>

typedef unsigned long long ull;

#define DM 512
#define TS 4096
#define NB 2
#define NH 8
#define DHD 64
#define BT_ (NB*TS)    // 8192
#define BH_ (NB*NH)    // 16

// ---------------- device scratch (static, allocation-free) ----------------
// RULE (root cause of R4-R7 failures): these symbols are referenced ONLY
// inside device code. Never pass a __device__ symbol as a kernel argument.
__device__ __nv_bfloat16 g_Wb[4][DM*DM];
__device__ float g_ws[4][DM];
__device__ __nv_bfloat16 g_xhi[BT_*DM];
__device__ __nv_bfloat16 g_xlo[BT_*DM];
__device__ __nv_bfloat16 g_chi[BT_*DM];
__device__ __nv_bfloat16 g_clo[BT_*DM];
__device__ __nv_bfloat16 g_qhi[BH_*TS*DHD];   // Q pre-scaled (x0.125) bf16 hi/lo, [bh][t][dh]
__device__ __nv_bfloat16 g_qlo[BH_*TS*DHD];
__device__ float g_v [BH_*TS*DHD];            // V fp32 (for transposed gather)
__device__ __nv_bfloat16 g_kchi[BH_*TS*DHD];  // compacted K, [bh][rank][d] (written by gemm)
__device__ __nv_bfloat16 g_kclo[BH_*TS*DHD];
__device__ __nv_bfloat16 g_vchi[BH_*DHD*TS];  // compacted V transposed, [bh][d][rank]
__device__ __nv_bfloat16 g_vclo[BH_*DHD*TS];
__device__ int   g_kept[NB*TS];
__device__ int   g_rank[NB*TS];               // t -> rank (or -1)
__device__ int   g_cnt[NB];
__device__ int   g_absmax;

// ---------------- mma / ldmatrix / cp.async helpers ----------------
static __device__ __forceinline__ void mma16816(float* d, const uint32_t* a, const uint32_t* b){
    asm volatile("mma.sync.aligned.m16n8k16.row.col.f32.bf16.bf16.f32 "
        "{%0,%1,%2,%3}, {%4,%5,%6,%7}, {%8,%9}, {%0,%1,%2,%3};"
        : "+f"(d[0]),"+f"(d[1]),"+f"(d[2]),"+f"(d[3])
        : "r"(a[0]),"r"(a[1]),"r"(a[2]),"r"(a[3]), "r"(b[0]),"r"(b[1]));
}
static __device__ __forceinline__ void ldsm4(uint32_t* r, uint32_t a){
    asm volatile("ldmatrix.sync.aligned.m8n8.x4.shared.b16 {%0,%1,%2,%3}, [%4];"
        : "=r"(r[0]),"=r"(r[1]),"=r"(r[2]),"=r"(r[3]) : "r"(a));
}
static __device__ __forceinline__ uint32_t pkbf(float x, float y){
    uint32_t r; asm("cvt.rn.bf16x2.f32 %0, %1, %2;" : "=r"(r) : "f"(y), "f"(x)); return r;
}
static __device__ __forceinline__ uint32_t smem_u32(const void* p){
    uint32_t a;
    asm("{ .reg .u64 t; cvta.to.shared.u64 t, %1; cvt.u32.u64 %0, t; }" : "=r"(a) : "l"(p));
    return a;
}
static __device__ __forceinline__ void cp16(uint32_t dst, const void* src){
    asm volatile("cp.async.ca.shared.global [%0], [%1], 16;" :: "r"(dst), "l"(src) : "memory");
}
static __device__ __forceinline__ void cp16z(uint32_t dst, const void* src, int ssz){
    asm volatile("cp.async.ca.shared.global [%0], [%1], 16, %2;" :: "r"(dst), "l"(src), "r"(ssz) : "memory");
}
#define CP_COMMIT() asm volatile("cp.async.commit_group;" ::: "memory")
#define CP_WAIT1()  asm volatile("cp.async.wait_group 1;" ::: "memory")
#define CP_WAIT0()  asm volatile("cp.async.wait_group 0;" ::: "memory")

// ---------------- 1. per-row symmetric int8 weight quant ----------------
__global__ void quant_weights_kernel(const float* __restrict__ Wq, const float* __restrict__ Wk,
                                     const float* __restrict__ Wv, const float* __restrict__ Wo)
{
    int w = blockIdx.y;
    int row = blockIdx.x;
    const float* srcs[4] = {Wq, Wk, Wv, Wo};
    const float* wr = srcs[w] + row*DM;
    __nv_bfloat16* dst = &g_Wb[w][row*DM];
    int tid = threadIdx.x; // 128
    if (w==0 && row==0 && tid==0) g_absmax = 0;
    float mx = 0.f;
    for (int i=tid;i<DM;i+=128) mx = fmaxf(mx, fabsf(wr[i]));
    for (int off=16;off;off>>=1) mx = fmaxf(mx, __shfl_xor_sync(0xffffffffu, mx, off));
    __shared__ float sm4[4];
    if ((tid&31)==0) sm4[tid>>5] = mx;
    __syncthreads();
    mx = fmaxf(fmaxf(sm4[0],sm4[1]), fmaxf(sm4[2],sm4[3]));
    float s = fmaxf(__fdiv_rn(mx, 127.0f), 1e-8f);
    if (tid==0) g_ws[w][row] = s;
    for (int i=tid;i<DM;i+=128){
        float qv = rintf(__fdiv_rn(wr[i], s));
        qv = fminf(fmaxf(qv, -127.f), 127.f);
        dst[i] = __float2bfloat16(qv);
    }
}

// ---------------- 1b. bf16 hi/lo split of x ----------------
__global__ void split_x_kernel(const float* __restrict__ src)
{
    int i = (blockIdx.x*256 + threadIdx.x)*4;
    float4 v = *(const float4*)&src[i];
    __nv_bfloat16 h0=__float2bfloat16(v.x), h1=__float2bfloat16(v.y);
    __nv_bfloat16 h2=__float2bfloat16(v.z), h3=__float2bfloat16(v.w);
    __nv_bfloat162 hA; hA.x=h0; hA.y=h1;
    __nv_bfloat162 hB; hB.x=h2; hB.y=h3;
    __nv_bfloat162 lA; lA.x=__float2bfloat16(v.x-__bfloat162float(h0)); lA.y=__float2bfloat16(v.y-__bfloat162float(h1));
    __nv_bfloat162 lB; lB.x=__float2bfloat16(v.z-__bfloat162float(h2)); lB.y=__float2bfloat16(v.w-__bfloat162float(h3));
    *(__nv_bfloat162*)&g_xhi[i]   = hA;
    *(__nv_bfloat162*)&g_xhi[i+2] = hB;
    *(__nv_bfloat162*)&g_xlo[i]   = lA;
    *(__nv_bfloat162*)&g_xlo[i+2] = lB;
}

// ---------------- 2. mask compaction (+ inverse rank map) ----------------
__global__ void compact_kernel(const int* __restrict__ mask)
{
    int b = blockIdx.x;
    const int* m = mask + b*TS;
    __shared__ int part[1024];
    int tid = threadIdx.x; // 1024
    int base = tid*4;
    int f0 = m[base]!=0, f1 = m[base+1]!=0, f2 = m[base+2]!=0, f3 = m[base+3]!=0;
    int s = f0+f1+f2+f3;
    part[tid] = s;
    __syncthreads();
    for (int off=1; off<1024; off<<=1){
        int v = (tid>=off) ? part[tid-off] : 0;
        __syncthreads();
        part[tid] += v;
        __syncthreads();
    }
    int rr = part[tid] - s;
    int o = rr + b*TS;
    g_rank[b*TS+base  ] = f0 ? rr : -1; rr += f0;
    g_rank[b*TS+base+1] = f1 ? rr : -1; rr += f1;
    g_rank[b*TS+base+2] = f2 ? rr : -1; rr += f2;
    g_rank[b*TS+base+3] = f3 ? rr : -1;
    if (f0) g_kept[o++] = base;
    if (f1) g_kept[o++] = base+1;
    if (f2) g_kept[o++] = base+2;
    if (f3) g_kept[o++] = base+3;
    if (tid==1023) g_cnt[b] = part[1023];
}

// ---------------- 3. mma GEMM, cp.async 2-stage + ldmatrix; fused Q/K epilogues ----------------
#define GTILE 10240
#define GST3  (3*GTILE)          // 30720 per stage
#define GEMM_SMEM (2*GST3)       // 61440
__global__ void __launch_bounds__(256) gemm_mma_kernel(
    const float* __restrict__ bq, const float* __restrict__ bk,
    const float* __restrict__ bv, const float* __restrict__ bo,
    float* __restrict__ outp, int modebase)
{
    extern __shared__ __align__(16) char dsm[];
    __shared__ float s_sc[128], s_bi[128];
    __shared__ float red8[8];
    int mode = modebase + blockIdx.z;
    int tid = threadIdx.x, lane = tid&31, wid = tid>>5;
    int wm = wid>>1, wn = wid&1;
    int g = lane>>2, t = lane&3;
    int rowbase = blockIdx.x*128, nbase = blockIdx.y*128;
    uint32_t sbase = smem_u32(dsm);

    const __nv_bfloat16* __restrict__ Ahi = (mode<3) ? g_xhi : g_chi;
    const __nv_bfloat16* __restrict__ Alo = (mode<3) ? g_xlo : g_clo;
    const __nv_bfloat16* __restrict__ Bw  = g_Wb[mode];
    const float* biasp = (mode==0)?bq:((mode==1)?bk:((mode==2)?bv:bo));

    auto issue_tile = [&](int st, int kt){
        uint32_t stg = sbase + st*GST3;
        int kb = kt*32;
        #pragma unroll
        for (int i=0;i<2;i++){
            int id = tid + i*256;   // 0..511
            int r = id>>2, c = id&3;
            cp16(stg +           r*80 + c*16, &Ahi[(rowbase+r)*DM + kb + c*8]);
            cp16(stg + GTILE   + r*80 + c*16, &Alo[(rowbase+r)*DM + kb + c*8]);
            cp16(stg + 2*GTILE + r*80 + c*16, &Bw [(nbase  +r)*DM + kb + c*8]);
        }
    };

    issue_tile(0, 0);
    CP_COMMIT();
    if (tid<128) s_sc[tid] = g_ws[mode][nbase+tid];
    else         s_bi[tid-128] = biasp[tid-128+nbase];

    float acc[2][8][4];
    #pragma unroll
    for (int mt=0;mt<2;mt++)
      #pragma unroll
      for (int nt=0;nt<8;nt++)
        #pragma unroll
        for (int c=0;c<4;c++) acc[mt][nt][c] = 0.f;

    int aRow = lane&15, aCol = (lane>>4)<<3;
    int g2 = lane>>3, lr = lane&7;

    for (int kt=0; kt<16; kt++){
        if (kt+1 < 16) issue_tile((kt+1)&1, kt+1);
        CP_COMMIT();
        CP_WAIT1();
        __syncthreads();
        uint32_t stg = sbase + (kt&1)*GST3;
        #pragma unroll
        for (int ks=0; ks<32; ks+=16){
            uint32_t af[2][2][4];
            #pragma unroll
            for (int h=0; h<2; h++)
              #pragma unroll
              for (int mt=0; mt<2; mt++){
                int r0 = wm*32 + mt*16;
                ldsm4(af[h][mt], stg + h*GTILE + (uint32_t)((r0+aRow)*80 + (ks+aCol)*2));
              }
            #pragma unroll
            for (int p=0; p<4; p++){
                int nn = wn*64 + p*16 + ((g2>>1)<<3) + lr;
                int kc = ks + ((g2&1)<<3);
                uint32_t bf4[4];
                ldsm4(bf4, stg + 2*GTILE + (uint32_t)(nn*80 + kc*2));
                #pragma unroll
                for (int mt=0; mt<2; mt++){
                    mma16816(acc[mt][p*2],   af[0][mt], bf4);
                    mma16816(acc[mt][p*2+1], af[0][mt], bf4+2);
                    mma16816(acc[mt][p*2],   af[1][mt], bf4);
                    mma16816(acc[mt][p*2+1], af[1][mt], bf4+2);
                }
            }
        }
        __syncthreads();
    }
    float amax = 0.f;
    #pragma unroll
    for (int mt=0;mt<2;mt++){
      #pragma unroll
      for (int nt=0;nt<8;nt++){
        int ncol = wn*64 + nt*8 + 2*t;
        float s0 = s_sc[ncol], s1 = s_sc[ncol+1];
        float b0 = s_bi[ncol], b1 = s_bi[ncol+1];
        #pragma unroll
        for (int rh=0; rh<2; rh++){
            int row = rowbase + wm*32 + mt*16 + g + rh*8;
            float v0 = acc[mt][nt][rh*2  ]*s0 + b0;
            float v1 = acc[mt][nt][rh*2+1]*s1 + b1;
            if (mode==3){
                float2 w; w.x = v0; w.y = v1;
                *(float2*)&outp[row*DM + nbase + ncol] = w;
                amax = fmaxf(amax, fmaxf(fabsf(v0), fabsf(v1)));
            } else {
                int o = nbase + ncol;
                int head = o>>6, dh = o&63;
                int bb = row>>12, tt = row&4095;
                if (mode==0){
                    // Q: pre-scale by 1/sqrt(dh)=0.125 (exact), split hi/lo
                    float q0 = v0*0.125f, q1 = v1*0.125f;
                    float h0 = __bfloat162float(__float2bfloat16(q0));
                    float h1 = __bfloat162float(__float2bfloat16(q1));
                    int idx = ((bb*NH+head)*TS + tt)*DHD + dh;
                    *(uint32_t*)&g_qhi[idx] = pkbf(h0, h1);
                    *(uint32_t*)&g_qlo[idx] = pkbf(q0-h0, q1-h1);
                } else if (mode==1){
                    // K: write compacted bf16 hi/lo at rank position
                    int rk = g_rank[bb*TS + tt];
                    if (rk >= 0){
                        float h0 = __bfloat162float(__float2bfloat16(v0));
                        float h1 = __bfloat162float(__float2bfloat16(v1));
                        int idx = ((bb*NH+head)*TS + rk)*DHD + dh;
                        *(uint32_t*)&g_kchi[idx] = pkbf(h0, h1);
                        *(uint32_t*)&g_kclo[idx] = pkbf(v0-h0, v1-h1);
                    }
                } else {
                    float2 w; w.x = v0; w.y = v1;
                    *(float2*)&g_v[((bb*NH+head)*TS + tt)*DHD + dh] = w;
                }
            }
        }
      }
    }
    if (mode==3){
        for (int off=16;off;off>>=1) amax = fmaxf(amax, __shfl_xor_sync(0xffffffffu, amax, off));
        if (lane==0) red8[wid] = amax;
        __syncthreads();
        if (tid==0){
            float m = red8[0];
            #pragma unroll
            for (int i=1;i<8;i++) m = fmaxf(m, red8[i]);
            atomicMax(&g_absmax, __float_as_int(m));
        }
    }
}

// ---------------- 4. V-only coalesced gather+transpose: g_v kept rows -> [bh][d][rank] -------
__global__ void __launch_bounds__(256) gather_v_kernel()
{
    __shared__ float vs[64][65];
    __shared__ int srcs[64];
    int bh = blockIdx.y;
    int b = bh>>3;
    int jbase = blockIdx.x*64;
    int cnt = g_cnt[b];
    int tid = threadIdx.x;
    if (tid < 64){
        int j = jbase + tid;
        srcs[tid] = (j < cnt) ? g_kept[b*TS + j] : -1;
    }
    __syncthreads();
    #pragma unroll
    for (int i=0;i<16;i++){
        int id = tid + i*256;
        int j = id>>6, d = id&63;
        int src = srcs[j];
        vs[j][d] = (src >= 0) ? g_v[(bh*TS + src)*DHD + d] : 0.f;
    }
    __syncthreads();
    #pragma unroll
    for (int i=0;i<16;i++){
        int id = tid + i*256;
        int d = id>>6, j = id&63;
        float vv = vs[j][d];
        __nv_bfloat16 h = __float2bfloat16(vv);
        int o = (bh*DHD + d)*TS + jbase + j;
        g_vchi[o] = h;
        g_vclo[o] = __float2bfloat16(vv - __bfloat162float(h));
    }
}

// ---------------- 5. flash attention: BQ=128, BK=64, cp.async Q + single-sync KV pipeline ----
#define ASK 144                  // row stride bytes (72 bf16; 16B aligned)
#define AQ_REG 18432             // Q hi or lo: 128 rows x 144B
#define AST   36864              // per KV stage: KH|KL|VH|VL, 64x144 each
#define ATT_SMEM (2*AQ_REG + 2*AST)   // 110592
__global__ void __launch_bounds__(256, 2) attn_mma_kernel()
{
    extern __shared__ __align__(16) char smem[];
    const int OQH=0, OQL=AQ_REG;
    int bh = blockIdx.y;
    int b = bh>>3, h = bh&7;
    int qbase = blockIdx.x*128;
    int tid = threadIdx.x, lane = tid&31, wid = tid>>5;
    int g = lane>>2, t = lane&3;
    int cnt = g_cnt[b];
    uint32_t sbase = smem_u32(smem);

    auto issue_kv = [&](int st, int kb){
        uint32_t stg = sbase + 2*AQ_REG + st*AST;
        #pragma unroll
        for (int i=0;i<2;i++){
            int id = tid + i*256;   // 0..511
            int j = id>>3, c = id&7;
            int jj = kb + j;
            int kssz = (jj < cnt) ? 16 : 0;
            int jc = jj < TS ? jj : TS-1;
            cp16z(stg +         j*ASK + c*16, &g_kchi[(bh*TS+jc)*DHD + c*8], kssz);
            cp16z(stg +  9216 + j*ASK + c*16, &g_kclo[(bh*TS+jc)*DHD + c*8], kssz);
            int vb = (cnt - (kb + c*8))*2;
            vb = vb < 0 ? 0 : (vb > 16 ? 16 : vb);
            int cb2 = kb + c*8; if (cb2 > TS-8) cb2 = TS-8;
            cp16z(stg + 18432 + j*ASK + c*16, &g_vchi[(bh*DHD+j)*TS + cb2], vb);
            cp16z(stg + 27648 + j*ASK + c*16, &g_vclo[(bh*DHD+j)*TS + cb2], vb);
        }
    };

    // Q hi/lo straight from gmem (pre-scaled, pre-split by the QKV gemm epilogue)
    #pragma unroll
    for (int i=0;i<4;i++){
        int id = tid + i*256;    // 0..1023
        int q = id>>3, c = id&7;
        int gi = (bh*TS + qbase + q)*DHD + c*8;
        cp16(sbase + OQH + (uint32_t)(q*ASK + c*16), &g_qhi[gi]);
        cp16(sbase + OQL + (uint32_t)(q*ASK + c*16), &g_qlo[gi]);
    }
    CP_COMMIT();
    issue_kv(0, 0);
    CP_COMMIT();
    CP_WAIT1();                 // Q group complete
    __syncthreads();

    // hoist Q fragments via ldmatrix
    uint32_t qh[4][4], ql[4][4];
    int m0 = wid*16;
    int aRow = lane&15, aCol = (lane>>4)<<3;
    int g2 = lane>>3, lr = lane&7;
    #pragma unroll
    for (int kt=0;kt<4;kt++){
        uint32_t off = (uint32_t)((m0+aRow)*ASK + (kt*16+aCol)*2);
        ldsm4(qh[kt], sbase + OQH + off);
        ldsm4(ql[kt], sbase + OQL + off);
    }

    float oacc[8][4];
    #pragma unroll
    for (int np=0;np<8;np++){ oacc[np][0]=0.f; oacc[np][1]=0.f; oacc[np][2]=0.f; oacc[np][3]=0.f; }
    float sprev[2] = {-1e30f, -1e30f};
    float lrun[2]  = {0.f, 0.f};
    int NT = (cnt + 63) >> 6;

    for (int it=0; it<NT; it++){
        int kb = it*64;
        CP_WAIT0();
        __syncthreads();          // tile it visible; prior reads of slot (it+1)&1 done
        if (it+1 < NT) issue_kv((it+1)&1, kb+64);
        CP_COMMIT();
        uint32_t stg = sbase + 2*AQ_REG + (it&1)*AST;
        uint32_t uKH = stg, uKL = stg + 9216, uVH = stg + 18432, uVL = stg + 27648;

        // S = Q K^T (3 hi/lo combos)
        float sacc[8][4];
        #pragma unroll
        for (int np=0;np<8;np++){ sacc[np][0]=0.f; sacc[np][1]=0.f; sacc[np][2]=0.f; sacc[np][3]=0.f; }
        #pragma unroll
        for (int kt=0;kt<4;kt++){
            #pragma unroll
            for (int p=0;p<4;p++){
                int nn = p*16 + ((g2>>1)<<3) + lr;
                int kc = kt*16 + ((g2&1)<<3);
                uint32_t off = (uint32_t)(nn*ASK + kc*2);
                uint32_t bh4[4], bl4[4];
                ldsm4(bh4, uKH + off);
                ldsm4(bl4, uKL + off);
                mma16816(sacc[p*2],   qh[kt], bh4);
                mma16816(sacc[p*2+1], qh[kt], bh4+2);
                mma16816(sacc[p*2],   qh[kt], bl4);
                mma16816(sacc[p*2+1], qh[kt], bl4+2);
                mma16816(sacc[p*2],   ql[kt], bh4);
                mma16816(sacc[p*2+1], ql[kt], bh4+2);
            }
        }
        if (kb + 64 > cnt){
            #pragma unroll
            for (int np=0;np<8;np++)
              #pragma unroll
              for (int c=0;c<4;c++){
                  int j = kb + np*8 + 2*t + (c&1);
                  if (j >= cnt) sacc[np][c] = -1e30f;
              }
        }
        // online softmax
        float mt0 = sprev[0], mt1 = sprev[1];
        #pragma unroll
        for (int np=0;np<8;np++){
            mt0 = fmaxf(mt0, fmaxf(sacc[np][0], sacc[np][1]));
            mt1 = fmaxf(mt1, fmaxf(sacc[np][2], sacc[np][3]));
        }
        mt0 = fmaxf(mt0, __shfl_xor_sync(0xffffffffu, mt0, 1));
        mt0 = fmaxf(mt0, __shfl_xor_sync(0xffffffffu, mt0, 2));
        mt1 = fmaxf(mt1, __shfl_xor_sync(0xffffffffu, mt1, 1));
        mt1 = fmaxf(mt1, __shfl_xor_sync(0xffffffffu, mt1, 2));
        float c0 = __expf(sprev[0]-mt0), c1 = __expf(sprev[1]-mt1);
        float rs0 = 0.f, rs1 = 0.f;
        #pragma unroll
        for (int np=0;np<8;np++){
            sacc[np][0] = __expf(sacc[np][0]-mt0); rs0 += sacc[np][0];
            sacc[np][1] = __expf(sacc[np][1]-mt0); rs0 += sacc[np][1];
            sacc[np][2] = __expf(sacc[np][2]-mt1); rs1 += sacc[np][2];
            sacc[np][3] = __expf(sacc[np][3]-mt1); rs1 += sacc[np][3];
        }
        rs0 += __shfl_xor_sync(0xffffffffu, rs0, 1);
        rs0 += __shfl_xor_sync(0xffffffffu, rs0, 2);
        rs1 += __shfl_xor_sync(0xffffffffu, rs1, 1);
        rs1 += __shfl_xor_sync(0xffffffffu, rs1, 2);
        lrun[0] = lrun[0]*c0 + rs0;
        lrun[1] = lrun[1]*c1 + rs1;
        sprev[0] = mt0; sprev[1] = mt1;
        #pragma unroll
        for (int np=0;np<8;np++){
            oacc[np][0]*=c0; oacc[np][1]*=c0; oacc[np][2]*=c1; oacc[np][3]*=c1;
        }
        // O += P V (3 combos); P A-frags in-register (C-layout == A-layout)
        #pragma unroll
        for (int kt=0;kt<4;kt++){
            uint32_t ah[4], al[4];
            {
                float p0 = sacc[2*kt][0],   p1 = sacc[2*kt][1];
                float p2 = sacc[2*kt][2],   p3 = sacc[2*kt][3];
                float p4 = sacc[2*kt+1][0], p5 = sacc[2*kt+1][1];
                float p6 = sacc[2*kt+1][2], p7 = sacc[2*kt+1][3];
                ah[0] = pkbf(p0,p1); ah[1] = pkbf(p2,p3);
                ah[2] = pkbf(p4,p5); ah[3] = pkbf(p6,p7);
                al[0] = pkbf(p0-__bfloat162float(__float2bfloat16(p0)), p1-__bfloat162float(__float2bfloat16(p1)));
                al[1] = pkbf(p2-__bfloat162float(__float2bfloat16(p2)), p3-__bfloat162float(__float2bfloat16(p3)));
                al[2] = pkbf(p4-__bfloat162float(__float2bfloat16(p4)), p5-__bfloat162float(__float2bfloat16(p5)));
                al[3] = pkbf(p6-__bfloat162float(__float2bfloat16(p6)), p7-__bfloat162float(__float2bfloat16(p7)));
            }
            #pragma unroll
            for (int p=0;p<4;p++){
                int nn = p*16 + ((g2>>1)<<3) + lr;
                int kc = kt*16 + ((g2&1)<<3);
                uint32_t off = (uint32_t)(nn*ASK + kc*2);
                uint32_t vh4[4], vl4[4];
                ldsm4(vh4, uVH + off);
                ldsm4(vl4, uVL + off);
                mma16816(oacc[p*2],   ah, vh4);
                mma16816(oacc[p*2+1], ah, vh4+2);
                mma16816(oacc[p*2],   ah, vl4);
                mma16816(oacc[p*2+1], ah, vl4+2);
                mma16816(oacc[p*2],   al, vh4);
                mma16816(oacc[p*2+1], al, vh4+2);
            }
        }
    }
    // epilogue: normalize, hi/lo split, write ctx as bf16
    float inv0 = __fdiv_rn(1.0f, lrun[0]);
    float inv1 = __fdiv_rn(1.0f, lrun[1]);
    int t0 = qbase + m0 + g;
    int t1 = t0 + 8;
    #pragma unroll
    for (int np=0;np<8;np++){
        int col = h*DHD + np*8 + 2*t;
        float v0 = oacc[np][0]*inv0, v1 = oacc[np][1]*inv0;
        float v2 = oacc[np][2]*inv1, v3 = oacc[np][3]*inv1;
        __nv_bfloat16 h0=__float2bfloat16(v0), h1=__float2bfloat16(v1);
        __nv_bfloat16 h2=__float2bfloat16(v2), h3=__float2bfloat16(v3);
        *(uint32_t*)&g_chi[(b*TS + t0)*DM + col] = pkbf(__bfloat162float(h0), __bfloat162float(h1));
        *(uint32_t*)&g_clo[(b*TS + t0)*DM + col] = pkbf(v0-__bfloat162float(h0), v1-__bfloat162float(h1));
        *(uint32_t*)&g_chi[(b*TS + t1)*DM + col] = pkbf(__bfloat162float(h2), __bfloat162float(h3));
        *(uint32_t*)&g_clo[(b*TS + t1)*DM + col] = pkbf(v2-__bfloat162float(h2), v3-__bfloat162float(h3));
    }
}

// ---------------- 7. final per-tensor int8 quant-dequant ----------------
__global__ void quant_out_kernel(float* __restrict__ outp)
{
    float s = fmaxf(__fdiv_rn(__int_as_float(g_absmax), 127.0f), 1e-8f);
    int i = blockIdx.x*256 + threadIdx.x;
    float v = outp[i];
    float qv = rintf(__fdiv_rn(v, s));
    qv = fminf(fmaxf(qv, -127.f), 127.f);
    outp[i] = qv * s;
}

// ---------------- launch ----------------
extern "C" void kernel_launch(void* const* d_in, const int* in_sizes, int n_in,
                              void* d_out, int out_size)
{
    (void)in_sizes; (void)n_in; (void)out_size;
    const float* x  = (const float*)d_in[0];
    const int*   mk = (const int*)  d_in[1];
    const float* Wq = (const float*)d_in[2];
    const float* bq = (const float*)d_in[3];
    const float* Wk = (const float*)d_in[4];
    const float* bk = (const float*)d_in[5];
    const float* Wv = (const float*)d_in[6];
    const float* bv = (const float*)d_in[7];
    const float* Wo = (const float*)d_in[8];
    const float* bo = (const float*)d_in[9];
    float* outp = (float*)d_out;

    cudaFuncSetAttribute(gemm_mma_kernel, cudaFuncAttributeMaxDynamicSharedMemorySize, GEMM_SMEM);
    cudaFuncSetAttribute(attn_mma_kernel, cudaFuncAttributeMaxDynamicSharedMemorySize, ATT_SMEM);

    quant_weights_kernel<<<dim3(DM,4), 128>>>(Wq,Wk,Wv,Wo);
    split_x_kernel<<<(BT_*DM)/1024, 256>>>(x);
    compact_kernel<<<NB, 1024>>>(mk);
    gemm_mma_kernel<<<dim3(BT_/128, DM/128, 3), 256, GEMM_SMEM>>>(bq,bk,bv,bo, outp, 0);
    gather_v_kernel<<<dim3(TS/64, BH_), 256>>>();
    attn_mma_kernel<<<dim3(TS/128, BH_), 256, ATT_SMEM>>>();
    gemm_mma_kernel<<<dim3(BT_/128, DM/128, 1), 256, GEMM_SMEM>>>(bq,bk,bv,bo, outp, 3);
    quant_out_kernel<<<(BT_*DM)/256, 256>>>(outp);
}

// round 15
// speedup vs baseline: 1.1520x; 1.0381x over previous
#include <cuda_runtime.h>
#include <cuda_bf16.h>
#include <math.h>
#include <stdint.h>

typedef unsigned long long ull;

#define DM 512
#define TS 4096
#define NB 2
#define NH 8
#define DHD 64
#define BT_ (NB*TS)    // 8192
#define BH_ (NB*NH)    // 16

// ---------------- device scratch (static, allocation-free) ----------------
// RULE (root cause of R4-R7 failures): these symbols are referenced ONLY
// inside device code. Never pass a __device__ symbol as a kernel argument.
__device__ __nv_bfloat16 g_Wb[4][DM*DM];
__device__ float g_ws[4][DM];
__device__ __nv_bfloat16 g_xhi[BT_*DM];
__device__ __nv_bfloat16 g_xlo[BT_*DM];
__device__ __nv_bfloat16 g_chi[BT_*DM];
__device__ __nv_bfloat16 g_clo[BT_*DM];
__device__ __nv_bfloat16 g_qhi[BH_*TS*DHD];   // Q pre-scaled (x0.125) bf16 hi/lo, [bh][t][dh]
__device__ __nv_bfloat16 g_qlo[BH_*TS*DHD];
__device__ float g_v [BH_*TS*DHD];            // V fp32 (for transposed gather)
__device__ __nv_bfloat16 g_kchi[BH_*TS*DHD];  // compacted K, [bh][rank][d] (written by gemm)
__device__ __nv_bfloat16 g_kclo[BH_*TS*DHD];
__device__ __nv_bfloat16 g_vchi[BH_*DHD*TS];  // compacted V transposed, [bh][d][rank]
__device__ __nv_bfloat16 g_vclo[BH_*DHD*TS];
__device__ int   g_kept[NB*TS];
__device__ int   g_rank[NB*TS];               // t -> rank (or -1)
__device__ int   g_cnt[NB];
__device__ int   g_absmax;

// ---------------- mma / ldmatrix / cp.async helpers ----------------
static __device__ __forceinline__ void mma16816(float* d, const uint32_t* a, const uint32_t* b){
    asm volatile("mma.sync.aligned.m16n8k16.row.col.f32.bf16.bf16.f32 "
        "{%0,%1,%2,%3}, {%4,%5,%6,%7}, {%8,%9}, {%0,%1,%2,%3};"
        : "+f"(d[0]),"+f"(d[1]),"+f"(d[2]),"+f"(d[3])
        : "r"(a[0]),"r"(a[1]),"r"(a[2]),"r"(a[3]), "r"(b[0]),"r"(b[1]));
}
static __device__ __forceinline__ void ldsm4(uint32_t* r, uint32_t a){
    asm volatile("ldmatrix.sync.aligned.m8n8.x4.shared.b16 {%0,%1,%2,%3}, [%4];"
        : "=r"(r[0]),"=r"(r[1]),"=r"(r[2]),"=r"(r[3]) : "r"(a));
}
static __device__ __forceinline__ uint32_t pkbf(float x, float y){
    uint32_t r; asm("cvt.rn.bf16x2.f32 %0, %1, %2;" : "=r"(r) : "f"(y), "f"(x)); return r;
}
static __device__ __forceinline__ uint32_t smem_u32(const void* p){
    uint32_t a;
    asm("{ .reg .u64 t; cvta.to.shared.u64 t, %1; cvt.u32.u64 %0, t; }" : "=r"(a) : "l"(p));
    return a;
}
static __device__ __forceinline__ void cp16(uint32_t dst, const void* src){
    asm volatile("cp.async.ca.shared.global [%0], [%1], 16;" :: "r"(dst), "l"(src) : "memory");
}
static __device__ __forceinline__ void cp16z(uint32_t dst, const void* src, int ssz){
    asm volatile("cp.async.ca.shared.global [%0], [%1], 16, %2;" :: "r"(dst), "l"(src), "r"(ssz) : "memory");
}
#define CP_COMMIT() asm volatile("cp.async.commit_group;" ::: "memory")
#define CP_WAIT1()  asm volatile("cp.async.wait_group 1;" ::: "memory")
#define CP_WAIT0()  asm volatile("cp.async.wait_group 0;" ::: "memory")

// ---------------- 1. per-row symmetric int8 weight quant ----------------
__global__ void quant_weights_kernel(const float* __restrict__ Wq, const float* __restrict__ Wk,
                                     const float* __restrict__ Wv, const float* __restrict__ Wo)
{
    int w = blockIdx.y;
    int row = blockIdx.x;
    const float* srcs[4] = {Wq, Wk, Wv, Wo};
    const float* wr = srcs[w] + row*DM;
    __nv_bfloat16* dst = &g_Wb[w][row*DM];
    int tid = threadIdx.x; // 128
    if (w==0 && row==0 && tid==0) g_absmax = 0;
    float mx = 0.f;
    for (int i=tid;i<DM;i+=128) mx = fmaxf(mx, fabsf(wr[i]));
    for (int off=16;off;off>>=1) mx = fmaxf(mx, __shfl_xor_sync(0xffffffffu, mx, off));
    __shared__ float sm4[4];
    if ((tid&31)==0) sm4[tid>>5] = mx;
    __syncthreads();
    mx = fmaxf(fmaxf(sm4[0],sm4[1]), fmaxf(sm4[2],sm4[3]));
    float s = fmaxf(__fdiv_rn(mx, 127.0f), 1e-8f);
    if (tid==0) g_ws[w][row] = s;
    for (int i=tid;i<DM;i+=128){
        float qv = rintf(__fdiv_rn(wr[i], s));
        qv = fminf(fmaxf(qv, -127.f), 127.f);
        dst[i] = __float2bfloat16(qv);
    }
}

// ---------------- 1b. bf16 hi/lo split of x ----------------
__global__ void split_x_kernel(const float* __restrict__ src)
{
    int i = (blockIdx.x*256 + threadIdx.x)*4;
    float4 v = *(const float4*)&src[i];
    __nv_bfloat16 h0=__float2bfloat16(v.x), h1=__float2bfloat16(v.y);
    __nv_bfloat16 h2=__float2bfloat16(v.z), h3=__float2bfloat16(v.w);
    __nv_bfloat162 hA; hA.x=h0; hA.y=h1;
    __nv_bfloat162 hB; hB.x=h2; hB.y=h3;
    __nv_bfloat162 lA; lA.x=__float2bfloat16(v.x-__bfloat162float(h0)); lA.y=__float2bfloat16(v.y-__bfloat162float(h1));
    __nv_bfloat162 lB; lB.x=__float2bfloat16(v.z-__bfloat162float(h2)); lB.y=__float2bfloat16(v.w-__bfloat162float(h3));
    *(__nv_bfloat162*)&g_xhi[i]   = hA;
    *(__nv_bfloat162*)&g_xhi[i+2] = hB;
    *(__nv_bfloat162*)&g_xlo[i]   = lA;
    *(__nv_bfloat162*)&g_xlo[i+2] = lB;
}

// ---------------- 2. mask compaction (+ inverse rank map) ----------------
__global__ void compact_kernel(const int* __restrict__ mask)
{
    int b = blockIdx.x;
    const int* m = mask + b*TS;
    __shared__ int part[1024];
    int tid = threadIdx.x; // 1024
    int base = tid*4;
    int f0 = m[base]!=0, f1 = m[base+1]!=0, f2 = m[base+2]!=0, f3 = m[base+3]!=0;
    int s = f0+f1+f2+f3;
    part[tid] = s;
    __syncthreads();
    for (int off=1; off<1024; off<<=1){
        int v = (tid>=off) ? part[tid-off] : 0;
        __syncthreads();
        part[tid] += v;
        __syncthreads();
    }
    int rr = part[tid] - s;
    int o = rr + b*TS;
    g_rank[b*TS+base  ] = f0 ? rr : -1; rr += f0;
    g_rank[b*TS+base+1] = f1 ? rr : -1; rr += f1;
    g_rank[b*TS+base+2] = f2 ? rr : -1; rr += f2;
    g_rank[b*TS+base+3] = f3 ? rr : -1;
    if (f0) g_kept[o++] = base;
    if (f1) g_kept[o++] = base+1;
    if (f2) g_kept[o++] = base+2;
    if (f3) g_kept[o++] = base+3;
    if (tid==1023) g_cnt[b] = part[1023];
}

// ---------------- 3. mma GEMM, cp.async 2-stage + ldmatrix; fused Q/K epilogues ----------------
#define GTILE 10240
#define GST3  (3*GTILE)          // 30720 per stage
#define GEMM_SMEM (2*GST3)       // 61440
__global__ void __launch_bounds__(256) gemm_mma_kernel(
    const float* __restrict__ bq, const float* __restrict__ bk,
    const float* __restrict__ bv, const float* __restrict__ bo,
    float* __restrict__ outp, int modebase)
{
    extern __shared__ __align__(16) char dsm[];
    __shared__ float s_sc[128], s_bi[128];
    __shared__ float red8[8];
    int mode = modebase + blockIdx.z;
    int tid = threadIdx.x, lane = tid&31, wid = tid>>5;
    int wm = wid>>1, wn = wid&1;
    int g = lane>>2, t = lane&3;
    int rowbase = blockIdx.x*128, nbase = blockIdx.y*128;
    uint32_t sbase = smem_u32(dsm);

    const __nv_bfloat16* __restrict__ Ahi = (mode<3) ? g_xhi : g_chi;
    const __nv_bfloat16* __restrict__ Alo = (mode<3) ? g_xlo : g_clo;
    const __nv_bfloat16* __restrict__ Bw  = g_Wb[mode];
    const float* biasp = (mode==0)?bq:((mode==1)?bk:((mode==2)?bv:bo));

    auto issue_tile = [&](int st, int kt){
        uint32_t stg = sbase + st*GST3;
        int kb = kt*32;
        #pragma unroll
        for (int i=0;i<2;i++){
            int id = tid + i*256;   // 0..511
            int r = id>>2, c = id&3;
            cp16(stg +           r*80 + c*16, &Ahi[(rowbase+r)*DM + kb + c*8]);
            cp16(stg + GTILE   + r*80 + c*16, &Alo[(rowbase+r)*DM + kb + c*8]);
            cp16(stg + 2*GTILE + r*80 + c*16, &Bw [(nbase  +r)*DM + kb + c*8]);
        }
    };

    issue_tile(0, 0);
    CP_COMMIT();
    if (tid<128) s_sc[tid] = g_ws[mode][nbase+tid];
    else         s_bi[tid-128] = biasp[tid-128+nbase];

    float acc[2][8][4];
    #pragma unroll
    for (int mt=0;mt<2;mt++)
      #pragma unroll
      for (int nt=0;nt<8;nt++)
        #pragma unroll
        for (int c=0;c<4;c++) acc[mt][nt][c] = 0.f;

    int aRow = lane&15, aCol = (lane>>4)<<3;
    int g2 = lane>>3, lr = lane&7;

    for (int kt=0; kt<16; kt++){
        if (kt+1 < 16) issue_tile((kt+1)&1, kt+1);
        CP_COMMIT();
        CP_WAIT1();
        __syncthreads();
        uint32_t stg = sbase + (kt&1)*GST3;
        #pragma unroll
        for (int ks=0; ks<32; ks+=16){
            uint32_t af[2][2][4];
            #pragma unroll
            for (int h=0; h<2; h++)
              #pragma unroll
              for (int mt=0; mt<2; mt++){
                int r0 = wm*32 + mt*16;
                ldsm4(af[h][mt], stg + h*GTILE + (uint32_t)((r0+aRow)*80 + (ks+aCol)*2));
              }
            #pragma unroll
            for (int p=0; p<4; p++){
                int nn = wn*64 + p*16 + ((g2>>1)<<3) + lr;
                int kc = ks + ((g2&1)<<3);
                uint32_t bf4[4];
                ldsm4(bf4, stg + 2*GTILE + (uint32_t)(nn*80 + kc*2));
                #pragma unroll
                for (int mt=0; mt<2; mt++){
                    mma16816(acc[mt][p*2],   af[0][mt], bf4);
                    mma16816(acc[mt][p*2+1], af[0][mt], bf4+2);
                    mma16816(acc[mt][p*2],   af[1][mt], bf4);
                    mma16816(acc[mt][p*2+1], af[1][mt], bf4+2);
                }
            }
        }
        __syncthreads();
    }
    float amax = 0.f;
    #pragma unroll
    for (int mt=0;mt<2;mt++){
      #pragma unroll
      for (int nt=0;nt<8;nt++){
        int ncol = wn*64 + nt*8 + 2*t;
        float s0 = s_sc[ncol], s1 = s_sc[ncol+1];
        float b0 = s_bi[ncol], b1 = s_bi[ncol+1];
        #pragma unroll
        for (int rh=0; rh<2; rh++){
            int row = rowbase + wm*32 + mt*16 + g + rh*8;
            float v0 = acc[mt][nt][rh*2  ]*s0 + b0;
            float v1 = acc[mt][nt][rh*2+1]*s1 + b1;
            if (mode==3){
                float2 w; w.x = v0; w.y = v1;
                *(float2*)&outp[row*DM + nbase + ncol] = w;
                amax = fmaxf(amax, fmaxf(fabsf(v0), fabsf(v1)));
            } else {
                int o = nbase + ncol;
                int head = o>>6, dh = o&63;
                int bb = row>>12, tt = row&4095;
                if (mode==0){
                    float q0 = v0*0.125f, q1 = v1*0.125f;
                    float h0 = __bfloat162float(__float2bfloat16(q0));
                    float h1 = __bfloat162float(__float2bfloat16(q1));
                    int idx = ((bb*NH+head)*TS + tt)*DHD + dh;
                    *(uint32_t*)&g_qhi[idx] = pkbf(h0, h1);
                    *(uint32_t*)&g_qlo[idx] = pkbf(q0-h0, q1-h1);
                } else if (mode==1){
                    int rk = g_rank[bb*TS + tt];
                    if (rk >= 0){
                        float h0 = __bfloat162float(__float2bfloat16(v0));
                        float h1 = __bfloat162float(__float2bfloat16(v1));
                        int idx = ((bb*NH+head)*TS + rk)*DHD + dh;
                        *(uint32_t*)&g_kchi[idx] = pkbf(h0, h1);
                        *(uint32_t*)&g_kclo[idx] = pkbf(v0-h0, v1-h1);
                    }
                } else {
                    float2 w; w.x = v0; w.y = v1;
                    *(float2*)&g_v[((bb*NH+head)*TS + tt)*DHD + dh] = w;
                }
            }
        }
      }
    }
    if (mode==3){
        for (int off=16;off;off>>=1) amax = fmaxf(amax, __shfl_xor_sync(0xffffffffu, amax, off));
        if (lane==0) red8[wid] = amax;
        __syncthreads();
        if (tid==0){
            float m = red8[0];
            #pragma unroll
            for (int i=1;i<8;i++) m = fmaxf(m, red8[i]);
            atomicMax(&g_absmax, __float_as_int(m));
        }
    }
}

// ---------------- 4. V-only coalesced gather+transpose: g_v kept rows -> [bh][d][rank] -------
__global__ void __launch_bounds__(256) gather_v_kernel()
{
    __shared__ float vs[64][65];
    __shared__ int srcs[64];
    int bh = blockIdx.y;
    int b = bh>>3;
    int jbase = blockIdx.x*64;
    int cnt = g_cnt[b];
    int tid = threadIdx.x;
    if (tid < 64){
        int j = jbase + tid;
        srcs[tid] = (j < cnt) ? g_kept[b*TS + j] : -1;
    }
    __syncthreads();
    #pragma unroll
    for (int i=0;i<16;i++){
        int id = tid + i*256;
        int j = id>>6, d = id&63;
        int src = srcs[j];
        vs[j][d] = (src >= 0) ? g_v[(bh*TS + src)*DHD + d] : 0.f;
    }
    __syncthreads();
    #pragma unroll
    for (int i=0;i<16;i++){
        int id = tid + i*256;
        int d = id>>6, j = id&63;
        float vv = vs[j][d];
        __nv_bfloat16 h = __float2bfloat16(vv);
        int o = (bh*DHD + d)*TS + jbase + j;
        g_vchi[o] = h;
        g_vclo[o] = __float2bfloat16(vv - __bfloat162float(h));
    }
}

// ---------------- 5. flash attention: BQ=128, BK=64, 4 warps x m32, cp.async pipeline --------
#define ASK 144                  // row stride bytes (72 bf16; 16B aligned)
#define AQ_REG 18432             // Q hi or lo: 128 rows x 144B
#define AST   36864              // per KV stage: KH|KL|VH|VL, 64x144 each
#define ATT_SMEM (2*AQ_REG + 2*AST)   // 110592
__global__ void __launch_bounds__(128, 2) attn_mma_kernel()
{
    extern __shared__ __align__(16) char smem[];
    const int OQH=0, OQL=AQ_REG;
    int bh = blockIdx.y;
    int b = bh>>3, h = bh&7;
    int qbase = blockIdx.x*128;
    int tid = threadIdx.x, lane = tid&31, wid = tid>>5;   // 4 warps
    int g = lane>>2, t = lane&3;
    int cnt = g_cnt[b];
    uint32_t sbase = smem_u32(smem);

    auto issue_kv = [&](int st, int kb){
        uint32_t stg = sbase + 2*AQ_REG + st*AST;
        #pragma unroll
        for (int i=0;i<4;i++){
            int id = tid + i*128;   // 0..511
            int j = id>>3, c = id&7;
            int jj = kb + j;
            int kssz = (jj < cnt) ? 16 : 0;
            int jc = jj < TS ? jj : TS-1;
            cp16z(stg +         j*ASK + c*16, &g_kchi[(bh*TS+jc)*DHD + c*8], kssz);
            cp16z(stg +  9216 + j*ASK + c*16, &g_kclo[(bh*TS+jc)*DHD + c*8], kssz);
            int vb = (cnt - (kb + c*8))*2;
            vb = vb < 0 ? 0 : (vb > 16 ? 16 : vb);
            int cb2 = kb + c*8; if (cb2 > TS-8) cb2 = TS-8;
            cp16z(stg + 18432 + j*ASK + c*16, &g_vchi[(bh*DHD+j)*TS + cb2], vb);
            cp16z(stg + 27648 + j*ASK + c*16, &g_vclo[(bh*DHD+j)*TS + cb2], vb);
        }
    };

    // Q hi/lo straight from gmem (pre-scaled, pre-split by the QKV gemm epilogue)
    #pragma unroll
    for (int i=0;i<8;i++){
        int id = tid + i*128;    // 0..1023
        int q = id>>3, c = id&7;
        int gi = (bh*TS + qbase + q)*DHD + c*8;
        cp16(sbase + OQH + (uint32_t)(q*ASK + c*16), &g_qhi[gi]);
        cp16(sbase + OQL + (uint32_t)(q*ASK + c*16), &g_qlo[gi]);
    }
    CP_COMMIT();
    issue_kv(0, 0);
    CP_COMMIT();
    CP_WAIT1();                 // Q group complete
    __syncthreads();

    // hoist Q fragments via ldmatrix: two m16 tiles per warp
    uint32_t qh[2][4][4], ql[2][4][4];
    int m0 = wid*32;
    int aRow = lane&15, aCol = (lane>>4)<<3;
    int g2 = lane>>3, lr = lane&7;
    #pragma unroll
    for (int mt=0;mt<2;mt++)
      #pragma unroll
      for (int kt=0;kt<4;kt++){
        uint32_t off = (uint32_t)((m0+mt*16+aRow)*ASK + (kt*16+aCol)*2);
        ldsm4(qh[mt][kt], sbase + OQH + off);
        ldsm4(ql[mt][kt], sbase + OQL + off);
      }

    float oacc[2][8][4];
    #pragma unroll
    for (int mt=0;mt<2;mt++)
      #pragma unroll
      for (int np=0;np<8;np++){ oacc[mt][np][0]=0.f; oacc[mt][np][1]=0.f; oacc[mt][np][2]=0.f; oacc[mt][np][3]=0.f; }
    float sprev[2][2] = {{-1e30f,-1e30f},{-1e30f,-1e30f}};
    float lrun[2][2]  = {{0.f,0.f},{0.f,0.f}};
    int NT = (cnt + 63) >> 6;

    for (int it=0; it<NT; it++){
        int kb = it*64;
        CP_WAIT0();
        __syncthreads();          // tile it visible; prior reads of slot (it+1)&1 done
        if (it+1 < NT) issue_kv((it+1)&1, kb+64);
        CP_COMMIT();
        uint32_t stg = sbase + 2*AQ_REG + (it&1)*AST;
        uint32_t uKH = stg, uKL = stg + 9216, uVH = stg + 18432, uVL = stg + 27648;

        // S = Q K^T (3 hi/lo combos), two m-tiles share each K-fragment load
        float sacc[2][8][4];
        #pragma unroll
        for (int mt=0;mt<2;mt++)
          #pragma unroll
          for (int np=0;np<8;np++){ sacc[mt][np][0]=0.f; sacc[mt][np][1]=0.f; sacc[mt][np][2]=0.f; sacc[mt][np][3]=0.f; }
        #pragma unroll
        for (int kt=0;kt<4;kt++){
            #pragma unroll
            for (int p=0;p<4;p++){
                int nn = p*16 + ((g2>>1)<<3) + lr;
                int kc = kt*16 + ((g2&1)<<3);
                uint32_t off = (uint32_t)(nn*ASK + kc*2);
                uint32_t bh4[4], bl4[4];
                ldsm4(bh4, uKH + off);
                ldsm4(bl4, uKL + off);
                #pragma unroll
                for (int mt=0;mt<2;mt++){
                    mma16816(sacc[mt][p*2],   qh[mt][kt], bh4);
                    mma16816(sacc[mt][p*2+1], qh[mt][kt], bh4+2);
                    mma16816(sacc[mt][p*2],   qh[mt][kt], bl4);
                    mma16816(sacc[mt][p*2+1], qh[mt][kt], bl4+2);
                    mma16816(sacc[mt][p*2],   ql[mt][kt], bh4);
                    mma16816(sacc[mt][p*2+1], ql[mt][kt], bh4+2);
                }
            }
        }
        if (kb + 64 > cnt){
            #pragma unroll
            for (int mt=0;mt<2;mt++)
              #pragma unroll
              for (int np=0;np<8;np++)
                #pragma unroll
                for (int c=0;c<4;c++){
                    int j = kb + np*8 + 2*t + (c&1);
                    if (j >= cnt) sacc[mt][np][c] = -1e30f;
                }
        }
        // online softmax per m-tile (rows g and g+8 in each)
        #pragma unroll
        for (int mt=0;mt<2;mt++){
            float mt0 = sprev[mt][0], mt1 = sprev[mt][1];
            #pragma unroll
            for (int np=0;np<8;np++){
                mt0 = fmaxf(mt0, fmaxf(sacc[mt][np][0], sacc[mt][np][1]));
                mt1 = fmaxf(mt1, fmaxf(sacc[mt][np][2], sacc[mt][np][3]));
            }
            mt0 = fmaxf(mt0, __shfl_xor_sync(0xffffffffu, mt0, 1));
            mt0 = fmaxf(mt0, __shfl_xor_sync(0xffffffffu, mt0, 2));
            mt1 = fmaxf(mt1, __shfl_xor_sync(0xffffffffu, mt1, 1));
            mt1 = fmaxf(mt1, __shfl_xor_sync(0xffffffffu, mt1, 2));
            float c0 = __expf(sprev[mt][0]-mt0), c1 = __expf(sprev[mt][1]-mt1);
            float rs0 = 0.f, rs1 = 0.f;
            #pragma unroll
            for (int np=0;np<8;np++){
                sacc[mt][np][0] = __expf(sacc[mt][np][0]-mt0); rs0 += sacc[mt][np][0];
                sacc[mt][np][1] = __expf(sacc[mt][np][1]-mt0); rs0 += sacc[mt][np][1];
                sacc[mt][np][2] = __expf(sacc[mt][np][2]-mt1); rs1 += sacc[mt][np][2];
                sacc[mt][np][3] = __expf(sacc[mt][np][3]-mt1); rs1 += sacc[mt][np][3];
            }
            rs0 += __shfl_xor_sync(0xffffffffu, rs0, 1);
            rs0 += __shfl_xor_sync(0xffffffffu, rs0, 2);
            rs1 += __shfl_xor_sync(0xffffffffu, rs1, 1);
            rs1 += __shfl_xor_sync(0xffffffffu, rs1, 2);
            lrun[mt][0] = lrun[mt][0]*c0 + rs0;
            lrun[mt][1] = lrun[mt][1]*c1 + rs1;
            sprev[mt][0] = mt0; sprev[mt][1] = mt1;
            #pragma unroll
            for (int np=0;np<8;np++){
                oacc[mt][np][0]*=c0; oacc[mt][np][1]*=c0; oacc[mt][np][2]*=c1; oacc[mt][np][3]*=c1;
            }
        }
        // O += P V (3 combos); P A-frags in-register; V-fragment loads shared by both m-tiles
        #pragma unroll
        for (int kt=0;kt<4;kt++){
            uint32_t ah[2][4], al[2][4];
            #pragma unroll
            for (int mt=0;mt<2;mt++){
                float p0 = sacc[mt][2*kt][0],   p1 = sacc[mt][2*kt][1];
                float p2 = sacc[mt][2*kt][2],   p3 = sacc[mt][2*kt][3];
                float p4 = sacc[mt][2*kt+1][0], p5 = sacc[mt][2*kt+1][1];
                float p6 = sacc[mt][2*kt+1][2], p7 = sacc[mt][2*kt+1][3];
                ah[mt][0] = pkbf(p0,p1); ah[mt][1] = pkbf(p2,p3);
                ah[mt][2] = pkbf(p4,p5); ah[mt][3] = pkbf(p6,p7);
                al[mt][0] = pkbf(p0-__bfloat162float(__float2bfloat16(p0)), p1-__bfloat162float(__float2bfloat16(p1)));
                al[mt][1] = pkbf(p2-__bfloat162float(__float2bfloat16(p2)), p3-__bfloat162float(__float2bfloat16(p3)));
                al[mt][2] = pkbf(p4-__bfloat162float(__float2bfloat16(p4)), p5-__bfloat162float(__float2bfloat16(p5)));
                al[mt][3] = pkbf(p6-__bfloat162float(__float2bfloat16(p6)), p7-__bfloat162float(__float2bfloat16(p7)));
            }
            #pragma unroll
            for (int p=0;p<4;p++){
                int nn = p*16 + ((g2>>1)<<3) + lr;
                int kc = kt*16 + ((g2&1)<<3);
                uint32_t off = (uint32_t)(nn*ASK + kc*2);
                uint32_t vh4[4], vl4[4];
                ldsm4(vh4, uVH + off);
                ldsm4(vl4, uVL + off);
                #pragma unroll
                for (int mt=0;mt<2;mt++){
                    mma16816(oacc[mt][p*2],   ah[mt], vh4);
                    mma16816(oacc[mt][p*2+1], ah[mt], vh4+2);
                    mma16816(oacc[mt][p*2],   ah[mt], vl4);
                    mma16816(oacc[mt][p*2+1], ah[mt], vl4+2);
                    mma16816(oacc[mt][p*2],   al[mt], vh4);
                    mma16816(oacc[mt][p*2+1], al[mt], vh4+2);
                }
            }
        }
    }
    // epilogue: normalize, hi/lo split, write ctx as bf16
    #pragma unroll
    for (int mt=0;mt<2;mt++){
        float inv0 = __fdiv_rn(1.0f, lrun[mt][0]);
        float inv1 = __fdiv_rn(1.0f, lrun[mt][1]);
        int t0 = qbase + m0 + mt*16 + g;
        int t1 = t0 + 8;
        #pragma unroll
        for (int np=0;np<8;np++){
            int col = h*DHD + np*8 + 2*t;
            float v0 = oacc[mt][np][0]*inv0, v1 = oacc[mt][np][1]*inv0;
            float v2 = oacc[mt][np][2]*inv1, v3 = oacc[mt][np][3]*inv1;
            __nv_bfloat16 h0=__float2bfloat16(v0), h1=__float2bfloat16(v1);
            __nv_bfloat16 h2=__float2bfloat16(v2), h3=__float2bfloat16(v3);
            *(uint32_t*)&g_chi[(b*TS + t0)*DM + col] = pkbf(__bfloat162float(h0), __bfloat162float(h1));
            *(uint32_t*)&g_clo[(b*TS + t0)*DM + col] = pkbf(v0-__bfloat162float(h0), v1-__bfloat162float(h1));
            *(uint32_t*)&g_chi[(b*TS + t1)*DM + col] = pkbf(__bfloat162float(h2), __bfloat162float(h3));
            *(uint32_t*)&g_clo[(b*TS + t1)*DM + col] = pkbf(v2-__bfloat162float(h2), v3-__bfloat162float(h3));
        }
    }
}

// ---------------- 7. final per-tensor int8 quant-dequant ----------------
__global__ void quant_out_kernel(float* __restrict__ outp)
{
    float s = fmaxf(__fdiv_rn(__int_as_float(g_absmax), 127.0f), 1e-8f);
    int i = blockIdx.x*256 + threadIdx.x;
    float v = outp[i];
    float qv = rintf(__fdiv_rn(v, s));
    qv = fminf(fmaxf(qv, -127.f), 127.f);
    outp[i] = qv * s;
}

// ---------------- launch ----------------
extern "C" void kernel_launch(void* const* d_in, const int* in_sizes, int n_in,
                              void* d_out, int out_size)
{
    (void)in_sizes; (void)n_in; (void)out_size;
    const float* x  = (const float*)d_in[0];
    const int*   mk = (const int*)  d_in[1];
    const float* Wq = (const float*)d_in[2];
    const float* bq = (const float*)d_in[3];
    const float* Wk = (const float*)d_in[4];
    const float* bk = (const float*)d_in[5];
    const float* Wv = (const float*)d_in[6];
    const float* bv = (const float*)d_in[7];
    const float* Wo = (const float*)d_in[8];
    const float* bo = (const float*)d_in[9];
    float* outp = (float*)d_out;

    cudaFuncSetAttribute(gemm_mma_kernel, cudaFuncAttributeMaxDynamicSharedMemorySize, GEMM_SMEM);
    cudaFuncSetAttribute(attn_mma_kernel, cudaFuncAttributeMaxDynamicSharedMemorySize, ATT_SMEM);

    quant_weights_kernel<<<dim3(DM,4), 128>>>(Wq,Wk,Wv,Wo);
    split_x_kernel<<<(BT_*DM)/1024, 256>>>(x);
    compact_kernel<<<NB, 1024>>>(mk);
    gemm_mma_kernel<<<dim3(BT_/128, DM/128, 3), 256, GEMM_SMEM>>>(bq,bk,bv,bo, outp, 0);
    gather_v_kernel<<<dim3(TS/64, BH_), 256>>>();
    attn_mma_kernel<<<dim3(TS/128, BH_), 128, ATT_SMEM>>>();
    gemm_mma_kernel<<<dim3(BT_/128, DM/128, 1), 256, GEMM_SMEM>>>(bq,bk,bv,bo, outp, 3);
    quant_out_kernel<<<(BT_*DM)/256, 256>>>(outp);
}

// round 16
// speedup vs baseline: 1.1645x; 1.0108x over previous
#include <cuda_runtime.h>
#include <cuda_bf16.h>
#include <math.h>
#include <stdint.h>

typedef unsigned long long ull;

#define DM 512
#define TS 4096
#define NB 2
#define NH 8
#define DHD 64
#define BT_ (NB*TS)    // 8192
#define BH_ (NB*NH)    // 16

// ---------------- device scratch (static, allocation-free) ----------------
// RULE (root cause of R4-R7 failures): these symbols are referenced ONLY
// inside device code. Never pass a __device__ symbol as a kernel argument.
__device__ __nv_bfloat16 g_Wb[4][DM*DM];
__device__ float g_ws[4][DM];
__device__ __nv_bfloat16 g_xhi[BT_*DM];
__device__ __nv_bfloat16 g_xlo[BT_*DM];
__device__ __nv_bfloat16 g_chi[BT_*DM];
__device__ __nv_bfloat16 g_clo[BT_*DM];
__device__ __nv_bfloat16 g_qhi[BH_*TS*DHD];   // Q pre-scaled (x0.125) bf16 hi/lo, [bh][t][dh]
__device__ __nv_bfloat16 g_qlo[BH_*TS*DHD];
__device__ float g_v [BH_*TS*DHD];            // V fp32 (for transposed gather)
__device__ __nv_bfloat16 g_kchi[BH_*TS*DHD];  // compacted K, [bh][rank][d] (written by gemm)
__device__ __nv_bfloat16 g_kclo[BH_*TS*DHD];
__device__ __nv_bfloat16 g_vchi[BH_*DHD*TS];  // compacted V transposed, [bh][d][rank]
__device__ __nv_bfloat16 g_vclo[BH_*DHD*TS];
__device__ int   g_kept[NB*TS];
__device__ int   g_rank[NB*TS];               // t -> rank (or -1)
__device__ int   g_cnt[NB];
__device__ int   g_absmax;

// ---------------- mma / ldmatrix / cp.async helpers ----------------
static __device__ __forceinline__ void mma16816(float* d, const uint32_t* a, const uint32_t* b){
    asm volatile("mma.sync.aligned.m16n8k16.row.col.f32.bf16.bf16.f32 "
        "{%0,%1,%2,%3}, {%4,%5,%6,%7}, {%8,%9}, {%0,%1,%2,%3};"
        : "+f"(d[0]),"+f"(d[1]),"+f"(d[2]),"+f"(d[3])
        : "r"(a[0]),"r"(a[1]),"r"(a[2]),"r"(a[3]), "r"(b[0]),"r"(b[1]));
}
static __device__ __forceinline__ void ldsm4(uint32_t* r, uint32_t a){
    asm volatile("ldmatrix.sync.aligned.m8n8.x4.shared.b16 {%0,%1,%2,%3}, [%4];"
        : "=r"(r[0]),"=r"(r[1]),"=r"(r[2]),"=r"(r[3]) : "r"(a));
}
static __device__ __forceinline__ uint32_t pkbf(float x, float y){
    uint32_t r; asm("cvt.rn.bf16x2.f32 %0, %1, %2;" : "=r"(r) : "f"(y), "f"(x)); return r;
}
static __device__ __forceinline__ uint32_t smem_u32(const void* p){
    uint32_t a;
    asm("{ .reg .u64 t; cvta.to.shared.u64 t, %1; cvt.u32.u64 %0, t; }" : "=r"(a) : "l"(p));
    return a;
}
static __device__ __forceinline__ void cp16(uint32_t dst, const void* src){
    asm volatile("cp.async.ca.shared.global [%0], [%1], 16;" :: "r"(dst), "l"(src) : "memory");
}
static __device__ __forceinline__ void cp16z(uint32_t dst, const void* src, int ssz){
    asm volatile("cp.async.ca.shared.global [%0], [%1], 16, %2;" :: "r"(dst), "l"(src), "r"(ssz) : "memory");
}
#define CP_COMMIT() asm volatile("cp.async.commit_group;" ::: "memory")
#define CP_WAIT2()  asm volatile("cp.async.wait_group 2;" ::: "memory")
#define CP_WAIT1()  asm volatile("cp.async.wait_group 1;" ::: "memory")
#define CP_WAIT0()  asm volatile("cp.async.wait_group 0;" ::: "memory")

// ---------------- 1. per-row symmetric int8 weight quant ----------------
__global__ void quant_weights_kernel(const float* __restrict__ Wq, const float* __restrict__ Wk,
                                     const float* __restrict__ Wv, const float* __restrict__ Wo)
{
    int w = blockIdx.y;
    int row = blockIdx.x;
    const float* srcs[4] = {Wq, Wk, Wv, Wo};
    const float* wr = srcs[w] + row*DM;
    __nv_bfloat16* dst = &g_Wb[w][row*DM];
    int tid = threadIdx.x; // 128
    if (w==0 && row==0 && tid==0) g_absmax = 0;
    float mx = 0.f;
    for (int i=tid;i<DM;i+=128) mx = fmaxf(mx, fabsf(wr[i]));
    for (int off=16;off;off>>=1) mx = fmaxf(mx, __shfl_xor_sync(0xffffffffu, mx, off));
    __shared__ float sm4[4];
    if ((tid&31)==0) sm4[tid>>5] = mx;
    __syncthreads();
    mx = fmaxf(fmaxf(sm4[0],sm4[1]), fmaxf(sm4[2],sm4[3]));
    float s = fmaxf(__fdiv_rn(mx, 127.0f), 1e-8f);
    if (tid==0) g_ws[w][row] = s;
    for (int i=tid;i<DM;i+=128){
        float qv = rintf(__fdiv_rn(wr[i], s));
        qv = fminf(fmaxf(qv, -127.f), 127.f);
        dst[i] = __float2bfloat16(qv);
    }
}

// ---------------- 1b. bf16 hi/lo split of x ----------------
__global__ void split_x_kernel(const float* __restrict__ src)
{
    int i = (blockIdx.x*256 + threadIdx.x)*4;
    float4 v = *(const float4*)&src[i];
    __nv_bfloat16 h0=__float2bfloat16(v.x), h1=__float2bfloat16(v.y);
    __nv_bfloat16 h2=__float2bfloat16(v.z), h3=__float2bfloat16(v.w);
    __nv_bfloat162 hA; hA.x=h0; hA.y=h1;
    __nv_bfloat162 hB; hB.x=h2; hB.y=h3;
    __nv_bfloat162 lA; lA.x=__float2bfloat16(v.x-__bfloat162float(h0)); lA.y=__float2bfloat16(v.y-__bfloat162float(h1));
    __nv_bfloat162 lB; lB.x=__float2bfloat16(v.z-__bfloat162float(h2)); lB.y=__float2bfloat16(v.w-__bfloat162float(h3));
    *(__nv_bfloat162*)&g_xhi[i]   = hA;
    *(__nv_bfloat162*)&g_xhi[i+2] = hB;
    *(__nv_bfloat162*)&g_xlo[i]   = lA;
    *(__nv_bfloat162*)&g_xlo[i+2] = lB;
}

// ---------------- 2. mask compaction (+ inverse rank map) ----------------
__global__ void compact_kernel(const int* __restrict__ mask)
{
    int b = blockIdx.x;
    const int* m = mask + b*TS;
    __shared__ int part[1024];
    int tid = threadIdx.x; // 1024
    int base = tid*4;
    int f0 = m[base]!=0, f1 = m[base+1]!=0, f2 = m[base+2]!=0, f3 = m[base+3]!=0;
    int s = f0+f1+f2+f3;
    part[tid] = s;
    __syncthreads();
    for (int off=1; off<1024; off<<=1){
        int v = (tid>=off) ? part[tid-off] : 0;
        __syncthreads();
        part[tid] += v;
        __syncthreads();
    }
    int rr = part[tid] - s;
    int o = rr + b*TS;
    g_rank[b*TS+base  ] = f0 ? rr : -1; rr += f0;
    g_rank[b*TS+base+1] = f1 ? rr : -1; rr += f1;
    g_rank[b*TS+base+2] = f2 ? rr : -1; rr += f2;
    g_rank[b*TS+base+3] = f3 ? rr : -1;
    if (f0) g_kept[o++] = base;
    if (f1) g_kept[o++] = base+1;
    if (f2) g_kept[o++] = base+2;
    if (f3) g_kept[o++] = base+3;
    if (tid==1023) g_cnt[b] = part[1023];
}

// ---------------- 3. mma GEMM, cp.async 2-stage + ldmatrix; fused Q/K epilogues ----------------
#define GTILE 10240
#define GST3  (3*GTILE)          // 30720 per stage
#define GEMM_SMEM (2*GST3)       // 61440
__global__ void __launch_bounds__(256) gemm_mma_kernel(
    const float* __restrict__ bq, const float* __restrict__ bk,
    const float* __restrict__ bv, const float* __restrict__ bo,
    float* __restrict__ outp, int modebase)
{
    extern __shared__ __align__(16) char dsm[];
    __shared__ float s_sc[128], s_bi[128];
    __shared__ float red8[8];
    int mode = modebase + blockIdx.z;
    int tid = threadIdx.x, lane = tid&31, wid = tid>>5;
    int wm = wid>>1, wn = wid&1;
    int g = lane>>2, t = lane&3;
    int rowbase = blockIdx.x*128, nbase = blockIdx.y*128;
    uint32_t sbase = smem_u32(dsm);

    const __nv_bfloat16* __restrict__ Ahi = (mode<3) ? g_xhi : g_chi;
    const __nv_bfloat16* __restrict__ Alo = (mode<3) ? g_xlo : g_clo;
    const __nv_bfloat16* __restrict__ Bw  = g_Wb[mode];
    const float* biasp = (mode==0)?bq:((mode==1)?bk:((mode==2)?bv:bo));

    auto issue_tile = [&](int st, int kt){
        uint32_t stg = sbase + st*GST3;
        int kb = kt*32;
        #pragma unroll
        for (int i=0;i<2;i++){
            int id = tid + i*256;   // 0..511
            int r = id>>2, c = id&3;
            cp16(stg +           r*80 + c*16, &Ahi[(rowbase+r)*DM + kb + c*8]);
            cp16(stg + GTILE   + r*80 + c*16, &Alo[(rowbase+r)*DM + kb + c*8]);
            cp16(stg + 2*GTILE + r*80 + c*16, &Bw [(nbase  +r)*DM + kb + c*8]);
        }
    };

    issue_tile(0, 0);
    CP_COMMIT();
    if (tid<128) s_sc[tid] = g_ws[mode][nbase+tid];
    else         s_bi[tid-128] = biasp[tid-128+nbase];

    float acc[2][8][4];
    #pragma unroll
    for (int mt=0;mt<2;mt++)
      #pragma unroll
      for (int nt=0;nt<8;nt++)
        #pragma unroll
        for (int c=0;c<4;c++) acc[mt][nt][c] = 0.f;

    int aRow = lane&15, aCol = (lane>>4)<<3;
    int g2 = lane>>3, lr = lane&7;

    for (int kt=0; kt<16; kt++){
        if (kt+1 < 16) issue_tile((kt+1)&1, kt+1);
        CP_COMMIT();
        CP_WAIT1();
        __syncthreads();
        uint32_t stg = sbase + (kt&1)*GST3;
        #pragma unroll
        for (int ks=0; ks<32; ks+=16){
            uint32_t af[2][2][4];
            #pragma unroll
            for (int h=0; h<2; h++)
              #pragma unroll
              for (int mt=0; mt<2; mt++){
                int r0 = wm*32 + mt*16;
                ldsm4(af[h][mt], stg + h*GTILE + (uint32_t)((r0+aRow)*80 + (ks+aCol)*2));
              }
            #pragma unroll
            for (int p=0; p<4; p++){
                int nn = wn*64 + p*16 + ((g2>>1)<<3) + lr;
                int kc = ks + ((g2&1)<<3);
                uint32_t bf4[4];
                ldsm4(bf4, stg + 2*GTILE + (uint32_t)(nn*80 + kc*2));
                #pragma unroll
                for (int mt=0; mt<2; mt++){
                    mma16816(acc[mt][p*2],   af[0][mt], bf4);
                    mma16816(acc[mt][p*2+1], af[0][mt], bf4+2);
                    mma16816(acc[mt][p*2],   af[1][mt], bf4);
                    mma16816(acc[mt][p*2+1], af[1][mt], bf4+2);
                }
            }
        }
        __syncthreads();
    }
    float amax = 0.f;
    #pragma unroll
    for (int mt=0;mt<2;mt++){
      #pragma unroll
      for (int nt=0;nt<8;nt++){
        int ncol = wn*64 + nt*8 + 2*t;
        float s0 = s_sc[ncol], s1 = s_sc[ncol+1];
        float b0 = s_bi[ncol], b1 = s_bi[ncol+1];
        #pragma unroll
        for (int rh=0; rh<2; rh++){
            int row = rowbase + wm*32 + mt*16 + g + rh*8;
            float v0 = acc[mt][nt][rh*2  ]*s0 + b0;
            float v1 = acc[mt][nt][rh*2+1]*s1 + b1;
            if (mode==3){
                float2 w; w.x = v0; w.y = v1;
                *(float2*)&outp[row*DM + nbase + ncol] = w;
                amax = fmaxf(amax, fmaxf(fabsf(v0), fabsf(v1)));
            } else {
                int o = nbase + ncol;
                int head = o>>6, dh = o&63;
                int bb = row>>12, tt = row&4095;
                if (mode==0){
                    float q0 = v0*0.125f, q1 = v1*0.125f;
                    float h0 = __bfloat162float(__float2bfloat16(q0));
                    float h1 = __bfloat162float(__float2bfloat16(q1));
                    int idx = ((bb*NH+head)*TS + tt)*DHD + dh;
                    *(uint32_t*)&g_qhi[idx] = pkbf(h0, h1);
                    *(uint32_t*)&g_qlo[idx] = pkbf(q0-h0, q1-h1);
                } else if (mode==1){
                    int rk = g_rank[bb*TS + tt];
                    if (rk >= 0){
                        float h0 = __bfloat162float(__float2bfloat16(v0));
                        float h1 = __bfloat162float(__float2bfloat16(v1));
                        int idx = ((bb*NH+head)*TS + rk)*DHD + dh;
                        *(uint32_t*)&g_kchi[idx] = pkbf(h0, h1);
                        *(uint32_t*)&g_kclo[idx] = pkbf(v0-h0, v1-h1);
                    }
                } else {
                    float2 w; w.x = v0; w.y = v1;
                    *(float2*)&g_v[((bb*NH+head)*TS + tt)*DHD + dh] = w;
                }
            }
        }
      }
    }
    if (mode==3){
        for (int off=16;off;off>>=1) amax = fmaxf(amax, __shfl_xor_sync(0xffffffffu, amax, off));
        if (lane==0) red8[wid] = amax;
        __syncthreads();
        if (tid==0){
            float m = red8[0];
            #pragma unroll
            for (int i=1;i<8;i++) m = fmaxf(m, red8[i]);
            atomicMax(&g_absmax, __float_as_int(m));
        }
    }
}

// ---------------- 4. V-only coalesced gather+transpose: g_v kept rows -> [bh][d][rank] -------
__global__ void __launch_bounds__(256) gather_v_kernel()
{
    __shared__ float vs[64][65];
    __shared__ int srcs[64];
    int bh = blockIdx.y;
    int b = bh>>3;
    int jbase = blockIdx.x*64;
    int cnt = g_cnt[b];
    int tid = threadIdx.x;
    if (tid < 64){
        int j = jbase + tid;
        srcs[tid] = (j < cnt) ? g_kept[b*TS + j] : -1;
    }
    __syncthreads();
    #pragma unroll
    for (int i=0;i<16;i++){
        int id = tid + i*256;
        int j = id>>6, d = id&63;
        int src = srcs[j];
        vs[j][d] = (src >= 0) ? g_v[(bh*TS + src)*DHD + d] : 0.f;
    }
    __syncthreads();
    #pragma unroll
    for (int i=0;i<16;i++){
        int id = tid + i*256;
        int d = id>>6, j = id&63;
        float vv = vs[j][d];
        __nv_bfloat16 h = __float2bfloat16(vv);
        int o = (bh*DHD + d)*TS + jbase + j;
        g_vchi[o] = h;
        g_vclo[o] = __float2bfloat16(vv - __bfloat162float(h));
    }
}

// ---------------- 5. flash attention: BQ=128, BK=64, 4 warps x m32, 3-stage KV pipeline ------
// Q smem region (2 x 18432 = 36864 B) is exactly one KV stage; after the Q-fragment
// hoist it is recycled as stage 0 -> 3-stage pipeline with prefetch depth 2, same smem.
#define ASK 144                  // row stride bytes (72 bf16; 16B aligned)
#define AQ_REG 18432             // Q hi or lo: 128 rows x 144B
#define AST   36864              // per KV stage: KH|KL|VH|VL, 64x144 each
#define ATT_SMEM (3*AST)         // 110592 (s0 doubles as Q region)
__global__ void __launch_bounds__(128, 2) attn_mma_kernel()
{
    extern __shared__ __align__(16) char smem[];
    const int OQH=0, OQL=AQ_REG;     // Q occupies stage-0 region before the hoist
    int bh = blockIdx.y;
    int b = bh>>3, h = bh&7;
    int qbase = blockIdx.x*128;
    int tid = threadIdx.x, lane = tid&31, wid = tid>>5;   // 4 warps
    int g = lane>>2, t = lane&3;
    int cnt = g_cnt[b];
    uint32_t sbase = smem_u32(smem);

    auto issue_kv = [&](int st, int kb){
        uint32_t stg = sbase + st*AST;
        #pragma unroll
        for (int i=0;i<4;i++){
            int id = tid + i*128;   // 0..511
            int j = id>>3, c = id&7;
            int jj = kb + j;
            int kssz = (jj < cnt) ? 16 : 0;
            int jc = jj < TS ? jj : TS-1;
            cp16z(stg +         j*ASK + c*16, &g_kchi[(bh*TS+jc)*DHD + c*8], kssz);
            cp16z(stg +  9216 + j*ASK + c*16, &g_kclo[(bh*TS+jc)*DHD + c*8], kssz);
            int vb = (cnt - (kb + c*8))*2;
            vb = vb < 0 ? 0 : (vb > 16 ? 16 : vb);
            int cb2 = kb + c*8; if (cb2 > TS-8) cb2 = TS-8;
            cp16z(stg + 18432 + j*ASK + c*16, &g_vchi[(bh*DHD+j)*TS + cb2], vb);
            cp16z(stg + 27648 + j*ASK + c*16, &g_vclo[(bh*DHD+j)*TS + cb2], vb);
        }
    };

    // prologue: Q into stage-0 region (group0), then KV tiles 0->s1, 1->s2
    #pragma unroll
    for (int i=0;i<8;i++){
        int id = tid + i*128;    // 0..1023
        int q = id>>3, c = id&7;
        int gi = (bh*TS + qbase + q)*DHD + c*8;
        cp16(sbase + OQH + (uint32_t)(q*ASK + c*16), &g_qhi[gi]);
        cp16(sbase + OQL + (uint32_t)(q*ASK + c*16), &g_qlo[gi]);
    }
    CP_COMMIT();
    issue_kv(1, 0);
    CP_COMMIT();
    issue_kv(2, 64);
    CP_COMMIT();
    CP_WAIT2();                 // Q group complete (t0,t1 may still be in flight)
    __syncthreads();

    // hoist Q fragments via ldmatrix: two m16 tiles per warp (then s0 is free)
    uint32_t qh[2][4][4], ql[2][4][4];
    int m0 = wid*32;
    int aRow = lane&15, aCol = (lane>>4)<<3;
    int g2 = lane>>3, lr = lane&7;
    #pragma unroll
    for (int mt=0;mt<2;mt++)
      #pragma unroll
      for (int kt=0;kt<4;kt++){
        uint32_t off = (uint32_t)((m0+mt*16+aRow)*ASK + (kt*16+aCol)*2);
        ldsm4(qh[mt][kt], sbase + OQH + off);
        ldsm4(ql[mt][kt], sbase + OQL + off);
      }

    float oacc[2][8][4];
    #pragma unroll
    for (int mt=0;mt<2;mt++)
      #pragma unroll
      for (int np=0;np<8;np++){ oacc[mt][np][0]=0.f; oacc[mt][np][1]=0.f; oacc[mt][np][2]=0.f; oacc[mt][np][3]=0.f; }
    float sprev[2][2] = {{-1e30f,-1e30f},{-1e30f,-1e30f}};
    float lrun[2][2]  = {{0.f,0.f},{0.f,0.f}};
    int NT = (cnt + 63) >> 6;

    for (int it=0; it<NT; it++){
        int kb = it*64;
        if (it+1 < NT) CP_WAIT1();   // newest pending = tile it+1 -> tile it done
        else           CP_WAIT0();   // last iter: tile it is the newest
        __syncthreads();             // all Q-hoist/prior-tile reads done before overwrite
        if (it+2 < NT){
            issue_kv((it+3)%3, kb+128);   // stage(t) = (t+1)%3
            CP_COMMIT();
        }
        uint32_t stg = sbase + (uint32_t)(((it+1)%3))*AST;
        uint32_t uKH = stg, uKL = stg + 9216, uVH = stg + 18432, uVL = stg + 27648;

        // S = Q K^T (3 hi/lo combos), two m-tiles share each K-fragment load
        float sacc[2][8][4];
        #pragma unroll
        for (int mt=0;mt<2;mt++)
          #pragma unroll
          for (int np=0;np<8;np++){ sacc[mt][np][0]=0.f; sacc[mt][np][1]=0.f; sacc[mt][np][2]=0.f; sacc[mt][np][3]=0.f; }
        #pragma unroll
        for (int kt=0;kt<4;kt++){
            #pragma unroll
            for (int p=0;p<4;p++){
                int nn = p*16 + ((g2>>1)<<3) + lr;
                int kc = kt*16 + ((g2&1)<<3);
                uint32_t off = (uint32_t)(nn*ASK + kc*2);
                uint32_t bh4[4], bl4[4];
                ldsm4(bh4, uKH + off);
                ldsm4(bl4, uKL + off);
                #pragma unroll
                for (int mt=0;mt<2;mt++){
                    mma16816(sacc[mt][p*2],   qh[mt][kt], bh4);
                    mma16816(sacc[mt][p*2+1], qh[mt][kt], bh4+2);
                    mma16816(sacc[mt][p*2],   qh[mt][kt], bl4);
                    mma16816(sacc[mt][p*2+1], qh[mt][kt], bl4+2);
                    mma16816(sacc[mt][p*2],   ql[mt][kt], bh4);
                    mma16816(sacc[mt][p*2+1], ql[mt][kt], bh4+2);
                }
            }
        }
        if (kb + 64 > cnt){
            #pragma unroll
            for (int mt=0;mt<2;mt++)
              #pragma unroll
              for (int np=0;np<8;np++)
                #pragma unroll
                for (int c=0;c<4;c++){
                    int j = kb + np*8 + 2*t + (c&1);
                    if (j >= cnt) sacc[mt][np][c] = -1e30f;
                }
        }
        // online softmax per m-tile (rows g and g+8 in each)
        #pragma unroll
        for (int mt=0;mt<2;mt++){
            float mt0 = sprev[mt][0], mt1 = sprev[mt][1];
            #pragma unroll
            for (int np=0;np<8;np++){
                mt0 = fmaxf(mt0, fmaxf(sacc[mt][np][0], sacc[mt][np][1]));
                mt1 = fmaxf(mt1, fmaxf(sacc[mt][np][2], sacc[mt][np][3]));
            }
            mt0 = fmaxf(mt0, __shfl_xor_sync(0xffffffffu, mt0, 1));
            mt0 = fmaxf(mt0, __shfl_xor_sync(0xffffffffu, mt0, 2));
            mt1 = fmaxf(mt1, __shfl_xor_sync(0xffffffffu, mt1, 1));
            mt1 = fmaxf(mt1, __shfl_xor_sync(0xffffffffu, mt1, 2));
            float c0 = __expf(sprev[mt][0]-mt0), c1 = __expf(sprev[mt][1]-mt1);
            float rs0 = 0.f, rs1 = 0.f;
            #pragma unroll
            for (int np=0;np<8;np++){
                sacc[mt][np][0] = __expf(sacc[mt][np][0]-mt0); rs0 += sacc[mt][np][0];
                sacc[mt][np][1] = __expf(sacc[mt][np][1]-mt0); rs0 += sacc[mt][np][1];
                sacc[mt][np][2] = __expf(sacc[mt][np][2]-mt1); rs1 += sacc[mt][np][2];
                sacc[mt][np][3] = __expf(sacc[mt][np][3]-mt1); rs1 += sacc[mt][np][3];
            }
            rs0 += __shfl_xor_sync(0xffffffffu, rs0, 1);
            rs0 += __shfl_xor_sync(0xffffffffu, rs0, 2);
            rs1 += __shfl_xor_sync(0xffffffffu, rs1, 1);
            rs1 += __shfl_xor_sync(0xffffffffu, rs1, 2);
            lrun[mt][0] = lrun[mt][0]*c0 + rs0;
            lrun[mt][1] = lrun[mt][1]*c1 + rs1;
            sprev[mt][0] = mt0; sprev[mt][1] = mt1;
            #pragma unroll
            for (int np=0;np<8;np++){
                oacc[mt][np][0]*=c0; oacc[mt][np][1]*=c0; oacc[mt][np][2]*=c1; oacc[mt][np][3]*=c1;
            }
        }
        // O += P V (3 combos); P A-frags in-register; V-fragment loads shared by both m-tiles
        #pragma unroll
        for (int kt=0;kt<4;kt++){
            uint32_t ah[2][4], al[2][4];
            #pragma unroll
            for (int mt=0;mt<2;mt++){
                float p0 = sacc[mt][2*kt][0],   p1 = sacc[mt][2*kt][1];
                float p2 = sacc[mt][2*kt][2],   p3 = sacc[mt][2*kt][3];
                float p4 = sacc[mt][2*kt+1][0], p5 = sacc[mt][2*kt+1][1];
                float p6 = sacc[mt][2*kt+1][2], p7 = sacc[mt][2*kt+1][3];
                ah[mt][0] = pkbf(p0,p1); ah[mt][1] = pkbf(p2,p3);
                ah[mt][2] = pkbf(p4,p5); ah[mt][3] = pkbf(p6,p7);
                al[mt][0] = pkbf(p0-__bfloat162float(__float2bfloat16(p0)), p1-__bfloat162float(__float2bfloat16(p1)));
                al[mt][1] = pkbf(p2-__bfloat162float(__float2bfloat16(p2)), p3-__bfloat162float(__float2bfloat16(p3)));
                al[mt][2] = pkbf(p4-__bfloat162float(__float2bfloat16(p4)), p5-__bfloat162float(__float2bfloat16(p5)));
                al[mt][3] = pkbf(p6-__bfloat162float(__float2bfloat16(p6)), p7-__bfloat162float(__float2bfloat16(p7)));
            }
            #pragma unroll
            for (int p=0;p<4;p++){
                int nn = p*16 + ((g2>>1)<<3) + lr;
                int kc = kt*16 + ((g2&1)<<3);
                uint32_t off = (uint32_t)(nn*ASK + kc*2);
                uint32_t vh4[4], vl4[4];
                ldsm4(vh4, uVH + off);
                ldsm4(vl4, uVL + off);
                #pragma unroll
                for (int mt=0;mt<2;mt++){
                    mma16816(oacc[mt][p*2],   ah[mt], vh4);
                    mma16816(oacc[mt][p*2+1], ah[mt], vh4+2);
                    mma16816(oacc[mt][p*2],   ah[mt], vl4);
                    mma16816(oacc[mt][p*2+1], ah[mt], vl4+2);
                    mma16816(oacc[mt][p*2],   al[mt], vh4);
                    mma16816(oacc[mt][p*2+1], al[mt], vh4+2);
                }
            }
        }
    }
    // epilogue: normalize, hi/lo split, write ctx as bf16
    #pragma unroll
    for (int mt=0;mt<2;mt++){
        float inv0 = __fdiv_rn(1.0f, lrun[mt][0]);
        float inv1 = __fdiv_rn(1.0f, lrun[mt][1]);
        int t0 = qbase + m0 + mt*16 + g;
        int t1 = t0 + 8;
        #pragma unroll
        for (int np=0;np<8;np++){
            int col = h*DHD + np*8 + 2*t;
            float v0 = oacc[mt][np][0]*inv0, v1 = oacc[mt][np][1]*inv0;
            float v2 = oacc[mt][np][2]*inv1, v3 = oacc[mt][np][3]*inv1;
            __nv_bfloat16 h0=__float2bfloat16(v0), h1=__float2bfloat16(v1);
            __nv_bfloat16 h2=__float2bfloat16(v2), h3=__float2bfloat16(v3);
            *(uint32_t*)&g_chi[(b*TS + t0)*DM + col] = pkbf(__bfloat162float(h0), __bfloat162float(h1));
            *(uint32_t*)&g_clo[(b*TS + t0)*DM + col] = pkbf(v0-__bfloat162float(h0), v1-__bfloat162float(h1));
            *(uint32_t*)&g_chi[(b*TS + t1)*DM + col] = pkbf(__bfloat162float(h2), __bfloat162float(h3));
            *(uint32_t*)&g_clo[(b*TS + t1)*DM + col] = pkbf(v2-__bfloat162float(h2), v3-__bfloat162float(h3));
        }
    }
}

// ---------------- 7. final per-tensor int8 quant-dequant ----------------
__global__ void quant_out_kernel(float* __restrict__ outp)
{
    float s = fmaxf(__fdiv_rn(__int_as_float(g_absmax), 127.0f), 1e-8f);
    int i = blockIdx.x*256 + threadIdx.x;
    float v = outp[i];
    float qv = rintf(__fdiv_rn(v, s));
    qv = fminf(fmaxf(qv, -127.f), 127.f);
    outp[i] = qv * s;
}

// ---------------- launch ----------------
extern "C" void kernel_launch(void* const* d_in, const int* in_sizes, int n_in,
                              void* d_out, int out_size)
{
    (void)in_sizes; (void)n_in; (void)out_size;
    const float* x  = (const float*)d_in[0];
    const int*   mk = (const int*)  d_in[1];
    const float* Wq = (const float*)d_in[2];
    const float* bq = (const float*)d_in[3];
    const float* Wk = (const float*)d_in[4];
    const float* bk = (const float*)d_in[5];
    const float* Wv = (const float*)d_in[6];
    const float* bv = (const float*)d_in[7];
    const float* Wo = (const float*)d_in[8];
    const float* bo = (const float*)d_in[9];
    float* outp = (float*)d_out;

    cudaFuncSetAttribute(gemm_mma_kernel, cudaFuncAttributeMaxDynamicSharedMemorySize, GEMM_SMEM);
    cudaFuncSetAttribute(attn_mma_kernel, cudaFuncAttributeMaxDynamicSharedMemorySize, ATT_SMEM);

    quant_weights_kernel<<<dim3(DM,4), 128>>>(Wq,Wk,Wv,Wo);
    split_x_kernel<<<(BT_*DM)/1024, 256>>>(x);
    compact_kernel<<<NB, 1024>>>(mk);
    gemm_mma_kernel<<<dim3(BT_/128, DM/128, 3), 256, GEMM_SMEM>>>(bq,bk,bv,bo, outp, 0);
    gather_v_kernel<<<dim3(TS/64, BH_), 256>>>();
    attn_mma_kernel<<<dim3(TS/128, BH_), 128, ATT_SMEM>>>();
    gemm_mma_kernel<<<dim3(BT_/128, DM/128, 1), 256, GEMM_SMEM>>>(bq,bk,bv,bo, outp, 3);
    quant_out_kernel<<<(BT_*DM)/256, 256>>>(outp);
}

// round 17
// speedup vs baseline: 1.1739x; 1.0081x over previous
#include <cuda_runtime.h>
#include <cuda_bf16.h>
#include <math.h>
#include <stdint.h>

typedef unsigned long long ull;

#define DM 512
#define TS 4096
#define NB 2
#define NH 8
#define DHD 64
#define BT_ (NB*TS)    // 8192
#define BH_ (NB*NH)    // 16

// ---------------- device scratch (static, allocation-free) ----------------
// RULE (root cause of R4-R7 failures): these symbols are referenced ONLY
// inside device code. Never pass a __device__ symbol as a kernel argument.
__device__ __nv_bfloat16 g_Wb[4][DM*DM];
__device__ float g_ws[4][DM];
__device__ __nv_bfloat16 g_xhi[BT_*DM];
__device__ __nv_bfloat16 g_xlo[BT_*DM];
__device__ __nv_bfloat16 g_chi[BT_*DM];
__device__ __nv_bfloat16 g_clo[BT_*DM];
__device__ __nv_bfloat16 g_qhi[BH_*TS*DHD];   // Q pre-scaled (x0.125) bf16 hi/lo, [bh][t][dh]
__device__ __nv_bfloat16 g_qlo[BH_*TS*DHD];
__device__ float g_v [BH_*TS*DHD];            // V fp32 (for transposed gather)
__device__ __nv_bfloat16 g_kchi[BH_*TS*DHD];  // compacted K, [bh][rank][d] (written by gemm)
__device__ __nv_bfloat16 g_kclo[BH_*TS*DHD];
__device__ __nv_bfloat16 g_vchi[BH_*DHD*TS];  // compacted V transposed, [bh][d][rank]
__device__ __nv_bfloat16 g_vclo[BH_*DHD*TS];
__device__ int   g_kept[NB*TS];
__device__ int   g_rank[NB*TS];               // t -> rank (or -1)
__device__ int   g_cnt[NB];
__device__ int   g_absmax;

// ---------------- mma / ldmatrix / cp.async helpers ----------------
static __device__ __forceinline__ void mma16816(float* d, const uint32_t* a, const uint32_t* b){
    asm volatile("mma.sync.aligned.m16n8k16.row.col.f32.bf16.bf16.f32 "
        "{%0,%1,%2,%3}, {%4,%5,%6,%7}, {%8,%9}, {%0,%1,%2,%3};"
        : "+f"(d[0]),"+f"(d[1]),"+f"(d[2]),"+f"(d[3])
        : "r"(a[0]),"r"(a[1]),"r"(a[2]),"r"(a[3]), "r"(b[0]),"r"(b[1]));
}
static __device__ __forceinline__ void ldsm4(uint32_t* r, uint32_t a){
    asm volatile("ldmatrix.sync.aligned.m8n8.x4.shared.b16 {%0,%1,%2,%3}, [%4];"
        : "=r"(r[0]),"=r"(r[1]),"=r"(r[2]),"=r"(r[3]) : "r"(a));
}
static __device__ __forceinline__ uint32_t pkbf(float x, float y){
    uint32_t r; asm("cvt.rn.bf16x2.f32 %0, %1, %2;" : "=r"(r) : "f"(y), "f"(x)); return r;
}
static __device__ __forceinline__ uint32_t smem_u32(const void* p){
    uint32_t a;
    asm("{ .reg .u64 t; cvta.to.shared.u64 t, %1; cvt.u32.u64 %0, t; }" : "=r"(a) : "l"(p));
    return a;
}
static __device__ __forceinline__ void cp16(uint32_t dst, const void* src){
    asm volatile("cp.async.ca.shared.global [%0], [%1], 16;" :: "r"(dst), "l"(src) : "memory");
}
static __device__ __forceinline__ void cp16z(uint32_t dst, const void* src, int ssz){
    asm volatile("cp.async.ca.shared.global [%0], [%1], 16, %2;" :: "r"(dst), "l"(src), "r"(ssz) : "memory");
}
#define CP_COMMIT() asm volatile("cp.async.commit_group;" ::: "memory")
#define CP_WAIT2()  asm volatile("cp.async.wait_group 2;" ::: "memory")
#define CP_WAIT1()  asm volatile("cp.async.wait_group 1;" ::: "memory")
#define CP_WAIT0()  asm volatile("cp.async.wait_group 0;" ::: "memory")

// ---------------- 1. merged prologue: weight quant | x split | mask compaction --------------
// One launch, 1024 threads/block; branch is uniform per block (blockIdx only).
//   bid [0,256):     weight quant-dequant, 8 rows per block (128-thread groups)
//   bid [256,1280):  bf16 hi/lo split of x (4096 floats per block)
//   bid [1280,1282): per-batch mask compaction (verbatim 1024-thread scan)
#define PRO_QB 256
#define PRO_SB 1024
__global__ void __launch_bounds__(1024) prologue_kernel(
    const float* __restrict__ x, const int* __restrict__ mask,
    const float* __restrict__ Wq, const float* __restrict__ Wk,
    const float* __restrict__ Wv, const float* __restrict__ Wo)
{
    int bid = blockIdx.x;
    int tid = threadIdx.x;
    if (bid < PRO_QB){
        // ---- weight quant: task = row index in [0, 4*512) ----
        __shared__ float sm4[8][4];
        int grp = tid>>7, lt = tid&127;          // 8 groups x 128 threads
        int task = bid*8 + grp;
        int w = task>>9, row = task&511;
        const float* srcs[4] = {Wq, Wk, Wv, Wo};
        const float* wr = srcs[w] + row*DM;
        __nv_bfloat16* dst = &g_Wb[w][row*DM];
        if (task==0 && lt==0) g_absmax = 0;
        float mx = 0.f;
        for (int i=lt;i<DM;i+=128) mx = fmaxf(mx, fabsf(wr[i]));
        for (int off=16;off;off>>=1) mx = fmaxf(mx, __shfl_xor_sync(0xffffffffu, mx, off));
        if ((lt&31)==0) sm4[grp][lt>>5] = mx;
        __syncthreads();
        mx = fmaxf(fmaxf(sm4[grp][0],sm4[grp][1]), fmaxf(sm4[grp][2],sm4[grp][3]));
        float s = fmaxf(__fdiv_rn(mx, 127.0f), 1e-8f);
        if (lt==0) g_ws[w][row] = s;
        for (int i=lt;i<DM;i+=128){
            float qv = rintf(__fdiv_rn(wr[i], s));       // round-half-even == jnp.round
            qv = fminf(fmaxf(qv, -127.f), 127.f);
            dst[i] = __float2bfloat16(qv);
        }
    } else if (bid < PRO_QB + PRO_SB){
        // ---- x hi/lo split ----
        int i = ((bid - PRO_QB)*1024 + tid)*4;
        float4 v = *(const float4*)&x[i];
        __nv_bfloat16 h0=__float2bfloat16(v.x), h1=__float2bfloat16(v.y);
        __nv_bfloat16 h2=__float2bfloat16(v.z), h3=__float2bfloat16(v.w);
        __nv_bfloat162 hA; hA.x=h0; hA.y=h1;
        __nv_bfloat162 hB; hB.x=h2; hB.y=h3;
        __nv_bfloat162 lA; lA.x=__float2bfloat16(v.x-__bfloat162float(h0)); lA.y=__float2bfloat16(v.y-__bfloat162float(h1));
        __nv_bfloat162 lB; lB.x=__float2bfloat16(v.z-__bfloat162float(h2)); lB.y=__float2bfloat16(v.w-__bfloat162float(h3));
        *(__nv_bfloat162*)&g_xhi[i]   = hA;
        *(__nv_bfloat162*)&g_xhi[i+2] = hB;
        *(__nv_bfloat162*)&g_xlo[i]   = lA;
        *(__nv_bfloat162*)&g_xlo[i+2] = lB;
    } else {
        // ---- mask compaction (+ inverse rank map) ----
        __shared__ int part[1024];
        int b = bid - (PRO_QB + PRO_SB);
        const int* m = mask + b*TS;
        int base = tid*4;
        int f0 = m[base]!=0, f1 = m[base+1]!=0, f2 = m[base+2]!=0, f3 = m[base+3]!=0;
        int s = f0+f1+f2+f3;
        part[tid] = s;
        __syncthreads();
        for (int off=1; off<1024; off<<=1){
            int v = (tid>=off) ? part[tid-off] : 0;
            __syncthreads();
            part[tid] += v;
            __syncthreads();
        }
        int rr = part[tid] - s;
        int o = rr + b*TS;
        g_rank[b*TS+base  ] = f0 ? rr : -1; rr += f0;
        g_rank[b*TS+base+1] = f1 ? rr : -1; rr += f1;
        g_rank[b*TS+base+2] = f2 ? rr : -1; rr += f2;
        g_rank[b*TS+base+3] = f3 ? rr : -1;
        if (f0) g_kept[o++] = base;
        if (f1) g_kept[o++] = base+1;
        if (f2) g_kept[o++] = base+2;
        if (f3) g_kept[o++] = base+3;
        if (tid==1023) g_cnt[b] = part[1023];
    }
}

// ---------------- 3. mma GEMM, cp.async 2-stage + ldmatrix; fused Q/K epilogues ----------------
#define GTILE 10240
#define GST3  (3*GTILE)          // 30720 per stage
#define GEMM_SMEM (2*GST3)       // 61440
__global__ void __launch_bounds__(256) gemm_mma_kernel(
    const float* __restrict__ bq, const float* __restrict__ bk,
    const float* __restrict__ bv, const float* __restrict__ bo,
    float* __restrict__ outp, int modebase)
{
    extern __shared__ __align__(16) char dsm[];
    __shared__ float s_sc[128], s_bi[128];
    __shared__ float red8[8];
    int mode = modebase + blockIdx.z;
    int tid = threadIdx.x, lane = tid&31, wid = tid>>5;
    int wm = wid>>1, wn = wid&1;
    int g = lane>>2, t = lane&3;
    int rowbase = blockIdx.x*128, nbase = blockIdx.y*128;
    uint32_t sbase = smem_u32(dsm);

    const __nv_bfloat16* __restrict__ Ahi = (mode<3) ? g_xhi : g_chi;
    const __nv_bfloat16* __restrict__ Alo = (mode<3) ? g_xlo : g_clo;
    const __nv_bfloat16* __restrict__ Bw  = g_Wb[mode];
    const float* biasp = (mode==0)?bq:((mode==1)?bk:((mode==2)?bv:bo));

    auto issue_tile = [&](int st, int kt){
        uint32_t stg = sbase + st*GST3;
        int kb = kt*32;
        #pragma unroll
        for (int i=0;i<2;i++){
            int id = tid + i*256;   // 0..511
            int r = id>>2, c = id&3;
            cp16(stg +           r*80 + c*16, &Ahi[(rowbase+r)*DM + kb + c*8]);
            cp16(stg + GTILE   + r*80 + c*16, &Alo[(rowbase+r)*DM + kb + c*8]);
            cp16(stg + 2*GTILE + r*80 + c*16, &Bw [(nbase  +r)*DM + kb + c*8]);
        }
    };

    issue_tile(0, 0);
    CP_COMMIT();
    if (tid<128) s_sc[tid] = g_ws[mode][nbase+tid];
    else         s_bi[tid-128] = biasp[tid-128+nbase];

    float acc[2][8][4];
    #pragma unroll
    for (int mt=0;mt<2;mt++)
      #pragma unroll
      for (int nt=0;nt<8;nt++)
        #pragma unroll
        for (int c=0;c<4;c++) acc[mt][nt][c] = 0.f;

    int aRow = lane&15, aCol = (lane>>4)<<3;
    int g2 = lane>>3, lr = lane&7;

    for (int kt=0; kt<16; kt++){
        if (kt+1 < 16) issue_tile((kt+1)&1, kt+1);
        CP_COMMIT();
        CP_WAIT1();
        __syncthreads();
        uint32_t stg = sbase + (kt&1)*GST3;
        #pragma unroll
        for (int ks=0; ks<32; ks+=16){
            uint32_t af[2][2][4];
            #pragma unroll
            for (int h=0; h<2; h++)
              #pragma unroll
              for (int mt=0; mt<2; mt++){
                int r0 = wm*32 + mt*16;
                ldsm4(af[h][mt], stg + h*GTILE + (uint32_t)((r0+aRow)*80 + (ks+aCol)*2));
              }
            #pragma unroll
            for (int p=0; p<4; p++){
                int nn = wn*64 + p*16 + ((g2>>1)<<3) + lr;
                int kc = ks + ((g2&1)<<3);
                uint32_t bf4[4];
                ldsm4(bf4, stg + 2*GTILE + (uint32_t)(nn*80 + kc*2));
                #pragma unroll
                for (int mt=0; mt<2; mt++){
                    mma16816(acc[mt][p*2],   af[0][mt], bf4);
                    mma16816(acc[mt][p*2+1], af[0][mt], bf4+2);
                    mma16816(acc[mt][p*2],   af[1][mt], bf4);
                    mma16816(acc[mt][p*2+1], af[1][mt], bf4+2);
                }
            }
        }
        __syncthreads();
    }
    float amax = 0.f;
    #pragma unroll
    for (int mt=0;mt<2;mt++){
      #pragma unroll
      for (int nt=0;nt<8;nt++){
        int ncol = wn*64 + nt*8 + 2*t;
        float s0 = s_sc[ncol], s1 = s_sc[ncol+1];
        float b0 = s_bi[ncol], b1 = s_bi[ncol+1];
        #pragma unroll
        for (int rh=0; rh<2; rh++){
            int row = rowbase + wm*32 + mt*16 + g + rh*8;
            float v0 = acc[mt][nt][rh*2  ]*s0 + b0;
            float v1 = acc[mt][nt][rh*2+1]*s1 + b1;
            if (mode==3){
                float2 w; w.x = v0; w.y = v1;
                *(float2*)&outp[row*DM + nbase + ncol] = w;
                amax = fmaxf(amax, fmaxf(fabsf(v0), fabsf(v1)));
            } else {
                int o = nbase + ncol;
                int head = o>>6, dh = o&63;
                int bb = row>>12, tt = row&4095;
                if (mode==0){
                    float q0 = v0*0.125f, q1 = v1*0.125f;
                    float h0 = __bfloat162float(__float2bfloat16(q0));
                    float h1 = __bfloat162float(__float2bfloat16(q1));
                    int idx = ((bb*NH+head)*TS + tt)*DHD + dh;
                    *(uint32_t*)&g_qhi[idx] = pkbf(h0, h1);
                    *(uint32_t*)&g_qlo[idx] = pkbf(q0-h0, q1-h1);
                } else if (mode==1){
                    int rk = g_rank[bb*TS + tt];
                    if (rk >= 0){
                        float h0 = __bfloat162float(__float2bfloat16(v0));
                        float h1 = __bfloat162float(__float2bfloat16(v1));
                        int idx = ((bb*NH+head)*TS + rk)*DHD + dh;
                        *(uint32_t*)&g_kchi[idx] = pkbf(h0, h1);
                        *(uint32_t*)&g_kclo[idx] = pkbf(v0-h0, v1-h1);
                    }
                } else {
                    float2 w; w.x = v0; w.y = v1;
                    *(float2*)&g_v[((bb*NH+head)*TS + tt)*DHD + dh] = w;
                }
            }
        }
      }
    }
    if (mode==3){
        for (int off=16;off;off>>=1) amax = fmaxf(amax, __shfl_xor_sync(0xffffffffu, amax, off));
        if (lane==0) red8[wid] = amax;
        __syncthreads();
        if (tid==0){
            float m = red8[0];
            #pragma unroll
            for (int i=1;i<8;i++) m = fmaxf(m, red8[i]);
            atomicMax(&g_absmax, __float_as_int(m));
        }
    }
}

// ---------------- 4. V-only coalesced gather+transpose: g_v kept rows -> [bh][d][rank] -------
__global__ void __launch_bounds__(256) gather_v_kernel()
{
    __shared__ float vs[64][65];
    __shared__ int srcs[64];
    int bh = blockIdx.y;
    int b = bh>>3;
    int jbase = blockIdx.x*64;
    int cnt = g_cnt[b];
    int tid = threadIdx.x;
    if (tid < 64){
        int j = jbase + tid;
        srcs[tid] = (j < cnt) ? g_kept[b*TS + j] : -1;
    }
    __syncthreads();
    #pragma unroll
    for (int i=0;i<16;i++){
        int id = tid + i*256;
        int j = id>>6, d = id&63;
        int src = srcs[j];
        vs[j][d] = (src >= 0) ? g_v[(bh*TS + src)*DHD + d] : 0.f;
    }
    __syncthreads();
    #pragma unroll
    for (int i=0;i<16;i++){
        int id = tid + i*256;
        int d = id>>6, j = id&63;
        float vv = vs[j][d];
        __nv_bfloat16 h = __float2bfloat16(vv);
        int o = (bh*DHD + d)*TS + jbase + j;
        g_vchi[o] = h;
        g_vclo[o] = __float2bfloat16(vv - __bfloat162float(h));
    }
}

// ---------------- 5. flash attention: BQ=128, BK=64, 4 warps x m32, 3-stage KV pipeline ------
#define ASK 144                  // row stride bytes (72 bf16; 16B aligned)
#define AQ_REG 18432             // Q hi or lo: 128 rows x 144B
#define AST   36864              // per KV stage: KH|KL|VH|VL, 64x144 each
#define ATT_SMEM (3*AST)         // 110592 (s0 doubles as Q region)
__global__ void __launch_bounds__(128, 2) attn_mma_kernel()
{
    extern __shared__ __align__(16) char smem[];
    const int OQH=0, OQL=AQ_REG;     // Q occupies stage-0 region before the hoist
    int bh = blockIdx.y;
    int b = bh>>3, h = bh&7;
    int qbase = blockIdx.x*128;
    int tid = threadIdx.x, lane = tid&31, wid = tid>>5;   // 4 warps
    int g = lane>>2, t = lane&3;
    int cnt = g_cnt[b];
    uint32_t sbase = smem_u32(smem);

    auto issue_kv = [&](int st, int kb){
        uint32_t stg = sbase + st*AST;
        #pragma unroll
        for (int i=0;i<4;i++){
            int id = tid + i*128;   // 0..511
            int j = id>>3, c = id&7;
            int jj = kb + j;
            int kssz = (jj < cnt) ? 16 : 0;
            int jc = jj < TS ? jj : TS-1;
            cp16z(stg +         j*ASK + c*16, &g_kchi[(bh*TS+jc)*DHD + c*8], kssz);
            cp16z(stg +  9216 + j*ASK + c*16, &g_kclo[(bh*TS+jc)*DHD + c*8], kssz);
            int vb = (cnt - (kb + c*8))*2;
            vb = vb < 0 ? 0 : (vb > 16 ? 16 : vb);
            int cb2 = kb + c*8; if (cb2 > TS-8) cb2 = TS-8;
            cp16z(stg + 18432 + j*ASK + c*16, &g_vchi[(bh*DHD+j)*TS + cb2], vb);
            cp16z(stg + 27648 + j*ASK + c*16, &g_vclo[(bh*DHD+j)*TS + cb2], vb);
        }
    };

    // prologue: Q into stage-0 region (group0), then KV tiles 0->s1, 1->s2
    #pragma unroll
    for (int i=0;i<8;i++){
        int id = tid + i*128;    // 0..1023
        int q = id>>3, c = id&7;
        int gi = (bh*TS + qbase + q)*DHD + c*8;
        cp16(sbase + OQH + (uint32_t)(q*ASK + c*16), &g_qhi[gi]);
        cp16(sbase + OQL + (uint32_t)(q*ASK + c*16), &g_qlo[gi]);
    }
    CP_COMMIT();
    issue_kv(1, 0);
    CP_COMMIT();
    issue_kv(2, 64);
    CP_COMMIT();
    CP_WAIT2();                 // Q group complete (t0,t1 may still be in flight)
    __syncthreads();

    // hoist Q fragments via ldmatrix: two m16 tiles per warp (then s0 is free)
    uint32_t qh[2][4][4], ql[2][4][4];
    int m0 = wid*32;
    int aRow = lane&15, aCol = (lane>>4)<<3;
    int g2 = lane>>3, lr = lane&7;
    #pragma unroll
    for (int mt=0;mt<2;mt++)
      #pragma unroll
      for (int kt=0;kt<4;kt++){
        uint32_t off = (uint32_t)((m0+mt*16+aRow)*ASK + (kt*16+aCol)*2);
        ldsm4(qh[mt][kt], sbase + OQH + off);
        ldsm4(ql[mt][kt], sbase + OQL + off);
      }

    float oacc[2][8][4];
    #pragma unroll
    for (int mt=0;mt<2;mt++)
      #pragma unroll
      for (int np=0;np<8;np++){ oacc[mt][np][0]=0.f; oacc[mt][np][1]=0.f; oacc[mt][np][2]=0.f; oacc[mt][np][3]=0.f; }
    float sprev[2][2] = {{-1e30f,-1e30f},{-1e30f,-1e30f}};
    float lrun[2][2]  = {{0.f,0.f},{0.f,0.f}};
    int NT = (cnt + 63) >> 6;

    for (int it=0; it<NT; it++){
        int kb = it*64;
        if (it+1 < NT) CP_WAIT1();   // newest pending = tile it+1 -> tile it done
        else           CP_WAIT0();   // last iter: tile it is the newest
        __syncthreads();             // all Q-hoist/prior-tile reads done before overwrite
        if (it+2 < NT){
            issue_kv((it+3)%3, kb+128);   // stage(t) = (t+1)%3
            CP_COMMIT();
        }
        uint32_t stg = sbase + (uint32_t)(((it+1)%3))*AST;
        uint32_t uKH = stg, uKL = stg + 9216, uVH = stg + 18432, uVL = stg + 27648;

        // S = Q K^T (3 hi/lo combos), two m-tiles share each K-fragment load
        float sacc[2][8][4];
        #pragma unroll
        for (int mt=0;mt<2;mt++)
          #pragma unroll
          for (int np=0;np<8;np++){ sacc[mt][np][0]=0.f; sacc[mt][np][1]=0.f; sacc[mt][np][2]=0.f; sacc[mt][np][3]=0.f; }
        #pragma unroll
        for (int kt=0;kt<4;kt++){
            #pragma unroll
            for (int p=0;p<4;p++){
                int nn = p*16 + ((g2>>1)<<3) + lr;
                int kc = kt*16 + ((g2&1)<<3);
                uint32_t off = (uint32_t)(nn*ASK + kc*2);
                uint32_t bh4[4], bl4[4];
                ldsm4(bh4, uKH + off);
                ldsm4(bl4, uKL + off);
                #pragma unroll
                for (int mt=0;mt<2;mt++){
                    mma16816(sacc[mt][p*2],   qh[mt][kt], bh4);
                    mma16816(sacc[mt][p*2+1], qh[mt][kt], bh4+2);
                    mma16816(sacc[mt][p*2],   qh[mt][kt], bl4);
                    mma16816(sacc[mt][p*2+1], qh[mt][kt], bl4+2);
                    mma16816(sacc[mt][p*2],   ql[mt][kt], bh4);
                    mma16816(sacc[mt][p*2+1], ql[mt][kt], bh4+2);
                }
            }
        }
        if (kb + 64 > cnt){
            #pragma unroll
            for (int mt=0;mt<2;mt++)
              #pragma unroll
              for (int np=0;np<8;np++)
                #pragma unroll
                for (int c=0;c<4;c++){
                    int j = kb + np*8 + 2*t + (c&1);
                    if (j >= cnt) sacc[mt][np][c] = -1e30f;
                }
        }
        // online softmax per m-tile (rows g and g+8 in each)
        #pragma unroll
        for (int mt=0;mt<2;mt++){
            float mt0 = sprev[mt][0], mt1 = sprev[mt][1];
            #pragma unroll
            for (int np=0;np<8;np++){
                mt0 = fmaxf(mt0, fmaxf(sacc[mt][np][0], sacc[mt][np][1]));
                mt1 = fmaxf(mt1, fmaxf(sacc[mt][np][2], sacc[mt][np][3]));
            }
            mt0 = fmaxf(mt0, __shfl_xor_sync(0xffffffffu, mt0, 1));
            mt0 = fmaxf(mt0, __shfl_xor_sync(0xffffffffu, mt0, 2));
            mt1 = fmaxf(mt1, __shfl_xor_sync(0xffffffffu, mt1, 1));
            mt1 = fmaxf(mt1, __shfl_xor_sync(0xffffffffu, mt1, 2));
            float c0 = __expf(sprev[mt][0]-mt0), c1 = __expf(sprev[mt][1]-mt1);
            float rs0 = 0.f, rs1 = 0.f;
            #pragma unroll
            for (int np=0;np<8;np++){
                sacc[mt][np][0] = __expf(sacc[mt][np][0]-mt0); rs0 += sacc[mt][np][0];
                sacc[mt][np][1] = __expf(sacc[mt][np][1]-mt0); rs0 += sacc[mt][np][1];
                sacc[mt][np][2] = __expf(sacc[mt][np][2]-mt1); rs1 += sacc[mt][np][2];
                sacc[mt][np][3] = __expf(sacc[mt][np][3]-mt1); rs1 += sacc[mt][np][3];
            }
            rs0 += __shfl_xor_sync(0xffffffffu, rs0, 1);
            rs0 += __shfl_xor_sync(0xffffffffu, rs0, 2);
            rs1 += __shfl_xor_sync(0xffffffffu, rs1, 1);
            rs1 += __shfl_xor_sync(0xffffffffu, rs1, 2);
            lrun[mt][0] = lrun[mt][0]*c0 + rs0;
            lrun[mt][1] = lrun[mt][1]*c1 + rs1;
            sprev[mt][0] = mt0; sprev[mt][1] = mt1;
            #pragma unroll
            for (int np=0;np<8;np++){
                oacc[mt][np][0]*=c0; oacc[mt][np][1]*=c0; oacc[mt][np][2]*=c1; oacc[mt][np][3]*=c1;
            }
        }
        // O += P V (3 combos); P A-frags in-register; V-fragment loads shared by both m-tiles
        #pragma unroll
        for (int kt=0;kt<4;kt++){
            uint32_t ah[2][4], al[2][4];
            #pragma unroll
            for (int mt=0;mt<2;mt++){
                float p0 = sacc[mt][2*kt][0],   p1 = sacc[mt][2*kt][1];
                float p2 = sacc[mt][2*kt][2],   p3 = sacc[mt][2*kt][3];
                float p4 = sacc[mt][2*kt+1][0], p5 = sacc[mt][2*kt+1][1];
                float p6 = sacc[mt][2*kt+1][2], p7 = sacc[mt][2*kt+1][3];
                ah[mt][0] = pkbf(p0,p1); ah[mt][1] = pkbf(p2,p3);
                ah[mt][2] = pkbf(p4,p5); ah[mt][3] = pkbf(p6,p7);
                al[mt][0] = pkbf(p0-__bfloat162float(__float2bfloat16(p0)), p1-__bfloat162float(__float2bfloat16(p1)));
                al[mt][1] = pkbf(p2-__bfloat162float(__float2bfloat16(p2)), p3-__bfloat162float(__float2bfloat16(p3)));
                al[mt][2] = pkbf(p4-__bfloat162float(__float2bfloat16(p4)), p5-__bfloat162float(__float2bfloat16(p5)));
                al[mt][3] = pkbf(p6-__bfloat162float(__float2bfloat16(p6)), p7-__bfloat162float(__float2bfloat16(p7)));
            }
            #pragma unroll
            for (int p=0;p<4;p++){
                int nn = p*16 + ((g2>>1)<<3) + lr;
                int kc = kt*16 + ((g2&1)<<3);
                uint32_t off = (uint32_t)(nn*ASK + kc*2);
                uint32_t vh4[4], vl4[4];
                ldsm4(vh4, uVH + off);
                ldsm4(vl4, uVL + off);
                #pragma unroll
                for (int mt=0;mt<2;mt++){
                    mma16816(oacc[mt][p*2],   ah[mt], vh4);
                    mma16816(oacc[mt][p*2+1], ah[mt], vh4+2);
                    mma16816(oacc[mt][p*2],   ah[mt], vl4);
                    mma16816(oacc[mt][p*2+1], ah[mt], vl4+2);
                    mma16816(oacc[mt][p*2],   al[mt], vh4);
                    mma16816(oacc[mt][p*2+1], al[mt], vh4+2);
                }
            }
        }
    }
    // epilogue: normalize, hi/lo split, write ctx as bf16
    #pragma unroll
    for (int mt=0;mt<2;mt++){
        float inv0 = __fdiv_rn(1.0f, lrun[mt][0]);
        float inv1 = __fdiv_rn(1.0f, lrun[mt][1]);
        int t0 = qbase + m0 + mt*16 + g;
        int t1 = t0 + 8;
        #pragma unroll
        for (int np=0;np<8;np++){
            int col = h*DHD + np*8 + 2*t;
            float v0 = oacc[mt][np][0]*inv0, v1 = oacc[mt][np][1]*inv0;
            float v2 = oacc[mt][np][2]*inv1, v3 = oacc[mt][np][3]*inv1;
            __nv_bfloat16 h0=__float2bfloat16(v0), h1=__float2bfloat16(v1);
            __nv_bfloat16 h2=__float2bfloat16(v2), h3=__float2bfloat16(v3);
            *(uint32_t*)&g_chi[(b*TS + t0)*DM + col] = pkbf(__bfloat162float(h0), __bfloat162float(h1));
            *(uint32_t*)&g_clo[(b*TS + t0)*DM + col] = pkbf(v0-__bfloat162float(h0), v1-__bfloat162float(h1));
            *(uint32_t*)&g_chi[(b*TS + t1)*DM + col] = pkbf(__bfloat162float(h2), __bfloat162float(h3));
            *(uint32_t*)&g_clo[(b*TS + t1)*DM + col] = pkbf(v2-__bfloat162float(h2), v3-__bfloat162float(h3));
        }
    }
}

// ---------------- 7. final per-tensor int8 quant-dequant ----------------
__global__ void quant_out_kernel(float* __restrict__ outp)
{
    float s = fmaxf(__fdiv_rn(__int_as_float(g_absmax), 127.0f), 1e-8f);
    int i = blockIdx.x*256 + threadIdx.x;
    float v = outp[i];
    float qv = rintf(__fdiv_rn(v, s));
    qv = fminf(fmaxf(qv, -127.f), 127.f);
    outp[i] = qv * s;
}

// ---------------- launch ----------------
extern "C" void kernel_launch(void* const* d_in, const int* in_sizes, int n_in,
                              void* d_out, int out_size)
{
    (void)in_sizes; (void)n_in; (void)out_size;
    const float* x  = (const float*)d_in[0];
    const int*   mk = (const int*)  d_in[1];
    const float* Wq = (const float*)d_in[2];
    const float* bq = (const float*)d_in[3];
    const float* Wk = (const float*)d_in[4];
    const float* bk = (const float*)d_in[5];
    const float* Wv = (const float*)d_in[6];
    const float* bv = (const float*)d_in[7];
    const float* Wo = (const float*)d_in[8];
    const float* bo = (const float*)d_in[9];
    float* outp = (float*)d_out;

    cudaFuncSetAttribute(gemm_mma_kernel, cudaFuncAttributeMaxDynamicSharedMemorySize, GEMM_SMEM);
    cudaFuncSetAttribute(attn_mma_kernel, cudaFuncAttributeMaxDynamicSharedMemorySize, ATT_SMEM);

    prologue_kernel<<<PRO_QB + PRO_SB + NB, 1024>>>(x, mk, Wq, Wk, Wv, Wo);
    gemm_mma_kernel<<<dim3(BT_/128, DM/128, 3), 256, GEMM_SMEM>>>(bq,bk,bv,bo, outp, 0);
    gather_v_kernel<<<dim3(TS/64, BH_), 256>>>();
    attn_mma_kernel<<<dim3(TS/128, BH_), 128, ATT_SMEM>>>();
    gemm_mma_kernel<<<dim3(BT_/128, DM/128, 1), 256, GEMM_SMEM>>>(bq,bk,bv,bo, outp, 3);
    quant_out_kernel<<<(BT_*DM)/256, 256>>>(outp);
}